// round 2
// baseline (speedup 1.0000x reference)
#include <cuda_runtime.h>
#include <cstdint>

// Problem constants
#define B_   8
#define N_   4096
#define C_   1536
#define H_   24
#define R_   8
#define M_   192      // H_ * R_
#define SCALE_ 0.125f // (64)^-0.5

// Scratch (static device globals; no allocation allowed)
__device__ float g_Q[B_ * R_ * C_];            // 0.39 MB  folded q
__device__ float g_QK[B_ * M_ * C_];           // 9.4 MB   q @ Wk (per head)
__device__ float g_S[(size_t)B_ * M_ * N_];    // 25.2 MB  scores, then softmax P (in place)
__device__ float g_AX[B_ * M_ * C_];           // 9.4 MB   P @ x
__device__ float g_XCLS[B_ * R_ * C_];         // 0.39 MB  pooled values

// ---------------------------------------------------------------------------
// helpers
// ---------------------------------------------------------------------------
__device__ __forceinline__ uint32_t f2tf(float f) {
    uint32_t u;
    asm("cvt.rna.tf32.f32 %0, %1;" : "=r"(u) : "f"(f));
    return u;
}

__device__ __forceinline__ void mma8(float* c, const uint32_t* a, const uint32_t* b) {
    asm volatile(
        "mma.sync.aligned.m16n8k8.row.col.f32.tf32.tf32.f32 "
        "{%0,%1,%2,%3}, {%4,%5,%6,%7}, {%8,%9}, {%0,%1,%2,%3};"
        : "+f"(c[0]), "+f"(c[1]), "+f"(c[2]), "+f"(c[3])
        : "r"(a[0]), "r"(a[1]), "r"(a[2]), "r"(a[3]), "r"(b[0]), "r"(b[1]));
}

__device__ __forceinline__ float warpMax(float v) {
    #pragma unroll
    for (int o = 16; o; o >>= 1) v = fmaxf(v, __shfl_xor_sync(0xffffffffu, v, o));
    return v;
}
__device__ __forceinline__ float warpSum(float v) {
    #pragma unroll
    for (int o = 16; o; o >>= 1) v += __shfl_xor_sync(0xffffffffu, v, o);
    return v;
}

// ---------------------------------------------------------------------------
// k_q: Q[b,r,c'] = SCALE * sum_c x[b,r,c] * Wq[c',c]   (r < 8)
// grid (6, 8) blocks of 256: blockIdx.x = c'-tile, blockIdx.y = b
// ---------------------------------------------------------------------------
__global__ __launch_bounds__(256) void k_q(const float* __restrict__ x,
                                           const float* __restrict__ Wq) {
    __shared__ float xs[R_ * C_];  // 48 KB: the 8 query-token rows for this batch
    int b = blockIdx.y;
    int t = threadIdx.x;
    {
        const float4* src = (const float4*)(x + (size_t)b * N_ * C_);
        float4* dst = (float4*)xs;
        #pragma unroll 4
        for (int i = t; i < R_ * C_ / 4; i += 256) dst[i] = src[i];
    }
    __syncthreads();

    int cp = blockIdx.x * 256 + t;
    const float4* wr = (const float4*)(Wq + (size_t)cp * C_);
    float acc[R_] = {};
    for (int k4 = 0; k4 < C_ / 4; k4++) {
        float4 w = wr[k4];
        #pragma unroll
        for (int r = 0; r < R_; r++) {
            float4 a = ((const float4*)(xs + r * C_))[k4];
            acc[r] += a.x * w.x + a.y * w.y + a.z * w.z + a.w * w.w;
        }
    }
    #pragma unroll
    for (int r = 0; r < R_; r++)
        g_Q[(b * R_ + r) * C_ + cp] = acc[r] * SCALE_;
}

// ---------------------------------------------------------------------------
// k_qk: QK[b, h*8+r, c] = sum_d Q[b,r,h*64+d] * Wk[h*64+d, c]
// grid (6, 24): blockIdx.x = c-tile (256), blockIdx.y = h
// Each thread owns one c; accumulates all 64 (b,r) rows so Wk is read once.
// ---------------------------------------------------------------------------
__global__ __launch_bounds__(256) void k_qk(const float* __restrict__ Wk) {
    __shared__ float Qs[64][64];  // [br][d] for this head, 16 KB
    int h = blockIdx.y;
    int t = threadIdx.x;
    for (int i = t; i < 64 * 64; i += 256) {
        int br = i >> 6, d = i & 63;
        Qs[br][d] = g_Q[br * C_ + h * 64 + d];
    }
    __syncthreads();

    int c = blockIdx.x * 256 + t;
    float acc[64] = {};
    for (int d = 0; d < 64; d++) {
        float w = Wk[(size_t)(h * 64 + d) * C_ + c];
        #pragma unroll
        for (int br = 0; br < 64; br++) acc[br] += Qs[br][d] * w;
    }
    #pragma unroll
    for (int br = 0; br < 64; br++) {
        int b = br >> 3, r = br & 7;
        g_QK[((size_t)b * M_ + h * 8 + r) * C_ + c] = acc[br];
    }
}

// ---------------------------------------------------------------------------
// k_scores: S[b, m, n] = QK[b,m,:] . x[b,n,:]     (tf32 mma GEMM)
// per batch: M=192, N=4096, K=1536.  BM=64, BN=128, BK=16, 128 threads.
// grid (32, 3, 8)
// ---------------------------------------------------------------------------
__global__ __launch_bounds__(128) void k_scores(const float* __restrict__ x) {
    int b = blockIdx.z, mt = blockIdx.y, nt = blockIdx.x;
    const float* A  = g_QK + ((size_t)b * M_ + mt * 64) * C_;
    const float* Bx = x + (size_t)b * N_ * C_ + (size_t)nt * 128 * C_;
    float* C = g_S + ((size_t)b * M_ + mt * 64) * N_ + nt * 128;

    __shared__ uint32_t As[64 * 20];
    __shared__ uint32_t Bs[128 * 20];

    int tid = threadIdx.x, warp = tid >> 5, lane = tid & 31;
    int g = lane >> 2, q = lane & 3;
    int wm = (warp >> 1) * 32, wn = (warp & 1) * 64;

    float c[2][8][4] = {};

    for (int kb = 0; kb < C_; kb += 16) {
        #pragma unroll
        for (int i = 0; i < 2; i++) {  // A tile 64x16
            int idx = tid + i * 128;
            int row = idx >> 2, c4 = (idx & 3) * 4;
            float4 v = *(const float4*)(A + (size_t)row * C_ + kb + c4);
            uint32_t* d = &As[row * 20 + c4];
            d[0] = f2tf(v.x); d[1] = f2tf(v.y); d[2] = f2tf(v.z); d[3] = f2tf(v.w);
        }
        #pragma unroll
        for (int i = 0; i < 4; i++) {  // B tile 128x16 (x rows, k = channel)
            int idx = tid + i * 128;
            int row = idx >> 2, c4 = (idx & 3) * 4;
            float4 v = *(const float4*)(Bx + (size_t)row * C_ + kb + c4);
            uint32_t* d = &Bs[row * 20 + c4];
            d[0] = f2tf(v.x); d[1] = f2tf(v.y); d[2] = f2tf(v.z); d[3] = f2tf(v.w);
        }
        __syncthreads();
        #pragma unroll
        for (int ks = 0; ks < 16; ks += 8) {
            uint32_t af[2][4];
            #pragma unroll
            for (int m = 0; m < 2; m++) {
                int r0 = wm + m * 16;
                af[m][0] = As[(r0 + g)     * 20 + ks + q];
                af[m][1] = As[(r0 + g + 8) * 20 + ks + q];
                af[m][2] = As[(r0 + g)     * 20 + ks + q + 4];
                af[m][3] = As[(r0 + g + 8) * 20 + ks + q + 4];
            }
            #pragma unroll
            for (int n = 0; n < 8; n++) {
                int n0 = wn + n * 8;
                uint32_t bf[2];
                bf[0] = Bs[(n0 + g) * 20 + ks + q];
                bf[1] = Bs[(n0 + g) * 20 + ks + q + 4];
                mma8(c[0][n], af[0], bf);
                mma8(c[1][n], af[1], bf);
            }
        }
        __syncthreads();
    }
    #pragma unroll
    for (int m = 0; m < 2; m++)
        #pragma unroll
        for (int n = 0; n < 8; n++) {
            int row = wm + m * 16 + g;
            int col = wn + n * 8 + q * 2;
            *(float2*)(C + (size_t)row * N_ + col)       = make_float2(c[m][n][0], c[m][n][1]);
            *(float2*)(C + (size_t)(row + 8) * N_ + col) = make_float2(c[m][n][2], c[m][n][3]);
        }
}

// ---------------------------------------------------------------------------
// k_softmax: in-place masked softmax over each score row of length 4096
// grid 1536 blocks (b*192+m), 256 threads, 16 values per thread in registers.
// mask arrives as int32 (bool promoted by the harness).
// ---------------------------------------------------------------------------
__global__ __launch_bounds__(256) void k_softmax(const int* __restrict__ mask) {
    int row = blockIdx.x;
    int b = row / M_, m = row % M_, r = m & 7;
    float* S = g_S + (size_t)row * N_;
    const int* mrow = mask + ((size_t)(b * R_ + r)) * (N_ - R_);
    int tid = threadIdx.x;

    float vals[16];
    float mx = -1e30f;
    #pragma unroll
    for (int i = 0; i < 16; i++) {
        int n = i * 256 + tid;
        float s = S[n];
        bool valid = (n < R_) ? (n == r) : (mrow[n - R_] != 0);
        s = valid ? s : -1e30f;
        vals[i] = s;
        mx = fmaxf(mx, s);
    }
    __shared__ float sm[8], ss[8];
    float wmx = warpMax(mx);
    if ((tid & 31) == 0) sm[tid >> 5] = wmx;
    __syncthreads();
    float bm = sm[0];
    #pragma unroll
    for (int j = 1; j < 8; j++) bm = fmaxf(bm, sm[j]);

    float sum = 0.f;
    #pragma unroll
    for (int i = 0; i < 16; i++) {
        vals[i] = expf(vals[i] - bm);   // masked (-1e30) underflows to exactly 0
        sum += vals[i];
    }
    float wsm = warpSum(sum);
    if ((tid & 31) == 0) ss[tid >> 5] = wsm;
    __syncthreads();
    float tot = 0.f;
    #pragma unroll
    for (int j = 0; j < 8; j++) tot += ss[j];
    float inv = 1.0f / tot;
    #pragma unroll
    for (int i = 0; i < 16; i++) S[i * 256 + tid] = vals[i] * inv;
}

// ---------------------------------------------------------------------------
// k_ax: AX[b,m,c] = sum_n P[b,m,n] * x[b,n,c]      (tf32 mma GEMM)
// per batch: M=192, N(out)=1536, K=4096.  BM=64, BN=64, BK=16, 128 threads.
// grid (24, 3, 8)
// ---------------------------------------------------------------------------
__global__ __launch_bounds__(128) void k_ax(const float* __restrict__ x) {
    int b = blockIdx.z, mt = blockIdx.y, nt = blockIdx.x;
    const float* A  = g_S + ((size_t)b * M_ + mt * 64) * N_;
    const float* Bx = x + (size_t)b * N_ * C_ + nt * 64;
    float* C = g_AX + ((size_t)b * M_ + mt * 64) * C_ + nt * 64;

    __shared__ uint32_t As[64 * 20];
    __shared__ uint32_t Bs[16 * 68];

    int tid = threadIdx.x, warp = tid >> 5, lane = tid & 31;
    int g = lane >> 2, q = lane & 3;
    int wm = (warp >> 1) * 32, wn = (warp & 1) * 32;

    float c[2][4][4] = {};

    for (int kb = 0; kb < N_; kb += 16) {
        #pragma unroll
        for (int i = 0; i < 2; i++) {  // A tile 64x16 (P rows, lda = 4096)
            int idx = tid + i * 128;
            int row = idx >> 2, c4 = (idx & 3) * 4;
            float4 v = *(const float4*)(A + (size_t)row * N_ + kb + c4);
            uint32_t* d = &As[row * 20 + c4];
            d[0] = f2tf(v.x); d[1] = f2tf(v.y); d[2] = f2tf(v.z); d[3] = f2tf(v.w);
        }
        #pragma unroll
        for (int i = 0; i < 2; i++) {  // B tile 16(k=n) x 64(c)
            int idx = tid + i * 128;
            int row = idx >> 4, c4 = (idx & 15) * 4;
            float4 v = *(const float4*)(Bx + (size_t)(kb + row) * C_ + c4);
            uint32_t* d = &Bs[row * 68 + c4];
            d[0] = f2tf(v.x); d[1] = f2tf(v.y); d[2] = f2tf(v.z); d[3] = f2tf(v.w);
        }
        __syncthreads();
        #pragma unroll
        for (int ks = 0; ks < 16; ks += 8) {
            uint32_t af[2][4];
            #pragma unroll
            for (int m = 0; m < 2; m++) {
                int r0 = wm + m * 16;
                af[m][0] = As[(r0 + g)     * 20 + ks + q];
                af[m][1] = As[(r0 + g + 8) * 20 + ks + q];
                af[m][2] = As[(r0 + g)     * 20 + ks + q + 4];
                af[m][3] = As[(r0 + g + 8) * 20 + ks + q + 4];
            }
            #pragma unroll
            for (int n = 0; n < 4; n++) {
                int n0 = wn + n * 8;
                uint32_t bf[2];
                bf[0] = Bs[(ks + q)     * 68 + n0 + g];
                bf[1] = Bs[(ks + q + 4) * 68 + n0 + g];
                mma8(c[0][n], af[0], bf);
                mma8(c[1][n], af[1], bf);
            }
        }
        __syncthreads();
    }
    #pragma unroll
    for (int m = 0; m < 2; m++)
        #pragma unroll
        for (int n = 0; n < 4; n++) {
            int row = wm + m * 16 + g;
            int col = wn + n * 8 + q * 2;
            *(float2*)(C + (size_t)row * C_ + col)       = make_float2(c[m][n][0], c[m][n][1]);
            *(float2*)(C + (size_t)(row + 8) * C_ + col) = make_float2(c[m][n][2], c[m][n][3]);
        }
}

// ---------------------------------------------------------------------------
// k_d1: XCLS[b,r,cc] = sum_c AX[b, (cc/64)*8+r, c] * Wv[cc, c]
// grid (6, 8): c-tile, b. Each thread handles one cc, all 8 r.
// ---------------------------------------------------------------------------
__global__ __launch_bounds__(256) void k_d1(const float* __restrict__ Wv) {
    int b = blockIdx.y, t = threadIdx.x;
    int cc = blockIdx.x * 256 + t;
    int h = cc >> 6;
    const float4* wr = (const float4*)(Wv + (size_t)cc * C_);
    const float4* ax[R_];
    #pragma unroll
    for (int r = 0; r < R_; r++)
        ax[r] = (const float4*)(g_AX + ((size_t)b * M_ + h * 8 + r) * C_);
    float acc[R_] = {};
    for (int k4 = 0; k4 < C_ / 4; k4++) {
        float4 w = wr[k4];
        #pragma unroll
        for (int r = 0; r < R_; r++) {
            float4 a = ax[r][k4];
            acc[r] += a.x * w.x + a.y * w.y + a.z * w.z + a.w * w.w;
        }
    }
    #pragma unroll
    for (int r = 0; r < R_; r++)
        g_XCLS[(b * R_ + r) * C_ + cc] = acc[r];
}

// ---------------------------------------------------------------------------
// k_d2: out[b,r,c'] = bp[c'] + sum_cc XCLS[b,r,cc] * Wp[c',cc]
// grid (6, 8)
// ---------------------------------------------------------------------------
__global__ __launch_bounds__(256) void k_d2(const float* __restrict__ Wp,
                                            const float* __restrict__ bp,
                                            float* __restrict__ out) {
    int b = blockIdx.y, t = threadIdx.x;
    int cp = blockIdx.x * 256 + t;
    const float4* wr = (const float4*)(Wp + (size_t)cp * C_);
    const float4* xc[R_];
    #pragma unroll
    for (int r = 0; r < R_; r++)
        xc[r] = (const float4*)(g_XCLS + (size_t)(b * R_ + r) * C_);
    float acc[R_] = {};
    for (int k4 = 0; k4 < C_ / 4; k4++) {
        float4 w = wr[k4];
        #pragma unroll
        for (int r = 0; r < R_; r++) {
            float4 a = xc[r][k4];
            acc[r] += a.x * w.x + a.y * w.y + a.z * w.z + a.w * w.w;
        }
    }
    float bias = bp[cp];
    #pragma unroll
    for (int r = 0; r < R_; r++)
        out[((size_t)(b * R_ + r)) * C_ + cp] = acc[r] + bias;
}

// ---------------------------------------------------------------------------
// launch
// ---------------------------------------------------------------------------
extern "C" void kernel_launch(void* const* d_in, const int* in_sizes, int n_in,
                              void* d_out, int out_size) {
    const float* x  = (const float*)d_in[0];
    const int*   mask = (const int*)d_in[1];
    const float* Wq = (const float*)d_in[2];
    const float* Wk = (const float*)d_in[3];
    const float* Wv = (const float*)d_in[4];
    const float* Wp = (const float*)d_in[5];
    const float* bp = (const float*)d_in[6];
    float* out = (float*)d_out;

    k_q      <<<dim3(C_ / 256, B_), 256>>>(x, Wq);
    k_qk     <<<dim3(C_ / 256, H_), 256>>>(Wk);
    k_scores <<<dim3(N_ / 128, M_ / 64, B_), 128>>>(x);
    k_softmax<<<B_ * M_, 256>>>(mask);
    k_ax     <<<dim3(C_ / 64, M_ / 64, B_), 128>>>(x);
    k_d1     <<<dim3(C_ / 256, B_), 256>>>(Wv);
    k_d2     <<<dim3(C_ / 256, B_), 256>>>(Wp, bp, out);
}

// round 3
// speedup vs baseline: 1.1725x; 1.1725x over previous
#include <cuda_runtime.h>
#include <cstdint>

// Problem constants
#define B_   8
#define N_   4096
#define C_   1536
#define H_   24
#define R_   8
#define M_   192      // H_ * R_
#define SCALE_ 0.125f // (64)^-0.5

// Scratch (static device globals; no allocation allowed)
__device__ float    g_Q[B_ * R_ * C_];            // folded q (f32)
__device__ uint32_t g_QK[B_ * M_ * C_];           // q @ Wk, stored as tf32 bits
__device__ float    g_S[(size_t)B_ * M_ * N_];    // scores (f32), then P (tf32 bits) in place
__device__ float    g_AX[B_ * M_ * C_];           // P @ x (f32)
__device__ float    g_XCLS[B_ * R_ * C_];         // pooled values

// ---------------------------------------------------------------------------
// helpers
// ---------------------------------------------------------------------------
__device__ __forceinline__ uint32_t f2tf(float f) {
    uint32_t u;
    asm("cvt.rna.tf32.f32 %0, %1;" : "=r"(u) : "f"(f));
    return u;
}

__device__ __forceinline__ void mma8(float* c, const uint32_t* a, const uint32_t* b) {
    asm volatile(
        "mma.sync.aligned.m16n8k8.row.col.f32.tf32.tf32.f32 "
        "{%0,%1,%2,%3}, {%4,%5,%6,%7}, {%8,%9}, {%0,%1,%2,%3};"
        : "+f"(c[0]), "+f"(c[1]), "+f"(c[2]), "+f"(c[3])
        : "r"(a[0]), "r"(a[1]), "r"(a[2]), "r"(a[3]), "r"(b[0]), "r"(b[1]));
}

#define CPA(dst, src) asm volatile("cp.async.cg.shared.global [%0], [%1], 16;" :: "r"(dst), "l"(src))
#define CPCOMMIT()    asm volatile("cp.async.commit_group;")
#define CPWAIT1()     asm volatile("cp.async.wait_group 1;")
#define CPWAIT0()     asm volatile("cp.async.wait_group 0;")

__device__ __forceinline__ float warpMax(float v) {
    #pragma unroll
    for (int o = 16; o; o >>= 1) v = fmaxf(v, __shfl_xor_sync(0xffffffffu, v, o));
    return v;
}
__device__ __forceinline__ float warpSum(float v) {
    #pragma unroll
    for (int o = 16; o; o >>= 1) v += __shfl_xor_sync(0xffffffffu, v, o);
    return v;
}

// ---------------------------------------------------------------------------
// k_q: Q[b,r,c'] = SCALE * sum_c x[b,r,c] * Wq[c',c]   (r < 8)
// ---------------------------------------------------------------------------
__global__ __launch_bounds__(256) void k_q(const float* __restrict__ x,
                                           const float* __restrict__ Wq) {
    __shared__ float xs[R_ * C_];
    int b = blockIdx.y;
    int t = threadIdx.x;
    {
        const float4* src = (const float4*)(x + (size_t)b * N_ * C_);
        float4* dst = (float4*)xs;
        #pragma unroll 4
        for (int i = t; i < R_ * C_ / 4; i += 256) dst[i] = src[i];
    }
    __syncthreads();

    int cp = blockIdx.x * 256 + t;
    const float4* wr = (const float4*)(Wq + (size_t)cp * C_);
    float acc[R_] = {};
    for (int k4 = 0; k4 < C_ / 4; k4++) {
        float4 w = wr[k4];
        #pragma unroll
        for (int r = 0; r < R_; r++) {
            float4 a = ((const float4*)(xs + r * C_))[k4];
            acc[r] += a.x * w.x + a.y * w.y + a.z * w.z + a.w * w.w;
        }
    }
    #pragma unroll
    for (int r = 0; r < R_; r++)
        g_Q[(b * R_ + r) * C_ + cp] = acc[r] * SCALE_;
}

// ---------------------------------------------------------------------------
// k_qk: QK[b, h*8+r, c] = sum_d Q[b,r,h*64+d] * Wk[h*64+d, c]  (writes tf32)
// ---------------------------------------------------------------------------
__global__ __launch_bounds__(256) void k_qk(const float* __restrict__ Wk) {
    __shared__ float Qs[64][64];
    int h = blockIdx.y;
    int t = threadIdx.x;
    for (int i = t; i < 64 * 64; i += 256) {
        int br = i >> 6, d = i & 63;
        Qs[br][d] = g_Q[br * C_ + h * 64 + d];
    }
    __syncthreads();

    int c = blockIdx.x * 256 + t;
    float acc[64] = {};
    for (int d = 0; d < 64; d++) {
        float w = Wk[(size_t)(h * 64 + d) * C_ + c];
        #pragma unroll
        for (int br = 0; br < 64; br++) acc[br] += Qs[br][d] * w;
    }
    #pragma unroll
    for (int br = 0; br < 64; br++) {
        int b = br >> 3, r = br & 7;
        g_QK[((size_t)b * M_ + h * 8 + r) * C_ + c] = f2tf(acc[br]);
    }
}

// ---------------------------------------------------------------------------
// k_scores: S[b, m, n] = QK[b,m,:] . x[b,n,:]   tf32 mma, cp.async 2-stage
// BM=192 (all M), BN=64, BK=32. 384 threads, warp grid 6(m) x 2(n), warp 32x32.
// grid (64, 1, 8)
// ---------------------------------------------------------------------------
#define SC_AS   (192 * 36)   // one stage of A, u32
#define SC_BS   (64 * 36)
__global__ __launch_bounds__(384) void k_scores(const float* __restrict__ x) {
    extern __shared__ uint32_t sm[];
    uint32_t* As = sm;                    // 2 stages
    uint32_t* Bs = sm + 2 * SC_AS;

    int b = blockIdx.z, nt = blockIdx.x;
    const uint32_t* A  = g_QK + (size_t)b * M_ * C_;
    const float*    Bx = x + (size_t)b * N_ * C_ + (size_t)nt * 64 * C_;
    float*          Cp = g_S + (size_t)b * M_ * N_ + (size_t)nt * 64;

    int tid = threadIdx.x, lane = tid & 31, warp = tid >> 5;
    int g = lane >> 2, q = lane & 3;
    int mw = warp >> 1, nw = warp & 1;

    uint32_t as_sh = (uint32_t)__cvta_generic_to_shared(As);
    uint32_t bs_sh = (uint32_t)__cvta_generic_to_shared(Bs);

    float acc[2][4][4] = {};

    const int NK = C_ / 32;
    // stage loader: 1536 A-chunks + 512 B-chunks of 16B
    #define SC_LOAD(st, kb)                                                         \
        do {                                                                        \
            uint32_t a0 = as_sh + (st) * (SC_AS * 4);                               \
            uint32_t b0 = bs_sh + (st) * (SC_BS * 4);                               \
            for (int i = tid; i < 2048; i += 384) {                                 \
                if (i < 1536) {                                                     \
                    int row = i >> 3, c4 = (i & 7) << 2;                            \
                    CPA(a0 + (row * 36 + c4) * 4, A + (size_t)row * C_ + (kb) + c4);\
                } else {                                                            \
                    int j = i - 1536;                                               \
                    int row = j >> 3, c4 = (j & 7) << 2;                            \
                    CPA(b0 + (row * 36 + c4) * 4, Bx + (size_t)row * C_ + (kb) + c4);\
                }                                                                   \
            }                                                                       \
            CPCOMMIT();                                                             \
        } while (0)

    SC_LOAD(0, 0);
    for (int it = 0; it < NK; ++it) {
        if (it + 1 < NK) { SC_LOAD((it + 1) & 1, (it + 1) * 32); CPWAIT1(); }
        else             { CPWAIT0(); }
        __syncthreads();
        const uint32_t* as = As + (it & 1) * SC_AS;
        const uint32_t* bs = Bs + (it & 1) * SC_BS;
        #pragma unroll
        for (int ks = 0; ks < 32; ks += 8) {
            uint32_t af[2][4];
            #pragma unroll
            for (int m = 0; m < 2; m++) {
                int r0 = mw * 32 + m * 16;
                af[m][0] = as[(r0 + g)     * 36 + ks + q];
                af[m][1] = as[(r0 + g + 8) * 36 + ks + q];
                af[m][2] = as[(r0 + g)     * 36 + ks + q + 4];
                af[m][3] = as[(r0 + g + 8) * 36 + ks + q + 4];
            }
            #pragma unroll
            for (int n = 0; n < 4; n++) {
                int n0 = nw * 32 + n * 8;
                uint32_t bf[2];
                bf[0] = f2tf(__uint_as_float(bs[(n0 + g) * 36 + ks + q]));
                bf[1] = f2tf(__uint_as_float(bs[(n0 + g) * 36 + ks + q + 4]));
                mma8(acc[0][n], af[0], bf);
                mma8(acc[1][n], af[1], bf);
            }
        }
        __syncthreads();
    }
    #undef SC_LOAD

    #pragma unroll
    for (int m = 0; m < 2; m++)
        #pragma unroll
        for (int n = 0; n < 4; n++) {
            int row = mw * 32 + m * 16 + g;
            int col = nw * 32 + n * 8 + q * 2;
            *(float2*)(Cp + (size_t)row * N_ + col)       = make_float2(acc[m][n][0], acc[m][n][1]);
            *(float2*)(Cp + (size_t)(row + 8) * N_ + col) = make_float2(acc[m][n][2], acc[m][n][3]);
        }
}

// ---------------------------------------------------------------------------
// k_softmax: in-place masked softmax; reads f32 scores, writes tf32 P.
// mask arrives as int32 (bool promoted by the harness).
// ---------------------------------------------------------------------------
__global__ __launch_bounds__(256) void k_softmax(const int* __restrict__ mask) {
    int row = blockIdx.x;
    int b = row / M_, m = row % M_, r = m & 7;
    float* S = g_S + (size_t)row * N_;
    const int* mrow = mask + ((size_t)(b * R_ + r)) * (N_ - R_);
    int tid = threadIdx.x;

    float vals[16];
    float mx = -1e30f;
    #pragma unroll
    for (int i = 0; i < 16; i++) {
        int n = i * 256 + tid;
        float s = S[n];
        bool valid = (n < R_) ? (n == r) : (mrow[n - R_] != 0);
        s = valid ? s : -1e30f;
        vals[i] = s;
        mx = fmaxf(mx, s);
    }
    __shared__ float smx[8], ssm[8];
    float wmx = warpMax(mx);
    if ((tid & 31) == 0) smx[tid >> 5] = wmx;
    __syncthreads();
    float bm = smx[0];
    #pragma unroll
    for (int j = 1; j < 8; j++) bm = fmaxf(bm, smx[j]);

    float sum = 0.f;
    #pragma unroll
    for (int i = 0; i < 16; i++) {
        vals[i] = expf(vals[i] - bm);
        sum += vals[i];
    }
    float wsm = warpSum(sum);
    if ((tid & 31) == 0) ssm[tid >> 5] = wsm;
    __syncthreads();
    float tot = 0.f;
    #pragma unroll
    for (int j = 0; j < 8; j++) tot += ssm[j];
    float inv = 1.0f / tot;
    uint32_t* Su = (uint32_t*)S;
    #pragma unroll
    for (int i = 0; i < 16; i++) Su[i * 256 + tid] = f2tf(vals[i] * inv);
}

// ---------------------------------------------------------------------------
// k_ax: AX[b,m,c] = sum_n P[b,m,n] * x[b,n,c]   tf32 mma, cp.async 2-stage
// BM=192 (all M), BN=64 cols, BK=32 over N=4096. 384 threads, warp 6x2.
// grid (24, 1, 8)
// ---------------------------------------------------------------------------
#define AX_AS   (192 * 36)
#define AX_BS   (32 * 68)
__global__ __launch_bounds__(384) void k_ax(const float* __restrict__ x) {
    extern __shared__ uint32_t sm[];
    uint32_t* As = sm;
    uint32_t* Bs = sm + 2 * AX_AS;

    int b = blockIdx.z, nt = blockIdx.x;
    const uint32_t* A  = (const uint32_t*)g_S + (size_t)b * M_ * N_;   // P as tf32
    const float*    Bx = x + (size_t)b * N_ * C_ + nt * 64;
    float*          Cp = g_AX + (size_t)b * M_ * C_ + nt * 64;

    int tid = threadIdx.x, lane = tid & 31, warp = tid >> 5;
    int g = lane >> 2, q = lane & 3;
    int mw = warp >> 1, nw = warp & 1;

    uint32_t as_sh = (uint32_t)__cvta_generic_to_shared(As);
    uint32_t bs_sh = (uint32_t)__cvta_generic_to_shared(Bs);

    float acc[2][4][4] = {};

    const int NK = N_ / 32;
    #define AX_LOAD(st, kb)                                                              \
        do {                                                                             \
            uint32_t a0 = as_sh + (st) * (AX_AS * 4);                                    \
            uint32_t b0 = bs_sh + (st) * (AX_BS * 4);                                    \
            for (int i = tid; i < 2048; i += 384) {                                      \
                if (i < 1536) {                                                          \
                    int row = i >> 3, c4 = (i & 7) << 2;                                 \
                    CPA(a0 + (row * 36 + c4) * 4, A + (size_t)row * N_ + (kb) + c4);     \
                } else {                                                                 \
                    int j = i - 1536;                                                    \
                    int row = j >> 4, c4 = (j & 15) << 2;                                \
                    CPA(b0 + (row * 68 + c4) * 4, Bx + (size_t)((kb) + row) * C_ + c4);  \
                }                                                                        \
            }                                                                            \
            CPCOMMIT();                                                                  \
        } while (0)

    AX_LOAD(0, 0);
    for (int it = 0; it < NK; ++it) {
        if (it + 1 < NK) { AX_LOAD((it + 1) & 1, (it + 1) * 32); CPWAIT1(); }
        else             { CPWAIT0(); }
        __syncthreads();
        const uint32_t* as = As + (it & 1) * AX_AS;
        const uint32_t* bs = Bs + (it & 1) * AX_BS;
        #pragma unroll
        for (int ks = 0; ks < 32; ks += 8) {
            uint32_t af[2][4];
            #pragma unroll
            for (int m = 0; m < 2; m++) {
                int r0 = mw * 32 + m * 16;
                af[m][0] = as[(r0 + g)     * 36 + ks + q];
                af[m][1] = as[(r0 + g + 8) * 36 + ks + q];
                af[m][2] = as[(r0 + g)     * 36 + ks + q + 4];
                af[m][3] = as[(r0 + g + 8) * 36 + ks + q + 4];
            }
            #pragma unroll
            for (int n = 0; n < 4; n++) {
                int n0 = nw * 32 + n * 8;
                uint32_t bf[2];
                bf[0] = f2tf(__uint_as_float(bs[(ks + q)     * 68 + n0 + g]));
                bf[1] = f2tf(__uint_as_float(bs[(ks + q + 4) * 68 + n0 + g]));
                mma8(acc[0][n], af[0], bf);
                mma8(acc[1][n], af[1], bf);
            }
        }
        __syncthreads();
    }
    #undef AX_LOAD

    #pragma unroll
    for (int m = 0; m < 2; m++)
        #pragma unroll
        for (int n = 0; n < 4; n++) {
            int row = mw * 32 + m * 16 + g;
            int col = nw * 32 + n * 8 + q * 2;
            *(float2*)(Cp + (size_t)row * C_ + col)       = make_float2(acc[m][n][0], acc[m][n][1]);
            *(float2*)(Cp + (size_t)(row + 8) * C_ + col) = make_float2(acc[m][n][2], acc[m][n][3]);
        }
}

// ---------------------------------------------------------------------------
// k_d1: XCLS[b,r,cc] = sum_c AX[b, (cc/64)*8+r, c] * Wv[cc, c]
// ---------------------------------------------------------------------------
__global__ __launch_bounds__(256) void k_d1(const float* __restrict__ Wv) {
    int b = blockIdx.y, t = threadIdx.x;
    int cc = blockIdx.x * 256 + t;
    int h = cc >> 6;
    const float4* wr = (const float4*)(Wv + (size_t)cc * C_);
    const float4* ax[R_];
    #pragma unroll
    for (int r = 0; r < R_; r++)
        ax[r] = (const float4*)(g_AX + ((size_t)b * M_ + h * 8 + r) * C_);
    float acc[R_] = {};
    for (int k4 = 0; k4 < C_ / 4; k4++) {
        float4 w = wr[k4];
        #pragma unroll
        for (int r = 0; r < R_; r++) {
            float4 a = ax[r][k4];
            acc[r] += a.x * w.x + a.y * w.y + a.z * w.z + a.w * w.w;
        }
    }
    #pragma unroll
    for (int r = 0; r < R_; r++)
        g_XCLS[(b * R_ + r) * C_ + cc] = acc[r];
}

// ---------------------------------------------------------------------------
// k_d2: out[b,r,c'] = bp[c'] + sum_cc XCLS[b,r,cc] * Wp[c',cc]
// ---------------------------------------------------------------------------
__global__ __launch_bounds__(256) void k_d2(const float* __restrict__ Wp,
                                            const float* __restrict__ bp,
                                            float* __restrict__ out) {
    int b = blockIdx.y, t = threadIdx.x;
    int cp = blockIdx.x * 256 + t;
    const float4* wr = (const float4*)(Wp + (size_t)cp * C_);
    const float4* xc[R_];
    #pragma unroll
    for (int r = 0; r < R_; r++)
        xc[r] = (const float4*)(g_XCLS + (size_t)(b * R_ + r) * C_);
    float acc[R_] = {};
    for (int k4 = 0; k4 < C_ / 4; k4++) {
        float4 w = wr[k4];
        #pragma unroll
        for (int r = 0; r < R_; r++) {
            float4 a = xc[r][k4];
            acc[r] += a.x * w.x + a.y * w.y + a.z * w.z + a.w * w.w;
        }
    }
    float bias = bp[cp];
    #pragma unroll
    for (int r = 0; r < R_; r++)
        out[((size_t)(b * R_ + r)) * C_ + cp] = acc[r] + bias;
}

// ---------------------------------------------------------------------------
// launch
// ---------------------------------------------------------------------------
extern "C" void kernel_launch(void* const* d_in, const int* in_sizes, int n_in,
                              void* d_out, int out_size) {
    const float* x    = (const float*)d_in[0];
    const int*   mask = (const int*)d_in[1];
    const float* Wq   = (const float*)d_in[2];
    const float* Wk   = (const float*)d_in[3];
    const float* Wv   = (const float*)d_in[4];
    const float* Wp   = (const float*)d_in[5];
    const float* bp   = (const float*)d_in[6];
    float* out = (float*)d_out;

    const int SC_SMEM = (2 * SC_AS + 2 * SC_BS) * 4;  // 73728 B
    const int AX_SMEM = (2 * AX_AS + 2 * AX_BS) * 4;  // 72704 B
    cudaFuncSetAttribute(k_scores, cudaFuncAttributeMaxDynamicSharedMemorySize, SC_SMEM);
    cudaFuncSetAttribute(k_ax,     cudaFuncAttributeMaxDynamicSharedMemorySize, AX_SMEM);

    k_q      <<<dim3(C_ / 256, B_), 256>>>(x, Wq);
    k_qk     <<<dim3(C_ / 256, H_), 256>>>(Wk);
    k_scores <<<dim3(N_ / 64, 1, B_), 384, SC_SMEM>>>(x);
    k_softmax<<<B_ * M_, 256>>>(mask);
    k_ax     <<<dim3(C_ / 64, 1, B_), 384, AX_SMEM>>>(x);
    k_d1     <<<dim3(C_ / 256, B_), 256>>>(Wv);
    k_d2     <<<dim3(C_ / 256, B_), 256>>>(Wp, bp, out);
}

// round 5
// speedup vs baseline: 1.4241x; 1.2145x over previous
#include <cuda_runtime.h>
#include <cuda_fp16.h>
#include <cstdint>

// Problem constants
#define B_   8
#define N_   4096
#define C_   1536
#define H_   24
#define R_   8
#define M_   192
#define SCALE_ 0.125f

// Scratch (static device globals)
__device__ float    g_Q[B_ * R_ * C_];
__device__ __half   g_QK16[B_ * M_ * C_];              // q@Wk, fp16
__device__ float    g_S[(size_t)B_ * M_ * N_];         // scores f32
__device__ __half   g_P16[(size_t)B_ * M_ * N_];       // softmax probs fp16
__device__ float    g_AX[B_ * M_ * C_];                // P @ x
__device__ float    g_XCLS[B_ * R_ * C_];
__device__ __half   g_x16[(size_t)B_ * N_ * C_];       // x fp16

// ---------------------------------------------------------------------------
// helpers
// ---------------------------------------------------------------------------
#define CPA(dst, src) asm volatile("cp.async.cg.shared.global [%0], [%1], 16;" :: "r"(dst), "l"(src))
#define CPCOMMIT()    asm volatile("cp.async.commit_group;")
#define CPWAIT0()     asm volatile("cp.async.wait_group 0;")
#define CPWAIT1()     asm volatile("cp.async.wait_group 1;")
#define CPWAIT2()     asm volatile("cp.async.wait_group 2;")

#define LDSM4(r0, r1, r2, r3, addr) \
    asm volatile("ldmatrix.sync.aligned.m8n8.x4.shared.b16 {%0,%1,%2,%3}, [%4];" \
                 : "=r"(r0), "=r"(r1), "=r"(r2), "=r"(r3) : "r"(addr))
#define LDSM4T(r0, r1, r2, r3, addr) \
    asm volatile("ldmatrix.sync.aligned.m8n8.x4.trans.shared.b16 {%0,%1,%2,%3}, [%4];" \
                 : "=r"(r0), "=r"(r1), "=r"(r2), "=r"(r3) : "r"(addr))

__device__ __forceinline__ void mma16(float* c, const uint32_t* a, const uint32_t* b) {
    asm volatile(
        "mma.sync.aligned.m16n8k16.row.col.f32.f16.f16.f32 "
        "{%0,%1,%2,%3}, {%4,%5,%6,%7}, {%8,%9}, {%0,%1,%2,%3};"
        : "+f"(c[0]), "+f"(c[1]), "+f"(c[2]), "+f"(c[3])
        : "r"(a[0]), "r"(a[1]), "r"(a[2]), "r"(a[3]), "r"(b[0]), "r"(b[1]));
}

__device__ __forceinline__ float warpMax(float v) {
    #pragma unroll
    for (int o = 16; o; o >>= 1) v = fmaxf(v, __shfl_xor_sync(0xffffffffu, v, o));
    return v;
}
__device__ __forceinline__ float warpSum(float v) {
    #pragma unroll
    for (int o = 16; o; o >>= 1) v += __shfl_xor_sync(0xffffffffu, v, o);
    return v;
}

// ---------------------------------------------------------------------------
// k_conv: x (f32) -> g_x16 (fp16), linear
// ---------------------------------------------------------------------------
__global__ __launch_bounds__(256) void k_conv(const float* __restrict__ x) {
    const size_t total = (size_t)B_ * N_ * C_ / 8;
    size_t stride = (size_t)gridDim.x * 256;
    for (size_t i = blockIdx.x * 256 + threadIdx.x; i < total; i += stride) {
        float4 v0 = ((const float4*)x)[i * 2];
        float4 v1 = ((const float4*)x)[i * 2 + 1];
        __half h[8];
        h[0] = __float2half_rn(v0.x); h[1] = __float2half_rn(v0.y);
        h[2] = __float2half_rn(v0.z); h[3] = __float2half_rn(v0.w);
        h[4] = __float2half_rn(v1.x); h[5] = __float2half_rn(v1.y);
        h[6] = __float2half_rn(v1.z); h[7] = __float2half_rn(v1.w);
        ((uint4*)g_x16)[i] = *(uint4*)h;
    }
}

// ---------------------------------------------------------------------------
// k_q: Q[b,r,c'] = SCALE * sum_c x[b,r,c] * Wq[c',c]
// ---------------------------------------------------------------------------
__global__ __launch_bounds__(256) void k_q(const float* __restrict__ x,
                                           const float* __restrict__ Wq) {
    __shared__ float xs[R_ * C_];
    int b = blockIdx.y, t = threadIdx.x;
    {
        const float4* src = (const float4*)(x + (size_t)b * N_ * C_);
        float4* dst = (float4*)xs;
        #pragma unroll 4
        for (int i = t; i < R_ * C_ / 4; i += 256) dst[i] = src[i];
    }
    __syncthreads();
    int cp = blockIdx.x * 256 + t;
    const float4* wr = (const float4*)(Wq + (size_t)cp * C_);
    float acc[R_] = {};
    for (int k4 = 0; k4 < C_ / 4; k4++) {
        float4 w = wr[k4];
        #pragma unroll
        for (int r = 0; r < R_; r++) {
            float4 a = ((const float4*)(xs + r * C_))[k4];
            acc[r] += a.x * w.x + a.y * w.y + a.z * w.z + a.w * w.w;
        }
    }
    #pragma unroll
    for (int r = 0; r < R_; r++)
        g_Q[(b * R_ + r) * C_ + cp] = acc[r] * SCALE_;
}

// ---------------------------------------------------------------------------
// k_qk: QK16[b, h*8+r, c] = sum_d Q[b,r,h*64+d] * Wk[h*64+d, c]   (fp16 out)
// ---------------------------------------------------------------------------
__global__ __launch_bounds__(256) void k_qk(const float* __restrict__ Wk) {
    __shared__ float Qs[64][64];
    int h = blockIdx.y, t = threadIdx.x;
    for (int i = t; i < 64 * 64; i += 256) {
        int br = i >> 6, d = i & 63;
        Qs[br][d] = g_Q[br * C_ + h * 64 + d];
    }
    __syncthreads();
    int c = blockIdx.x * 256 + t;
    float acc[64] = {};
    for (int d = 0; d < 64; d++) {
        float w = Wk[(size_t)(h * 64 + d) * C_ + c];
        #pragma unroll
        for (int br = 0; br < 64; br++) acc[br] += Qs[br][d] * w;
    }
    #pragma unroll
    for (int br = 0; br < 64; br++) {
        int b = br >> 3, r = br & 7;
        g_QK16[((size_t)(b * M_ + h * 8 + r)) * C_ + c] = __float2half_rn(acc[br]);
    }
}

// ---------------------------------------------------------------------------
// k_scores: S = QK16 . x16^T   fp16 mma m16n8k16, ldmatrix, 3-stage cp.async
// BM=192 (all M), BN=64, BK=32. 192 threads: 6 warps (3m x 2n), warp 64x32.
// grid (64, 1, 8)
// A stage: 192 x 40 halfs (80B rows), B stage: 64 x 40 halfs.
// ---------------------------------------------------------------------------
#define SC_STAGE 20480                       // bytes per stage
#define SC_BOFF  15360                       // B offset within stage
__global__ __launch_bounds__(192) void k_scores() {
    extern __shared__ char smem[];
    uint32_t sb = (uint32_t)__cvta_generic_to_shared(smem);
    int b = blockIdx.z, nt = blockIdx.x;
    int tid = threadIdx.x, lane = tid & 31, warp = tid >> 5;
    int g = lane >> 2, q = lane & 3;
    int m0 = (warp >> 1) * 64, n0 = (warp & 1) * 32;

    const __half* Ab = g_QK16 + (size_t)b * M_ * C_;
    const __half* Bb = g_x16 + ((size_t)(b * N_ + nt * 64)) * C_;

    float acc[4][4][4] = {};

    #define SC_LOAD(st, itv)                                                     \
        do {                                                                     \
            uint32_t a0 = sb + (st) * SC_STAGE;                                  \
            uint32_t b0 = a0 + SC_BOFF;                                          \
            int kb = (itv) * 32;                                                 \
            for (int i = tid; i < 1024; i += 192) {                              \
                if (i < 768) {                                                   \
                    int row = i >> 2, ch = i & 3;                                \
                    CPA(a0 + (row * 40 + ch * 8) * 2,                            \
                        Ab + (size_t)row * C_ + kb + ch * 8);                    \
                } else {                                                         \
                    int j = i - 768;                                             \
                    int row = j >> 2, ch = j & 3;                                \
                    CPA(b0 + (row * 40 + ch * 8) * 2,                            \
                        Bb + (size_t)row * C_ + kb + ch * 8);                    \
                }                                                                \
            }                                                                    \
            CPCOMMIT();                                                          \
        } while (0)

    const int NK = C_ / 32;  // 48
    SC_LOAD(0, 0); SC_LOAD(1, 1); SC_LOAD(2, 2);

    for (int it = 0; it < NK; ++it) {
        int s = it % 3;
        int pend = NK - 1 - it;
        if (pend >= 2)      CPWAIT2();
        else if (pend == 1) CPWAIT1();
        else                CPWAIT0();
        __syncthreads();

        uint32_t aB = sb + s * SC_STAGE;
        uint32_t bB = aB + SC_BOFF;
        #pragma unroll
        for (int ks = 0; ks < 32; ks += 16) {
            uint32_t a[4][4];
            #pragma unroll
            for (int mi = 0; mi < 4; mi++) {
                uint32_t ad = aB + ((m0 + mi * 16 + (lane & 7) + ((lane >> 3) & 1) * 8) * 40
                                    + ks + (lane >> 4) * 8) * 2;
                LDSM4(a[mi][0], a[mi][1], a[mi][2], a[mi][3], ad);
            }
            uint32_t bf[2][4];
            #pragma unroll
            for (int bi = 0; bi < 2; bi++) {
                uint32_t bd = bB + ((n0 + bi * 16 + (lane & 7) + ((lane >> 4) & 1) * 8) * 40
                                    + ks + ((lane >> 3) & 1) * 8) * 2;
                LDSM4(bf[bi][0], bf[bi][1], bf[bi][2], bf[bi][3], bd);
            }
            #pragma unroll
            for (int mi = 0; mi < 4; mi++)
                #pragma unroll
                for (int ni = 0; ni < 4; ni++)
                    mma16(acc[mi][ni], a[mi], &bf[ni >> 1][(ni & 1) * 2]);
        }
        __syncthreads();
        int nx = it + 3;
        if (nx < NK) SC_LOAD(s, nx);
    }
    #undef SC_LOAD

    float* Cb = g_S + (size_t)b * M_ * N_ + (size_t)nt * 64;
    #pragma unroll
    for (int mi = 0; mi < 4; mi++)
        #pragma unroll
        for (int ni = 0; ni < 4; ni++) {
            int row = m0 + mi * 16 + g;
            int col = n0 + ni * 8 + q * 2;
            *(float2*)(Cb + (size_t)row * N_ + col)       = make_float2(acc[mi][ni][0], acc[mi][ni][1]);
            *(float2*)(Cb + (size_t)(row + 8) * N_ + col) = make_float2(acc[mi][ni][2], acc[mi][ni][3]);
        }
}

// ---------------------------------------------------------------------------
// k_softmax: masked softmax; reads g_S f32, writes g_P16 fp16
// ---------------------------------------------------------------------------
__global__ __launch_bounds__(256) void k_softmax(const int* __restrict__ mask) {
    int row = blockIdx.x;
    int b = row / M_, m = row % M_, r = m & 7;
    const float* S = g_S + (size_t)row * N_;
    __half* P = g_P16 + (size_t)row * N_;
    const int* mrow = mask + ((size_t)(b * R_ + r)) * (N_ - R_);
    int tid = threadIdx.x;

    float vals[16];
    float mx = -1e30f;
    #pragma unroll
    for (int i = 0; i < 16; i++) {
        int n = i * 256 + tid;
        float s = S[n];
        bool valid = (n < R_) ? (n == r) : (mrow[n - R_] != 0);
        s = valid ? s : -1e30f;
        vals[i] = s;
        mx = fmaxf(mx, s);
    }
    __shared__ float smx[8], ssm[8];
    float wmx = warpMax(mx);
    if ((tid & 31) == 0) smx[tid >> 5] = wmx;
    __syncthreads();
    float bm = smx[0];
    #pragma unroll
    for (int j = 1; j < 8; j++) bm = fmaxf(bm, smx[j]);

    float sum = 0.f;
    #pragma unroll
    for (int i = 0; i < 16; i++) {
        vals[i] = expf(vals[i] - bm);
        sum += vals[i];
    }
    float wsm = warpSum(sum);
    if ((tid & 31) == 0) ssm[tid >> 5] = wsm;
    __syncthreads();
    float tot = 0.f;
    #pragma unroll
    for (int j = 0; j < 8; j++) tot += ssm[j];
    float inv = 1.0f / tot;
    #pragma unroll
    for (int i = 0; i < 16; i++) P[i * 256 + tid] = __float2half_rn(vals[i] * inv);
}

// ---------------------------------------------------------------------------
// k_ax: AX[m,c] = sum_n P16[m,n] * x16[n,c]   fp16 mma, B via ldmatrix.trans
// BM=192, BN=64 (c), BK=32 (tokens). 192 threads, warp 64x32. grid (24, 1, 8)
// A stage: 192 x 40 halfs; B stage: 32 x 72 halfs (144B rows).
// ---------------------------------------------------------------------------
#define AX_STAGE 19968
#define AX_BOFF  15360
__global__ __launch_bounds__(192) void k_ax() {
    extern __shared__ char smem[];
    uint32_t sb = (uint32_t)__cvta_generic_to_shared(smem);
    int b = blockIdx.z, nt = blockIdx.x;
    int tid = threadIdx.x, lane = tid & 31, warp = tid >> 5;
    int g = lane >> 2, q = lane & 3;
    int m0 = (warp >> 1) * 64, n0 = (warp & 1) * 32;

    const __half* Ab = g_P16 + (size_t)b * M_ * N_;
    const __half* Bx = g_x16 + (size_t)b * N_ * C_ + nt * 64;

    float acc[4][4][4] = {};

    #define AX_LOAD(st, itv)                                                     \
        do {                                                                     \
            uint32_t a0 = sb + (st) * AX_STAGE;                                  \
            uint32_t b0 = a0 + AX_BOFF;                                          \
            int kb = (itv) * 32;                                                 \
            for (int i = tid; i < 1024; i += 192) {                              \
                if (i < 768) {                                                   \
                    int row = i >> 2, ch = i & 3;                                \
                    CPA(a0 + (row * 40 + ch * 8) * 2,                            \
                        Ab + (size_t)row * N_ + kb + ch * 8);                    \
                } else {                                                         \
                    int j = i - 768;                                             \
                    int row = j >> 3, ch = j & 7;                                \
                    CPA(b0 + (row * 72 + ch * 8) * 2,                            \
                        Bx + (size_t)(kb + row) * C_ + ch * 8);                  \
                }                                                                \
            }                                                                    \
            CPCOMMIT();                                                          \
        } while (0)

    const int NK = N_ / 32;  // 128
    AX_LOAD(0, 0); AX_LOAD(1, 1); AX_LOAD(2, 2);

    for (int it = 0; it < NK; ++it) {
        int s = it % 3;
        int pend = NK - 1 - it;
        if (pend >= 2)      CPWAIT2();
        else if (pend == 1) CPWAIT1();
        else                CPWAIT0();
        __syncthreads();

        uint32_t aB = sb + s * AX_STAGE;
        uint32_t bB = aB + AX_BOFF;
        #pragma unroll
        for (int ks = 0; ks < 32; ks += 16) {
            uint32_t a[4][4];
            #pragma unroll
            for (int mi = 0; mi < 4; mi++) {
                uint32_t ad = aB + ((m0 + mi * 16 + (lane & 7) + ((lane >> 3) & 1) * 8) * 40
                                    + ks + (lane >> 4) * 8) * 2;
                LDSM4(a[mi][0], a[mi][1], a[mi][2], a[mi][3], ad);
            }
            uint32_t bf[2][4];
            #pragma unroll
            for (int bi = 0; bi < 2; bi++) {
                // trans: storage rows = k (tokens), cols = n (channels)
                uint32_t bd = bB + ((ks + (lane & 7) + ((lane >> 3) & 1) * 8) * 72
                                    + n0 + bi * 16 + ((lane >> 4) & 1) * 8) * 2;
                LDSM4T(bf[bi][0], bf[bi][1], bf[bi][2], bf[bi][3], bd);
            }
            #pragma unroll
            for (int mi = 0; mi < 4; mi++)
                #pragma unroll
                for (int ni = 0; ni < 4; ni++)
                    mma16(acc[mi][ni], a[mi], &bf[ni >> 1][(ni & 1) * 2]);
        }
        __syncthreads();
        int nx = it + 3;
        if (nx < NK) AX_LOAD(s, nx);
    }
    #undef AX_LOAD

    float* Cb = g_AX + (size_t)b * M_ * C_ + nt * 64;
    #pragma unroll
    for (int mi = 0; mi < 4; mi++)
        #pragma unroll
        for (int ni = 0; ni < 4; ni++) {
            int row = m0 + mi * 16 + g;
            int col = n0 + ni * 8 + q * 2;
            *(float2*)(Cb + (size_t)row * C_ + col)       = make_float2(acc[mi][ni][0], acc[mi][ni][1]);
            *(float2*)(Cb + (size_t)(row + 8) * C_ + col) = make_float2(acc[mi][ni][2], acc[mi][ni][3]);
        }
}

// ---------------------------------------------------------------------------
// k_d1: XCLS[b,r,cc] = sum_c AX[b, (cc/64)*8+r, c] * Wv[cc, c]
// ---------------------------------------------------------------------------
__global__ __launch_bounds__(256) void k_d1(const float* __restrict__ Wv) {
    int b = blockIdx.y, t = threadIdx.x;
    int cc = blockIdx.x * 256 + t;
    int h = cc >> 6;
    const float4* wr = (const float4*)(Wv + (size_t)cc * C_);
    const float4* ax[R_];
    #pragma unroll
    for (int r = 0; r < R_; r++)
        ax[r] = (const float4*)(g_AX + ((size_t)b * M_ + h * 8 + r) * C_);
    float acc[R_] = {};
    for (int k4 = 0; k4 < C_ / 4; k4++) {
        float4 w = wr[k4];
        #pragma unroll
        for (int r = 0; r < R_; r++) {
            float4 a = ax[r][k4];
            acc[r] += a.x * w.x + a.y * w.y + a.z * w.z + a.w * w.w;
        }
    }
    #pragma unroll
    for (int r = 0; r < R_; r++)
        g_XCLS[(b * R_ + r) * C_ + cc] = acc[r];
}

// ---------------------------------------------------------------------------
// k_d2: out[b,r,c'] = bp[c'] + sum_cc XCLS[b,r,cc] * Wp[c',cc]
// ---------------------------------------------------------------------------
__global__ __launch_bounds__(256) void k_d2(const float* __restrict__ Wp,
                                            const float* __restrict__ bp,
                                            float* __restrict__ out) {
    int b = blockIdx.y, t = threadIdx.x;
    int cp = blockIdx.x * 256 + t;
    const float4* wr = (const float4*)(Wp + (size_t)cp * C_);
    const float4* xc[R_];
    #pragma unroll
    for (int r = 0; r < R_; r++)
        xc[r] = (const float4*)(g_XCLS + (size_t)(b * R_ + r) * C_);
    float acc[R_] = {};
    for (int k4 = 0; k4 < C_ / 4; k4++) {
        float4 w = wr[k4];
        #pragma unroll
        for (int r = 0; r < R_; r++) {
            float4 a = xc[r][k4];
            acc[r] += a.x * w.x + a.y * w.y + a.z * w.z + a.w * w.w;
        }
    }
    float bias = bp[cp];
    #pragma unroll
    for (int r = 0; r < R_; r++)
        out[((size_t)(b * R_ + r)) * C_ + cp] = acc[r] + bias;
}

// ---------------------------------------------------------------------------
// launch
// ---------------------------------------------------------------------------
extern "C" void kernel_launch(void* const* d_in, const int* in_sizes, int n_in,
                              void* d_out, int out_size) {
    const float* x    = (const float*)d_in[0];
    const int*   mask = (const int*)d_in[1];
    const float* Wq   = (const float*)d_in[2];
    const float* Wk   = (const float*)d_in[3];
    const float* Wv   = (const float*)d_in[4];
    const float* Wp   = (const float*)d_in[5];
    const float* bp   = (const float*)d_in[6];
    float* out = (float*)d_out;

    const int SC_SMEM = 3 * SC_STAGE;  // 61440
    const int AX_SMEM = 3 * AX_STAGE;  // 59904
    cudaFuncSetAttribute(k_scores, cudaFuncAttributeMaxDynamicSharedMemorySize, SC_SMEM);
    cudaFuncSetAttribute(k_ax,     cudaFuncAttributeMaxDynamicSharedMemorySize, AX_SMEM);

    k_conv   <<<4096, 256>>>(x);
    k_q      <<<dim3(C_ / 256, B_), 256>>>(x, Wq);
    k_qk     <<<dim3(C_ / 256, H_), 256>>>(Wk);
    k_scores <<<dim3(N_ / 64, 1, B_), 192, SC_SMEM>>>();
    k_softmax<<<B_ * M_, 256>>>(mask);
    k_ax     <<<dim3(C_ / 64, 1, B_), 192, AX_SMEM>>>();
    k_d1     <<<dim3(C_ / 256, B_), 256>>>(Wv);
    k_d2     <<<dim3(C_ / 256, B_), 256>>>(Wp, bp, out);
}

// round 6
// speedup vs baseline: 1.4434x; 1.0136x over previous
#include <cuda_runtime.h>
#include <cuda_fp16.h>
#include <cstdint>

// Problem constants
#define B_   8
#define N_   4096
#define C_   1536
#define H_   24
#define R_   8
#define M_   192
#define SCALE_ 0.125f

// Scratch (static device globals)
__device__ float    g_Q[B_ * R_ * C_];
__device__ __half   g_QK16[B_ * M_ * C_];              // q@Wk, fp16
__device__ float    g_S[(size_t)B_ * M_ * N_];         // scores f32
__device__ __half   g_P16[(size_t)B_ * M_ * N_];       // softmax probs fp16
__device__ float    g_AX[B_ * M_ * C_];                // P @ x (split-K accumulated)
__device__ float    g_XCLS[B_ * R_ * C_];
__device__ __half   g_x16[(size_t)B_ * N_ * C_];       // x fp16

// ---------------------------------------------------------------------------
// helpers
// ---------------------------------------------------------------------------
#define CPA(dst, src) asm volatile("cp.async.cg.shared.global [%0], [%1], 16;" :: "r"(dst), "l"(src))
#define CPCOMMIT()    asm volatile("cp.async.commit_group;")
#define CPWAIT0()     asm volatile("cp.async.wait_group 0;")
#define CPWAIT1()     asm volatile("cp.async.wait_group 1;")
#define CPWAIT2()     asm volatile("cp.async.wait_group 2;")

#define LDSM4(r0, r1, r2, r3, addr) \
    asm volatile("ldmatrix.sync.aligned.m8n8.x4.shared.b16 {%0,%1,%2,%3}, [%4];" \
                 : "=r"(r0), "=r"(r1), "=r"(r2), "=r"(r3) : "r"(addr))
#define LDSM4T(r0, r1, r2, r3, addr) \
    asm volatile("ldmatrix.sync.aligned.m8n8.x4.trans.shared.b16 {%0,%1,%2,%3}, [%4];" \
                 : "=r"(r0), "=r"(r1), "=r"(r2), "=r"(r3) : "r"(addr))

__device__ __forceinline__ void mma16(float* c, const uint32_t* a, const uint32_t* b) {
    asm volatile(
        "mma.sync.aligned.m16n8k16.row.col.f32.f16.f16.f32 "
        "{%0,%1,%2,%3}, {%4,%5,%6,%7}, {%8,%9}, {%0,%1,%2,%3};"
        : "+f"(c[0]), "+f"(c[1]), "+f"(c[2]), "+f"(c[3])
        : "r"(a[0]), "r"(a[1]), "r"(a[2]), "r"(a[3]), "r"(b[0]), "r"(b[1]));
}

__device__ __forceinline__ float warpMax(float v) {
    #pragma unroll
    for (int o = 16; o; o >>= 1) v = fmaxf(v, __shfl_xor_sync(0xffffffffu, v, o));
    return v;
}
__device__ __forceinline__ float warpSum(float v) {
    #pragma unroll
    for (int o = 16; o; o >>= 1) v += __shfl_xor_sync(0xffffffffu, v, o);
    return v;
}

// ---------------------------------------------------------------------------
// k_conv: x (f32) -> g_x16 (fp16), linear
// ---------------------------------------------------------------------------
__global__ __launch_bounds__(256) void k_conv(const float* __restrict__ x) {
    const size_t total = (size_t)B_ * N_ * C_ / 8;
    size_t stride = (size_t)gridDim.x * 256;
    for (size_t i = blockIdx.x * 256 + threadIdx.x; i < total; i += stride) {
        float4 v0 = ((const float4*)x)[i * 2];
        float4 v1 = ((const float4*)x)[i * 2 + 1];
        __half h[8];
        h[0] = __float2half_rn(v0.x); h[1] = __float2half_rn(v0.y);
        h[2] = __float2half_rn(v0.z); h[3] = __float2half_rn(v0.w);
        h[4] = __float2half_rn(v1.x); h[5] = __float2half_rn(v1.y);
        h[6] = __float2half_rn(v1.z); h[7] = __float2half_rn(v1.w);
        ((uint4*)g_x16)[i] = *(uint4*)h;
    }
}

// ---------------------------------------------------------------------------
// k_zero: zero g_AX before split-K atomics
// ---------------------------------------------------------------------------
__global__ __launch_bounds__(256) void k_zero() {
    const size_t total = (size_t)B_ * M_ * C_ / 4;
    size_t stride = (size_t)gridDim.x * 256;
    for (size_t i = blockIdx.x * 256 + threadIdx.x; i < total; i += stride)
        ((float4*)g_AX)[i] = make_float4(0.f, 0.f, 0.f, 0.f);
}

// ---------------------------------------------------------------------------
// k_q: Q[b,r,c'] = SCALE * sum_c x[b,r,c] * Wq[c',c]
// ---------------------------------------------------------------------------
__global__ __launch_bounds__(256) void k_q(const float* __restrict__ x,
                                           const float* __restrict__ Wq) {
    __shared__ float xs[R_ * C_];
    int b = blockIdx.y, t = threadIdx.x;
    {
        const float4* src = (const float4*)(x + (size_t)b * N_ * C_);
        float4* dst = (float4*)xs;
        #pragma unroll 4
        for (int i = t; i < R_ * C_ / 4; i += 256) dst[i] = src[i];
    }
    __syncthreads();
    int cp = blockIdx.x * 256 + t;
    const float4* wr = (const float4*)(Wq + (size_t)cp * C_);
    float acc[R_] = {};
    for (int k4 = 0; k4 < C_ / 4; k4++) {
        float4 w = wr[k4];
        #pragma unroll
        for (int r = 0; r < R_; r++) {
            float4 a = ((const float4*)(xs + r * C_))[k4];
            acc[r] += a.x * w.x + a.y * w.y + a.z * w.z + a.w * w.w;
        }
    }
    #pragma unroll
    for (int r = 0; r < R_; r++)
        g_Q[(b * R_ + r) * C_ + cp] = acc[r] * SCALE_;
}

// ---------------------------------------------------------------------------
// k_qk: QK16[b, h*8+r, c] = sum_d Q[b,r,h*64+d] * Wk[h*64+d, c]   (fp16 out)
// ---------------------------------------------------------------------------
__global__ __launch_bounds__(256) void k_qk(const float* __restrict__ Wk) {
    __shared__ float Qs[64][64];
    int h = blockIdx.y, t = threadIdx.x;
    for (int i = t; i < 64 * 64; i += 256) {
        int br = i >> 6, d = i & 63;
        Qs[br][d] = g_Q[br * C_ + h * 64 + d];
    }
    __syncthreads();
    int c = blockIdx.x * 256 + t;
    float acc[64] = {};
    for (int d = 0; d < 64; d++) {
        float w = Wk[(size_t)(h * 64 + d) * C_ + c];
        #pragma unroll
        for (int br = 0; br < 64; br++) acc[br] += Qs[br][d] * w;
    }
    #pragma unroll
    for (int br = 0; br < 64; br++) {
        int b = br >> 3, r = br & 7;
        g_QK16[((size_t)(b * M_ + h * 8 + r)) * C_ + c] = __float2half_rn(acc[br]);
    }
}

// ---------------------------------------------------------------------------
// k_scores: S = QK16 . x16^T   fp16 mma m16n8k16, ldmatrix, 3-stage cp.async
// BM=192 (all M), BN=64, BK=32. 192 threads: 6 warps (3m x 2n), warp 64x32.
// grid (64, 1, 8)
// ---------------------------------------------------------------------------
#define SC_STAGE 20480                       // bytes per stage
#define SC_BOFF  15360                       // B offset within stage
__global__ __launch_bounds__(192) void k_scores() {
    extern __shared__ char smem[];
    uint32_t sb = (uint32_t)__cvta_generic_to_shared(smem);
    int b = blockIdx.z, nt = blockIdx.x;
    int tid = threadIdx.x, lane = tid & 31, warp = tid >> 5;
    int g = lane >> 2, q = lane & 3;
    int m0 = (warp >> 1) * 64, n0 = (warp & 1) * 32;

    const __half* Ab = g_QK16 + (size_t)b * M_ * C_;
    const __half* Bb = g_x16 + ((size_t)(b * N_ + nt * 64)) * C_;

    float acc[4][4][4] = {};

    #define SC_LOAD(st, itv)                                                     \
        do {                                                                     \
            uint32_t a0 = sb + (st) * SC_STAGE;                                  \
            uint32_t b0 = a0 + SC_BOFF;                                          \
            int kb = (itv) * 32;                                                 \
            for (int i = tid; i < 1024; i += 192) {                              \
                if (i < 768) {                                                   \
                    int row = i >> 2, ch = i & 3;                                \
                    CPA(a0 + (row * 40 + ch * 8) * 2,                            \
                        Ab + (size_t)row * C_ + kb + ch * 8);                    \
                } else {                                                         \
                    int j = i - 768;                                             \
                    int row = j >> 2, ch = j & 3;                                \
                    CPA(b0 + (row * 40 + ch * 8) * 2,                            \
                        Bb + (size_t)row * C_ + kb + ch * 8);                    \
                }                                                                \
            }                                                                    \
            CPCOMMIT();                                                          \
        } while (0)

    const int NK = C_ / 32;  // 48
    SC_LOAD(0, 0); SC_LOAD(1, 1); SC_LOAD(2, 2);

    for (int it = 0; it < NK; ++it) {
        int s = it % 3;
        int pend = NK - 1 - it;
        if (pend >= 2)      CPWAIT2();
        else if (pend == 1) CPWAIT1();
        else                CPWAIT0();
        __syncthreads();

        uint32_t aB = sb + s * SC_STAGE;
        uint32_t bB = aB + SC_BOFF;
        #pragma unroll
        for (int ks = 0; ks < 32; ks += 16) {
            uint32_t a[4][4];
            #pragma unroll
            for (int mi = 0; mi < 4; mi++) {
                uint32_t ad = aB + ((m0 + mi * 16 + (lane & 7) + ((lane >> 3) & 1) * 8) * 40
                                    + ks + (lane >> 4) * 8) * 2;
                LDSM4(a[mi][0], a[mi][1], a[mi][2], a[mi][3], ad);
            }
            uint32_t bf[2][4];
            #pragma unroll
            for (int bi = 0; bi < 2; bi++) {
                uint32_t bd = bB + ((n0 + bi * 16 + (lane & 7) + ((lane >> 4) & 1) * 8) * 40
                                    + ks + ((lane >> 3) & 1) * 8) * 2;
                LDSM4(bf[bi][0], bf[bi][1], bf[bi][2], bf[bi][3], bd);
            }
            #pragma unroll
            for (int mi = 0; mi < 4; mi++)
                #pragma unroll
                for (int ni = 0; ni < 4; ni++)
                    mma16(acc[mi][ni], a[mi], &bf[ni >> 1][(ni & 1) * 2]);
        }
        __syncthreads();
        int nx = it + 3;
        if (nx < NK) SC_LOAD(s, nx);
    }
    #undef SC_LOAD

    float* Cb = g_S + (size_t)b * M_ * N_ + (size_t)nt * 64;
    #pragma unroll
    for (int mi = 0; mi < 4; mi++)
        #pragma unroll
        for (int ni = 0; ni < 4; ni++) {
            int row = m0 + mi * 16 + g;
            int col = n0 + ni * 8 + q * 2;
            *(float2*)(Cb + (size_t)row * N_ + col)       = make_float2(acc[mi][ni][0], acc[mi][ni][1]);
            *(float2*)(Cb + (size_t)(row + 8) * N_ + col) = make_float2(acc[mi][ni][2], acc[mi][ni][3]);
        }
}

// ---------------------------------------------------------------------------
// k_softmax: masked softmax; reads g_S f32, writes g_P16 fp16
// ---------------------------------------------------------------------------
__global__ __launch_bounds__(256) void k_softmax(const int* __restrict__ mask) {
    int row = blockIdx.x;
    int b = row / M_, m = row % M_, r = m & 7;
    const float* S = g_S + (size_t)row * N_;
    __half* P = g_P16 + (size_t)row * N_;
    const int* mrow = mask + ((size_t)(b * R_ + r)) * (N_ - R_);
    int tid = threadIdx.x;

    float vals[16];
    float mx = -1e30f;
    #pragma unroll
    for (int i = 0; i < 16; i++) {
        int n = i * 256 + tid;
        float s = S[n];
        bool valid = (n < R_) ? (n == r) : (mrow[n - R_] != 0);
        s = valid ? s : -1e30f;
        vals[i] = s;
        mx = fmaxf(mx, s);
    }
    __shared__ float smx[8], ssm[8];
    float wmx = warpMax(mx);
    if ((tid & 31) == 0) smx[tid >> 5] = wmx;
    __syncthreads();
    float bm = smx[0];
    #pragma unroll
    for (int j = 1; j < 8; j++) bm = fmaxf(bm, smx[j]);

    float sum = 0.f;
    #pragma unroll
    for (int i = 0; i < 16; i++) {
        vals[i] = expf(vals[i] - bm);
        sum += vals[i];
    }
    float wsm = warpSum(sum);
    if ((tid & 31) == 0) ssm[tid >> 5] = wsm;
    __syncthreads();
    float tot = 0.f;
    #pragma unroll
    for (int j = 0; j < 8; j++) tot += ssm[j];
    float inv = 1.0f / tot;
    #pragma unroll
    for (int i = 0; i < 16; i++) P[i * 256 + tid] = __float2half_rn(vals[i] * inv);
}

// ---------------------------------------------------------------------------
// k_ax: AX[m,c] += sum_{n in split} P16[m,n] * x16[n,c]   (split-K x4)
// BM=192, BN=64 (c), BK=32 (tokens), K-split 4x1024. 192 threads, warp 64x32.
// grid (24, 4, 8). Epilogue: atomicAdd into zeroed g_AX.
// ---------------------------------------------------------------------------
#define AX_STAGE 19968
#define AX_BOFF  15360
#define AX_SPLIT 4
__global__ __launch_bounds__(192) void k_ax() {
    extern __shared__ char smem[];
    uint32_t sb = (uint32_t)__cvta_generic_to_shared(smem);
    int b = blockIdx.z, nt = blockIdx.x, kc = blockIdx.y;
    int tid = threadIdx.x, lane = tid & 31, warp = tid >> 5;
    int g = lane >> 2, q = lane & 3;
    int m0 = (warp >> 1) * 64, n0 = (warp & 1) * 32;

    const int K0 = kc * (N_ / AX_SPLIT);      // split base (tokens)
    const __half* Ab = g_P16 + (size_t)b * M_ * N_ + K0;
    const __half* Bx = g_x16 + (size_t)b * N_ * C_ + (size_t)K0 * C_ + nt * 64;

    float acc[4][4][4] = {};

    #define AX_LOAD(st, itv)                                                     \
        do {                                                                     \
            uint32_t a0 = sb + (st) * AX_STAGE;                                  \
            uint32_t b0 = a0 + AX_BOFF;                                          \
            int kb = (itv) * 32;                                                 \
            for (int i = tid; i < 1024; i += 192) {                              \
                if (i < 768) {                                                   \
                    int row = i >> 2, ch = i & 3;                                \
                    CPA(a0 + (row * 40 + ch * 8) * 2,                            \
                        Ab + (size_t)row * N_ + kb + ch * 8);                    \
                } else {                                                         \
                    int j = i - 768;                                             \
                    int row = j >> 3, ch = j & 7;                                \
                    CPA(b0 + (row * 72 + ch * 8) * 2,                            \
                        Bx + (size_t)(kb + row) * C_ + ch * 8);                  \
                }                                                                \
            }                                                                    \
            CPCOMMIT();                                                          \
        } while (0)

    const int NK = (N_ / AX_SPLIT) / 32;  // 32
    AX_LOAD(0, 0); AX_LOAD(1, 1); AX_LOAD(2, 2);

    for (int it = 0; it < NK; ++it) {
        int s = it % 3;
        int pend = NK - 1 - it;
        if (pend >= 2)      CPWAIT2();
        else if (pend == 1) CPWAIT1();
        else                CPWAIT0();
        __syncthreads();

        uint32_t aB = sb + s * AX_STAGE;
        uint32_t bB = aB + AX_BOFF;
        #pragma unroll
        for (int ks = 0; ks < 32; ks += 16) {
            uint32_t a[4][4];
            #pragma unroll
            for (int mi = 0; mi < 4; mi++) {
                uint32_t ad = aB + ((m0 + mi * 16 + (lane & 7) + ((lane >> 3) & 1) * 8) * 40
                                    + ks + (lane >> 4) * 8) * 2;
                LDSM4(a[mi][0], a[mi][1], a[mi][2], a[mi][3], ad);
            }
            uint32_t bf[2][4];
            #pragma unroll
            for (int bi = 0; bi < 2; bi++) {
                uint32_t bd = bB + ((ks + (lane & 7) + ((lane >> 3) & 1) * 8) * 72
                                    + n0 + bi * 16 + ((lane >> 4) & 1) * 8) * 2;
                LDSM4T(bf[bi][0], bf[bi][1], bf[bi][2], bf[bi][3], bd);
            }
            #pragma unroll
            for (int mi = 0; mi < 4; mi++)
                #pragma unroll
                for (int ni = 0; ni < 4; ni++)
                    mma16(acc[mi][ni], a[mi], &bf[ni >> 1][(ni & 1) * 2]);
        }
        __syncthreads();
        int nx = it + 3;
        if (nx < NK) AX_LOAD(s, nx);
    }
    #undef AX_LOAD

    float* Cb = g_AX + (size_t)b * M_ * C_ + nt * 64;
    #pragma unroll
    for (int mi = 0; mi < 4; mi++)
        #pragma unroll
        for (int ni = 0; ni < 4; ni++) {
            int row = m0 + mi * 16 + g;
            int col = n0 + ni * 8 + q * 2;
            float* p0 = Cb + (size_t)row * C_ + col;
            float* p1 = Cb + (size_t)(row + 8) * C_ + col;
            atomicAdd(p0,     acc[mi][ni][0]);
            atomicAdd(p0 + 1, acc[mi][ni][1]);
            atomicAdd(p1,     acc[mi][ni][2]);
            atomicAdd(p1 + 1, acc[mi][ni][3]);
        }
}

// ---------------------------------------------------------------------------
// k_d1: XCLS[b,r,cc] = sum_c AX[b, (cc/64)*8+r, c] * Wv[cc, c]
// ---------------------------------------------------------------------------
__global__ __launch_bounds__(256) void k_d1(const float* __restrict__ Wv) {
    int b = blockIdx.y, t = threadIdx.x;
    int cc = blockIdx.x * 256 + t;
    int h = cc >> 6;
    const float4* wr = (const float4*)(Wv + (size_t)cc * C_);
    const float4* ax[R_];
    #pragma unroll
    for (int r = 0; r < R_; r++)
        ax[r] = (const float4*)(g_AX + ((size_t)b * M_ + h * 8 + r) * C_);
    float acc[R_] = {};
    for (int k4 = 0; k4 < C_ / 4; k4++) {
        float4 w = wr[k4];
        #pragma unroll
        for (int r = 0; r < R_; r++) {
            float4 a = ax[r][k4];
            acc[r] += a.x * w.x + a.y * w.y + a.z * w.z + a.w * w.w;
        }
    }
    #pragma unroll
    for (int r = 0; r < R_; r++)
        g_XCLS[(b * R_ + r) * C_ + cc] = acc[r];
}

// ---------------------------------------------------------------------------
// k_d2: out[b,r,c'] = bp[c'] + sum_cc XCLS[b,r,cc] * Wp[c',cc]
// ---------------------------------------------------------------------------
__global__ __launch_bounds__(256) void k_d2(const float* __restrict__ Wp,
                                            const float* __restrict__ bp,
                                            float* __restrict__ out) {
    int b = blockIdx.y, t = threadIdx.x;
    int cp = blockIdx.x * 256 + t;
    const float4* wr = (const float4*)(Wp + (size_t)cp * C_);
    const float4* xc[R_];
    #pragma unroll
    for (int r = 0; r < R_; r++)
        xc[r] = (const float4*)(g_XCLS + (size_t)(b * R_ + r) * C_);
    float acc[R_] = {};
    for (int k4 = 0; k4 < C_ / 4; k4++) {
        float4 w = wr[k4];
        #pragma unroll
        for (int r = 0; r < R_; r++) {
            float4 a = xc[r][k4];
            acc[r] += a.x * w.x + a.y * w.y + a.z * w.z + a.w * w.w;
        }
    }
    float bias = bp[cp];
    #pragma unroll
    for (int r = 0; r < R_; r++)
        out[((size_t)(b * R_ + r)) * C_ + cp] = acc[r] + bias;
}

// ---------------------------------------------------------------------------
// launch
// ---------------------------------------------------------------------------
extern "C" void kernel_launch(void* const* d_in, const int* in_sizes, int n_in,
                              void* d_out, int out_size) {
    const float* x    = (const float*)d_in[0];
    const int*   mask = (const int*)d_in[1];
    const float* Wq   = (const float*)d_in[2];
    const float* Wk   = (const float*)d_in[3];
    const float* Wv   = (const float*)d_in[4];
    const float* Wp   = (const float*)d_in[5];
    const float* bp   = (const float*)d_in[6];
    float* out = (float*)d_out;

    const int SC_SMEM = 3 * SC_STAGE;  // 61440
    const int AX_SMEM = 3 * AX_STAGE;  // 59904
    cudaFuncSetAttribute(k_scores, cudaFuncAttributeMaxDynamicSharedMemorySize, SC_SMEM);
    cudaFuncSetAttribute(k_ax,     cudaFuncAttributeMaxDynamicSharedMemorySize, AX_SMEM);

    k_conv   <<<4096, 256>>>(x);
    k_zero   <<<1024, 256>>>();
    k_q      <<<dim3(C_ / 256, B_), 256>>>(x, Wq);
    k_qk     <<<dim3(C_ / 256, H_), 256>>>(Wk);
    k_scores <<<dim3(N_ / 64, 1, B_), 192, SC_SMEM>>>();
    k_softmax<<<B_ * M_, 256>>>(mask);
    k_ax     <<<dim3(C_ / 64, AX_SPLIT, B_), 192, AX_SMEM>>>();
    k_d1     <<<dim3(C_ / 256, B_), 256>>>(Wv);
    k_d2     <<<dim3(C_ / 256, B_), 256>>>(Wp, bp, out);
}

// round 7
// speedup vs baseline: 2.6133x; 1.8105x over previous
#include <cuda_runtime.h>
#include <cuda_fp16.h>
#include <cstdint>

// Problem constants
#define B_   8
#define N_   4096
#define C_   1536
#define H_   24
#define R_   8
#define M_   192
#define SCALE_ 0.125f

// Scratch (static device globals)
__device__ float    g_Q[B_ * R_ * C_];                 // atomically accumulated
__device__ __half   g_QK16[B_ * M_ * C_];              // q@Wk, fp16
__device__ float    g_S[(size_t)B_ * M_ * N_];         // scores f32
__device__ __half   g_P16[(size_t)B_ * M_ * N_];       // softmax probs fp16
__device__ float    g_AX[B_ * M_ * C_];                // P @ x (split-K accumulated)
__device__ float    g_XCLS[B_ * R_ * C_];              // atomically accumulated
__device__ __half   g_x16[(size_t)B_ * N_ * C_];       // x fp16

// ---------------------------------------------------------------------------
// helpers
// ---------------------------------------------------------------------------
#define CPA(dst, src) asm volatile("cp.async.cg.shared.global [%0], [%1], 16;" :: "r"(dst), "l"(src))
#define CPCOMMIT()    asm volatile("cp.async.commit_group;")
#define CPWAIT0()     asm volatile("cp.async.wait_group 0;")
#define CPWAIT1()     asm volatile("cp.async.wait_group 1;")
#define CPWAIT2()     asm volatile("cp.async.wait_group 2;")

#define LDSM4(r0, r1, r2, r3, addr) \
    asm volatile("ldmatrix.sync.aligned.m8n8.x4.shared.b16 {%0,%1,%2,%3}, [%4];" \
                 : "=r"(r0), "=r"(r1), "=r"(r2), "=r"(r3) : "r"(addr))
#define LDSM4T(r0, r1, r2, r3, addr) \
    asm volatile("ldmatrix.sync.aligned.m8n8.x4.trans.shared.b16 {%0,%1,%2,%3}, [%4];" \
                 : "=r"(r0), "=r"(r1), "=r"(r2), "=r"(r3) : "r"(addr))

__device__ __forceinline__ void mma16(float* c, const uint32_t* a, const uint32_t* b) {
    asm volatile(
        "mma.sync.aligned.m16n8k16.row.col.f32.f16.f16.f32 "
        "{%0,%1,%2,%3}, {%4,%5,%6,%7}, {%8,%9}, {%0,%1,%2,%3};"
        : "+f"(c[0]), "+f"(c[1]), "+f"(c[2]), "+f"(c[3])
        : "r"(a[0]), "r"(a[1]), "r"(a[2]), "r"(a[3]), "r"(b[0]), "r"(b[1]));
}

__device__ __forceinline__ float warpMax(float v) {
    #pragma unroll
    for (int o = 16; o; o >>= 1) v = fmaxf(v, __shfl_xor_sync(0xffffffffu, v, o));
    return v;
}
__device__ __forceinline__ float warpSum(float v) {
    #pragma unroll
    for (int o = 16; o; o >>= 1) v += __shfl_xor_sync(0xffffffffu, v, o);
    return v;
}

// ---------------------------------------------------------------------------
// k_conv: x (f32) -> g_x16 (fp16), linear
// ---------------------------------------------------------------------------
__global__ __launch_bounds__(256) void k_conv(const float* __restrict__ x) {
    const size_t total = (size_t)B_ * N_ * C_ / 8;
    size_t stride = (size_t)gridDim.x * 256;
    for (size_t i = blockIdx.x * 256 + threadIdx.x; i < total; i += stride) {
        float4 v0 = ((const float4*)x)[i * 2];
        float4 v1 = ((const float4*)x)[i * 2 + 1];
        __half h[8];
        h[0] = __float2half_rn(v0.x); h[1] = __float2half_rn(v0.y);
        h[2] = __float2half_rn(v0.z); h[3] = __float2half_rn(v0.w);
        h[4] = __float2half_rn(v1.x); h[5] = __float2half_rn(v1.y);
        h[6] = __float2half_rn(v1.z); h[7] = __float2half_rn(v1.w);
        ((uint4*)g_x16)[i] = *(uint4*)h;
    }
}

// ---------------------------------------------------------------------------
// k_zero: zero all atomically-accumulated buffers (g_AX, g_Q, g_XCLS, out)
// ---------------------------------------------------------------------------
__global__ __launch_bounds__(256) void k_zero(float* __restrict__ out) {
    const float4 z = make_float4(0.f, 0.f, 0.f, 0.f);
    size_t stride = (size_t)gridDim.x * 256;
    size_t t0 = blockIdx.x * 256 + threadIdx.x;
    for (size_t i = t0; i < (size_t)B_ * M_ * C_ / 4; i += stride) ((float4*)g_AX)[i] = z;
    for (size_t i = t0; i < (size_t)B_ * R_ * C_ / 4; i += stride) {
        ((float4*)g_Q)[i] = z;
        ((float4*)g_XCLS)[i] = z;
        ((float4*)out)[i] = z;
    }
}

// ---------------------------------------------------------------------------
// k_q: Q[b,r,c'] += SCALE * sum_{c in slice} x[b,r,c] * Wq[c',c]
// K-split x8: grid (6, 8, 8) = 384 blocks. atomicAdd epilogue.
// ---------------------------------------------------------------------------
#define QK_SLICE (C_ / 8)   // 192
__global__ __launch_bounds__(256) void k_q(const float* __restrict__ x,
                                           const float* __restrict__ Wq) {
    __shared__ float xs[R_ * QK_SLICE];
    int b = blockIdx.y, kc = blockIdx.z, t = threadIdx.x;
    int k0 = kc * QK_SLICE;
    // load the 8 query-token slices for this batch/K-slice
    for (int i = t; i < R_ * QK_SLICE / 4; i += 256) {
        int r = i / (QK_SLICE / 4), c4 = i % (QK_SLICE / 4);
        ((float4*)xs)[i] = *(const float4*)(x + ((size_t)(b * N_ + r)) * C_ + k0 + c4 * 4);
    }
    __syncthreads();
    int cp = blockIdx.x * 256 + t;
    const float4* wr = (const float4*)(Wq + (size_t)cp * C_ + k0);
    float acc[R_] = {};
    #pragma unroll 4
    for (int k4 = 0; k4 < QK_SLICE / 4; k4++) {
        float4 w = wr[k4];
        #pragma unroll
        for (int r = 0; r < R_; r++) {
            float4 a = ((const float4*)(xs + r * QK_SLICE))[k4];
            acc[r] += a.x * w.x + a.y * w.y + a.z * w.z + a.w * w.w;
        }
    }
    #pragma unroll
    for (int r = 0; r < R_; r++)
        atomicAdd(&g_Q[(b * R_ + r) * C_ + cp], acc[r] * SCALE_);
}

// ---------------------------------------------------------------------------
// k_qk: QK16[b, h*8+r, c] = sum_d Q[b,r,h*64+d] * Wk[h*64+d, c]
// br-split x2: grid (6, 24, 2) = 288 blocks, 32 accs per thread.
// ---------------------------------------------------------------------------
__global__ __launch_bounds__(256) void k_qk(const float* __restrict__ Wk) {
    __shared__ float Qs[32][64];
    int h = blockIdx.y, half = blockIdx.z, t = threadIdx.x;
    for (int i = t; i < 32 * 64; i += 256) {
        int brl = i >> 6, d = i & 63;
        Qs[brl][d] = g_Q[(half * 32 + brl) * C_ + h * 64 + d];
    }
    __syncthreads();
    int c = blockIdx.x * 256 + t;
    float acc[32] = {};
    #pragma unroll 4
    for (int d = 0; d < 64; d++) {
        float w = Wk[(size_t)(h * 64 + d) * C_ + c];
        #pragma unroll
        for (int brl = 0; brl < 32; brl++) acc[brl] += Qs[brl][d] * w;
    }
    #pragma unroll
    for (int brl = 0; brl < 32; brl++) {
        int br = half * 32 + brl;
        int b = br >> 3, r = br & 7;
        g_QK16[((size_t)(b * M_ + h * 8 + r)) * C_ + c] = __float2half_rn(acc[brl]);
    }
}

// ---------------------------------------------------------------------------
// k_scores: S = QK16 . x16^T   fp16 mma m16n8k16, ldmatrix, 3-stage cp.async
// BM=192 (all M), BN=64, BK=32. 192 threads: 6 warps (3m x 2n), warp 64x32.
// grid (64, 1, 8)
// ---------------------------------------------------------------------------
#define SC_STAGE 20480                       // bytes per stage
#define SC_BOFF  15360                       // B offset within stage
__global__ __launch_bounds__(192) void k_scores() {
    extern __shared__ char smem[];
    uint32_t sb = (uint32_t)__cvta_generic_to_shared(smem);
    int b = blockIdx.z, nt = blockIdx.x;
    int tid = threadIdx.x, lane = tid & 31, warp = tid >> 5;
    int g = lane >> 2, q = lane & 3;
    int m0 = (warp >> 1) * 64, n0 = (warp & 1) * 32;

    const __half* Ab = g_QK16 + (size_t)b * M_ * C_;
    const __half* Bb = g_x16 + ((size_t)(b * N_ + nt * 64)) * C_;

    float acc[4][4][4] = {};

    #define SC_LOAD(st, itv)                                                     \
        do {                                                                     \
            uint32_t a0 = sb + (st) * SC_STAGE;                                  \
            uint32_t b0 = a0 + SC_BOFF;                                          \
            int kb = (itv) * 32;                                                 \
            for (int i = tid; i < 1024; i += 192) {                              \
                if (i < 768) {                                                   \
                    int row = i >> 2, ch = i & 3;                                \
                    CPA(a0 + (row * 40 + ch * 8) * 2,                            \
                        Ab + (size_t)row * C_ + kb + ch * 8);                    \
                } else {                                                         \
                    int j = i - 768;                                             \
                    int row = j >> 2, ch = j & 3;                                \
                    CPA(b0 + (row * 40 + ch * 8) * 2,                            \
                        Bb + (size_t)row * C_ + kb + ch * 8);                    \
                }                                                                \
            }                                                                    \
            CPCOMMIT();                                                          \
        } while (0)

    const int NK = C_ / 32;  // 48
    SC_LOAD(0, 0); SC_LOAD(1, 1); SC_LOAD(2, 2);

    for (int it = 0; it < NK; ++it) {
        int s = it % 3;
        int pend = NK - 1 - it;
        if (pend >= 2)      CPWAIT2();
        else if (pend == 1) CPWAIT1();
        else                CPWAIT0();
        __syncthreads();

        uint32_t aB = sb + s * SC_STAGE;
        uint32_t bB = aB + SC_BOFF;
        #pragma unroll
        for (int ks = 0; ks < 32; ks += 16) {
            uint32_t a[4][4];
            #pragma unroll
            for (int mi = 0; mi < 4; mi++) {
                uint32_t ad = aB + ((m0 + mi * 16 + (lane & 7) + ((lane >> 3) & 1) * 8) * 40
                                    + ks + (lane >> 4) * 8) * 2;
                LDSM4(a[mi][0], a[mi][1], a[mi][2], a[mi][3], ad);
            }
            uint32_t bf[2][4];
            #pragma unroll
            for (int bi = 0; bi < 2; bi++) {
                uint32_t bd = bB + ((n0 + bi * 16 + (lane & 7) + ((lane >> 4) & 1) * 8) * 40
                                    + ks + ((lane >> 3) & 1) * 8) * 2;
                LDSM4(bf[bi][0], bf[bi][1], bf[bi][2], bf[bi][3], bd);
            }
            #pragma unroll
            for (int mi = 0; mi < 4; mi++)
                #pragma unroll
                for (int ni = 0; ni < 4; ni++)
                    mma16(acc[mi][ni], a[mi], &bf[ni >> 1][(ni & 1) * 2]);
        }
        __syncthreads();
        int nx = it + 3;
        if (nx < NK) SC_LOAD(s, nx);
    }
    #undef SC_LOAD

    float* Cb = g_S + (size_t)b * M_ * N_ + (size_t)nt * 64;
    #pragma unroll
    for (int mi = 0; mi < 4; mi++)
        #pragma unroll
        for (int ni = 0; ni < 4; ni++) {
            int row = m0 + mi * 16 + g;
            int col = n0 + ni * 8 + q * 2;
            *(float2*)(Cb + (size_t)row * N_ + col)       = make_float2(acc[mi][ni][0], acc[mi][ni][1]);
            *(float2*)(Cb + (size_t)(row + 8) * N_ + col) = make_float2(acc[mi][ni][2], acc[mi][ni][3]);
        }
}

// ---------------------------------------------------------------------------
// k_softmax: masked softmax; reads g_S f32, writes g_P16 fp16
// ---------------------------------------------------------------------------
__global__ __launch_bounds__(256) void k_softmax(const int* __restrict__ mask) {
    int row = blockIdx.x;
    int b = row / M_, m = row % M_, r = m & 7;
    const float* S = g_S + (size_t)row * N_;
    __half* P = g_P16 + (size_t)row * N_;
    const int* mrow = mask + ((size_t)(b * R_ + r)) * (N_ - R_);
    int tid = threadIdx.x;

    float vals[16];
    float mx = -1e30f;
    #pragma unroll
    for (int i = 0; i < 16; i++) {
        int n = i * 256 + tid;
        float s = S[n];
        bool valid = (n < R_) ? (n == r) : (mrow[n - R_] != 0);
        s = valid ? s : -1e30f;
        vals[i] = s;
        mx = fmaxf(mx, s);
    }
    __shared__ float smx[8], ssm[8];
    float wmx = warpMax(mx);
    if ((tid & 31) == 0) smx[tid >> 5] = wmx;
    __syncthreads();
    float bm = smx[0];
    #pragma unroll
    for (int j = 1; j < 8; j++) bm = fmaxf(bm, smx[j]);

    float sum = 0.f;
    #pragma unroll
    for (int i = 0; i < 16; i++) {
        vals[i] = expf(vals[i] - bm);
        sum += vals[i];
    }
    float wsm = warpSum(sum);
    if ((tid & 31) == 0) ssm[tid >> 5] = wsm;
    __syncthreads();
    float tot = 0.f;
    #pragma unroll
    for (int j = 0; j < 8; j++) tot += ssm[j];
    float inv = 1.0f / tot;
    #pragma unroll
    for (int i = 0; i < 16; i++) P[i * 256 + tid] = __float2half_rn(vals[i] * inv);
}

// ---------------------------------------------------------------------------
// k_ax: AX[m,c] += sum_{n in split} P16[m,n] * x16[n,c]   (split-K x4)
// BM=192, BN=64 (c), BK=32 (tokens), K-split 4x1024. grid (24, 4, 8).
// ---------------------------------------------------------------------------
#define AX_STAGE 19968
#define AX_BOFF  15360
#define AX_SPLIT 4
__global__ __launch_bounds__(192) void k_ax() {
    extern __shared__ char smem[];
    uint32_t sb = (uint32_t)__cvta_generic_to_shared(smem);
    int b = blockIdx.z, nt = blockIdx.x, kc = blockIdx.y;
    int tid = threadIdx.x, lane = tid & 31, warp = tid >> 5;
    int g = lane >> 2, q = lane & 3;
    int m0 = (warp >> 1) * 64, n0 = (warp & 1) * 32;

    const int K0 = kc * (N_ / AX_SPLIT);      // split base (tokens)
    const __half* Ab = g_P16 + (size_t)b * M_ * N_ + K0;
    const __half* Bx = g_x16 + (size_t)b * N_ * C_ + (size_t)K0 * C_ + nt * 64;

    float acc[4][4][4] = {};

    #define AX_LOAD(st, itv)                                                     \
        do {                                                                     \
            uint32_t a0 = sb + (st) * AX_STAGE;                                  \
            uint32_t b0 = a0 + AX_BOFF;                                          \
            int kb = (itv) * 32;                                                 \
            for (int i = tid; i < 1024; i += 192) {                              \
                if (i < 768) {                                                   \
                    int row = i >> 2, ch = i & 3;                                \
                    CPA(a0 + (row * 40 + ch * 8) * 2,                            \
                        Ab + (size_t)row * N_ + kb + ch * 8);                    \
                } else {                                                         \
                    int j = i - 768;                                             \
                    int row = j >> 3, ch = j & 7;                                \
                    CPA(b0 + (row * 72 + ch * 8) * 2,                            \
                        Bx + (size_t)(kb + row) * C_ + ch * 8);                  \
                }                                                                \
            }                                                                    \
            CPCOMMIT();                                                          \
        } while (0)

    const int NK = (N_ / AX_SPLIT) / 32;  // 32
    AX_LOAD(0, 0); AX_LOAD(1, 1); AX_LOAD(2, 2);

    for (int it = 0; it < NK; ++it) {
        int s = it % 3;
        int pend = NK - 1 - it;
        if (pend >= 2)      CPWAIT2();
        else if (pend == 1) CPWAIT1();
        else                CPWAIT0();
        __syncthreads();

        uint32_t aB = sb + s * AX_STAGE;
        uint32_t bB = aB + AX_BOFF;
        #pragma unroll
        for (int ks = 0; ks < 32; ks += 16) {
            uint32_t a[4][4];
            #pragma unroll
            for (int mi = 0; mi < 4; mi++) {
                uint32_t ad = aB + ((m0 + mi * 16 + (lane & 7) + ((lane >> 3) & 1) * 8) * 40
                                    + ks + (lane >> 4) * 8) * 2;
                LDSM4(a[mi][0], a[mi][1], a[mi][2], a[mi][3], ad);
            }
            uint32_t bf[2][4];
            #pragma unroll
            for (int bi = 0; bi < 2; bi++) {
                uint32_t bd = bB + ((ks + (lane & 7) + ((lane >> 3) & 1) * 8) * 72
                                    + n0 + bi * 16 + ((lane >> 4) & 1) * 8) * 2;
                LDSM4T(bf[bi][0], bf[bi][1], bf[bi][2], bf[bi][3], bd);
            }
            #pragma unroll
            for (int mi = 0; mi < 4; mi++)
                #pragma unroll
                for (int ni = 0; ni < 4; ni++)
                    mma16(acc[mi][ni], a[mi], &bf[ni >> 1][(ni & 1) * 2]);
        }
        __syncthreads();
        int nx = it + 3;
        if (nx < NK) AX_LOAD(s, nx);
    }
    #undef AX_LOAD

    float* Cb = g_AX + (size_t)b * M_ * C_ + nt * 64;
    #pragma unroll
    for (int mi = 0; mi < 4; mi++)
        #pragma unroll
        for (int ni = 0; ni < 4; ni++) {
            int row = m0 + mi * 16 + g;
            int col = n0 + ni * 8 + q * 2;
            float* p0 = Cb + (size_t)row * C_ + col;
            float* p1 = Cb + (size_t)(row + 8) * C_ + col;
            atomicAdd(p0,     acc[mi][ni][0]);
            atomicAdd(p0 + 1, acc[mi][ni][1]);
            atomicAdd(p1,     acc[mi][ni][2]);
            atomicAdd(p1 + 1, acc[mi][ni][3]);
        }
}

// ---------------------------------------------------------------------------
// k_d1: XCLS[b,r,cc] += sum_{c in slice} AX[b, (cc/64)*8+r, c] * Wv[cc, c]
// K-split x8: grid (6, 8, 8). atomicAdd into zeroed g_XCLS.
// ---------------------------------------------------------------------------
__global__ __launch_bounds__(256) void k_d1(const float* __restrict__ Wv) {
    int b = blockIdx.y, kc = blockIdx.z, t = threadIdx.x;
    int k0 = kc * QK_SLICE;
    int cc = blockIdx.x * 256 + t;
    int h = cc >> 6;
    const float4* wr = (const float4*)(Wv + (size_t)cc * C_ + k0);
    const float4* ax[R_];
    #pragma unroll
    for (int r = 0; r < R_; r++)
        ax[r] = (const float4*)(g_AX + ((size_t)b * M_ + h * 8 + r) * C_ + k0);
    float acc[R_] = {};
    #pragma unroll 4
    for (int k4 = 0; k4 < QK_SLICE / 4; k4++) {
        float4 w = wr[k4];
        #pragma unroll
        for (int r = 0; r < R_; r++) {
            float4 a = ax[r][k4];
            acc[r] += a.x * w.x + a.y * w.y + a.z * w.z + a.w * w.w;
        }
    }
    #pragma unroll
    for (int r = 0; r < R_; r++)
        atomicAdd(&g_XCLS[(b * R_ + r) * C_ + cc], acc[r]);
}

// ---------------------------------------------------------------------------
// k_d2: out[b,r,c'] += sum_{cc in slice} XCLS[b,r,cc] * Wp[c',cc]  (+bias on kc0)
// K-split x8: grid (6, 8, 8). atomicAdd into zeroed out.
// ---------------------------------------------------------------------------
__global__ __launch_bounds__(256) void k_d2(const float* __restrict__ Wp,
                                            const float* __restrict__ bp,
                                            float* __restrict__ out) {
    int b = blockIdx.y, kc = blockIdx.z, t = threadIdx.x;
    int k0 = kc * QK_SLICE;
    int cp = blockIdx.x * 256 + t;
    const float4* wr = (const float4*)(Wp + (size_t)cp * C_ + k0);
    const float4* xc[R_];
    #pragma unroll
    for (int r = 0; r < R_; r++)
        xc[r] = (const float4*)(g_XCLS + (size_t)(b * R_ + r) * C_ + k0);
    float acc[R_] = {};
    #pragma unroll 4
    for (int k4 = 0; k4 < QK_SLICE / 4; k4++) {
        float4 w = wr[k4];
        #pragma unroll
        for (int r = 0; r < R_; r++) {
            float4 a = xc[r][k4];
            acc[r] += a.x * w.x + a.y * w.y + a.z * w.z + a.w * w.w;
        }
    }
    float bias = (kc == 0) ? bp[cp] : 0.f;
    #pragma unroll
    for (int r = 0; r < R_; r++)
        atomicAdd(&out[((size_t)(b * R_ + r)) * C_ + cp], acc[r] + bias);
}

// ---------------------------------------------------------------------------
// launch
// ---------------------------------------------------------------------------
extern "C" void kernel_launch(void* const* d_in, const int* in_sizes, int n_in,
                              void* d_out, int out_size) {
    const float* x    = (const float*)d_in[0];
    const int*   mask = (const int*)d_in[1];
    const float* Wq   = (const float*)d_in[2];
    const float* Wk   = (const float*)d_in[3];
    const float* Wv   = (const float*)d_in[4];
    const float* Wp   = (const float*)d_in[5];
    const float* bp   = (const float*)d_in[6];
    float* out = (float*)d_out;

    const int SC_SMEM = 3 * SC_STAGE;  // 61440
    const int AX_SMEM = 3 * AX_STAGE;  // 59904
    cudaFuncSetAttribute(k_scores, cudaFuncAttributeMaxDynamicSharedMemorySize, SC_SMEM);
    cudaFuncSetAttribute(k_ax,     cudaFuncAttributeMaxDynamicSharedMemorySize, AX_SMEM);

    k_zero   <<<1024, 256>>>(out);
    k_conv   <<<4096, 256>>>(x);
    k_q      <<<dim3(C_ / 256, B_, 8), 256>>>(x, Wq);
    k_qk     <<<dim3(C_ / 256, H_, 2), 256>>>(Wk);
    k_scores <<<dim3(N_ / 64, 1, B_), 192, SC_SMEM>>>();
    k_softmax<<<B_ * M_, 256>>>(mask);
    k_ax     <<<dim3(C_ / 64, AX_SPLIT, B_), 192, AX_SMEM>>>();
    k_d1     <<<dim3(C_ / 256, B_, 8), 256>>>(Wv);
    k_d2     <<<dim3(C_ / 256, B_, 8), 256>>>(Wp, bp, out);
}

// round 8
// speedup vs baseline: 2.7121x; 1.0378x over previous
#include <cuda_runtime.h>
#include <cuda_fp16.h>
#include <cstdint>

// Problem constants
#define B_   8
#define N_   4096
#define C_   1536
#define H_   24
#define R_   8
#define M_   192
#define SCALE_ 0.125f

// Scratch (static device globals)
__device__ float    g_Q[B_ * R_ * C_];                 // atomically accumulated
__device__ __half   g_QK16[B_ * M_ * C_];              // q@Wk, fp16
__device__ float    g_S[(size_t)B_ * M_ * N_];         // scores f32
__device__ __half   g_P16[(size_t)B_ * M_ * N_];       // softmax probs fp16
__device__ float    g_AX[B_ * M_ * C_];                // P @ x (split-K accumulated)
__device__ float    g_XCLS[B_ * R_ * C_];              // atomically accumulated
__device__ __half   g_x16[(size_t)B_ * N_ * C_];       // x fp16

// ---------------------------------------------------------------------------
// helpers
// ---------------------------------------------------------------------------
#define CPA(dst, src) asm volatile("cp.async.cg.shared.global [%0], [%1], 16;" :: "r"(dst), "l"(src))
#define CPCOMMIT()    asm volatile("cp.async.commit_group;")
#define CPWAIT0()     asm volatile("cp.async.wait_group 0;")
#define CPWAIT1()     asm volatile("cp.async.wait_group 1;")
#define CPWAIT2()     asm volatile("cp.async.wait_group 2;")

#define LDSM4(r0, r1, r2, r3, addr) \
    asm volatile("ldmatrix.sync.aligned.m8n8.x4.shared.b16 {%0,%1,%2,%3}, [%4];" \
                 : "=r"(r0), "=r"(r1), "=r"(r2), "=r"(r3) : "r"(addr))
#define LDSM4T(r0, r1, r2, r3, addr) \
    asm volatile("ldmatrix.sync.aligned.m8n8.x4.trans.shared.b16 {%0,%1,%2,%3}, [%4];" \
                 : "=r"(r0), "=r"(r1), "=r"(r2), "=r"(r3) : "r"(addr))

__device__ __forceinline__ void mma16(float* c, const uint32_t* a, const uint32_t* b) {
    asm volatile(
        "mma.sync.aligned.m16n8k16.row.col.f32.f16.f16.f32 "
        "{%0,%1,%2,%3}, {%4,%5,%6,%7}, {%8,%9}, {%0,%1,%2,%3};"
        : "+f"(c[0]), "+f"(c[1]), "+f"(c[2]), "+f"(c[3])
        : "r"(a[0]), "r"(a[1]), "r"(a[2]), "r"(a[3]), "r"(b[0]), "r"(b[1]));
}

__device__ __forceinline__ float warpMax(float v) {
    #pragma unroll
    for (int o = 16; o; o >>= 1) v = fmaxf(v, __shfl_xor_sync(0xffffffffu, v, o));
    return v;
}
__device__ __forceinline__ float warpSum(float v) {
    #pragma unroll
    for (int o = 16; o; o >>= 1) v += __shfl_xor_sync(0xffffffffu, v, o);
    return v;
}

// ---------------------------------------------------------------------------
// k_conv: x (f32) -> g_x16 (fp16), linear
// ---------------------------------------------------------------------------
__global__ __launch_bounds__(256) void k_conv(const float* __restrict__ x) {
    const size_t total = (size_t)B_ * N_ * C_ / 8;
    size_t stride = (size_t)gridDim.x * 256;
    for (size_t i = blockIdx.x * 256 + threadIdx.x; i < total; i += stride) {
        float4 v0 = ((const float4*)x)[i * 2];
        float4 v1 = ((const float4*)x)[i * 2 + 1];
        __half h[8];
        h[0] = __float2half_rn(v0.x); h[1] = __float2half_rn(v0.y);
        h[2] = __float2half_rn(v0.z); h[3] = __float2half_rn(v0.w);
        h[4] = __float2half_rn(v1.x); h[5] = __float2half_rn(v1.y);
        h[6] = __float2half_rn(v1.z); h[7] = __float2half_rn(v1.w);
        ((uint4*)g_x16)[i] = *(uint4*)h;
    }
}

// ---------------------------------------------------------------------------
// k_zero: zero all atomically-accumulated buffers (g_AX, g_Q, g_XCLS, out)
// ---------------------------------------------------------------------------
__global__ __launch_bounds__(256) void k_zero(float* __restrict__ out) {
    const float4 z = make_float4(0.f, 0.f, 0.f, 0.f);
    size_t stride = (size_t)gridDim.x * 256;
    size_t t0 = blockIdx.x * 256 + threadIdx.x;
    for (size_t i = t0; i < (size_t)B_ * M_ * C_ / 4; i += stride) ((float4*)g_AX)[i] = z;
    for (size_t i = t0; i < (size_t)B_ * R_ * C_ / 4; i += stride) {
        ((float4*)g_Q)[i] = z;
        ((float4*)g_XCLS)[i] = z;
        ((float4*)out)[i] = z;
    }
}

// ---------------------------------------------------------------------------
// k_q: Q[b,r,c'] += SCALE * sum_{c in slice} x[b,r,c] * Wq[c',c]
// K-split x8: grid (6, 8, 8) = 384 blocks. atomicAdd epilogue.
// ---------------------------------------------------------------------------
#define QK_SLICE (C_ / 8)   // 192
__global__ __launch_bounds__(256) void k_q(const float* __restrict__ x,
                                           const float* __restrict__ Wq) {
    __shared__ float xs[R_ * QK_SLICE];
    int b = blockIdx.y, kc = blockIdx.z, t = threadIdx.x;
    int k0 = kc * QK_SLICE;
    for (int i = t; i < R_ * QK_SLICE / 4; i += 256) {
        int r = i / (QK_SLICE / 4), c4 = i % (QK_SLICE / 4);
        ((float4*)xs)[i] = *(const float4*)(x + ((size_t)(b * N_ + r)) * C_ + k0 + c4 * 4);
    }
    __syncthreads();
    int cp = blockIdx.x * 256 + t;
    const float4* wr = (const float4*)(Wq + (size_t)cp * C_ + k0);
    float acc[R_] = {};
    #pragma unroll 4
    for (int k4 = 0; k4 < QK_SLICE / 4; k4++) {
        float4 w = wr[k4];
        #pragma unroll
        for (int r = 0; r < R_; r++) {
            float4 a = ((const float4*)(xs + r * QK_SLICE))[k4];
            acc[r] += a.x * w.x + a.y * w.y + a.z * w.z + a.w * w.w;
        }
    }
    #pragma unroll
    for (int r = 0; r < R_; r++)
        atomicAdd(&g_Q[(b * R_ + r) * C_ + cp], acc[r] * SCALE_);
}

// ---------------------------------------------------------------------------
// k_qk: QK16[b, h*8+r, c] = sum_d Q[b,r,h*64+d] * Wk[h*64+d, c]
// grid (12 c-tiles, 24 h, 4 br-quarters) = 1152 blocks, 128 threads,
// 16 accs/thread -> low regs, high occupancy.
// ---------------------------------------------------------------------------
__global__ __launch_bounds__(128) void k_qk(const float* __restrict__ Wk) {
    __shared__ float Qs[16][64];
    int h = blockIdx.y, qt = blockIdx.z, t = threadIdx.x;
    for (int i = t; i < 16 * 64; i += 128) {
        int brl = i >> 6, d = i & 63;
        Qs[brl][d] = g_Q[(qt * 16 + brl) * C_ + h * 64 + d];
    }
    __syncthreads();
    int c = blockIdx.x * 128 + t;
    float acc[16] = {};
    #pragma unroll 4
    for (int d = 0; d < 64; d++) {
        float w = Wk[(size_t)(h * 64 + d) * C_ + c];
        #pragma unroll
        for (int brl = 0; brl < 16; brl++) acc[brl] += Qs[brl][d] * w;
    }
    #pragma unroll
    for (int brl = 0; brl < 16; brl++) {
        int br = qt * 16 + brl;
        int b = br >> 3, r = br & 7;
        g_QK16[((size_t)(b * M_ + h * 8 + r)) * C_ + c] = __float2half_rn(acc[brl]);
    }
}

// ---------------------------------------------------------------------------
// k_scores: S = QK16 . x16^T   fp16 mma m16n8k16, ldmatrix, 3-stage cp.async
// BM=192 (all M), BN=128, BK=32. 384 threads: 12 warps (3m x 4n), warp 64x32.
// grid (32, 1, 8)
// ---------------------------------------------------------------------------
#define SC_STAGE 25600                       // bytes per stage (A 15360 + B 10240)
#define SC_BOFF  15360
__global__ __launch_bounds__(384) void k_scores() {
    extern __shared__ char smem[];
    uint32_t sb = (uint32_t)__cvta_generic_to_shared(smem);
    int b = blockIdx.z, nt = blockIdx.x;
    int tid = threadIdx.x, lane = tid & 31, warp = tid >> 5;
    int g = lane >> 2, q = lane & 3;
    int m0 = (warp >> 2) * 64, n0 = (warp & 3) * 32;

    const __half* Ab = g_QK16 + (size_t)b * M_ * C_;
    const __half* Bb = g_x16 + ((size_t)(b * N_ + nt * 128)) * C_;

    float acc[4][4][4] = {};

    #define SC_LOAD(st, itv)                                                     \
        do {                                                                     \
            uint32_t a0 = sb + (st) * SC_STAGE;                                  \
            uint32_t b0 = a0 + SC_BOFF;                                          \
            int kb = (itv) * 32;                                                 \
            for (int i = tid; i < 1280; i += 384) {                              \
                if (i < 768) {                                                   \
                    int row = i >> 2, ch = i & 3;                                \
                    CPA(a0 + (row * 40 + ch * 8) * 2,                            \
                        Ab + (size_t)row * C_ + kb + ch * 8);                    \
                } else {                                                         \
                    int j = i - 768;                                             \
                    int row = j >> 2, ch = j & 3;                                \
                    CPA(b0 + (row * 40 + ch * 8) * 2,                            \
                        Bb + (size_t)row * C_ + kb + ch * 8);                    \
                }                                                                \
            }                                                                    \
            CPCOMMIT();                                                          \
        } while (0)

    const int NK = C_ / 32;  // 48
    SC_LOAD(0, 0); SC_LOAD(1, 1); SC_LOAD(2, 2);

    for (int it = 0; it < NK; ++it) {
        int s = it % 3;
        int pend = NK - 1 - it;
        if (pend >= 2)      CPWAIT2();
        else if (pend == 1) CPWAIT1();
        else                CPWAIT0();
        __syncthreads();

        uint32_t aB = sb + s * SC_STAGE;
        uint32_t bB = aB + SC_BOFF;
        #pragma unroll
        for (int ks = 0; ks < 32; ks += 16) {
            uint32_t a[4][4];
            #pragma unroll
            for (int mi = 0; mi < 4; mi++) {
                uint32_t ad = aB + ((m0 + mi * 16 + (lane & 7) + ((lane >> 3) & 1) * 8) * 40
                                    + ks + (lane >> 4) * 8) * 2;
                LDSM4(a[mi][0], a[mi][1], a[mi][2], a[mi][3], ad);
            }
            uint32_t bf[2][4];
            #pragma unroll
            for (int bi = 0; bi < 2; bi++) {
                uint32_t bd = bB + ((n0 + bi * 16 + (lane & 7) + ((lane >> 4) & 1) * 8) * 40
                                    + ks + ((lane >> 3) & 1) * 8) * 2;
                LDSM4(bf[bi][0], bf[bi][1], bf[bi][2], bf[bi][3], bd);
            }
            #pragma unroll
            for (int mi = 0; mi < 4; mi++)
                #pragma unroll
                for (int ni = 0; ni < 4; ni++)
                    mma16(acc[mi][ni], a[mi], &bf[ni >> 1][(ni & 1) * 2]);
        }
        __syncthreads();
        int nx = it + 3;
        if (nx < NK) SC_LOAD(s, nx);
    }
    #undef SC_LOAD

    float* Cb = g_S + (size_t)b * M_ * N_ + (size_t)nt * 128;
    #pragma unroll
    for (int mi = 0; mi < 4; mi++)
        #pragma unroll
        for (int ni = 0; ni < 4; ni++) {
            int row = m0 + mi * 16 + g;
            int col = n0 + ni * 8 + q * 2;
            *(float2*)(Cb + (size_t)row * N_ + col)       = make_float2(acc[mi][ni][0], acc[mi][ni][1]);
            *(float2*)(Cb + (size_t)(row + 8) * N_ + col) = make_float2(acc[mi][ni][2], acc[mi][ni][3]);
        }
}

// ---------------------------------------------------------------------------
// k_softmax: masked softmax; reads g_S f32, writes g_P16 fp16
// ---------------------------------------------------------------------------
__global__ __launch_bounds__(256) void k_softmax(const int* __restrict__ mask) {
    int row = blockIdx.x;
    int b = row / M_, m = row % M_, r = m & 7;
    const float* S = g_S + (size_t)row * N_;
    __half* P = g_P16 + (size_t)row * N_;
    const int* mrow = mask + ((size_t)(b * R_ + r)) * (N_ - R_);
    int tid = threadIdx.x;

    float vals[16];
    float mx = -1e30f;
    #pragma unroll
    for (int i = 0; i < 16; i++) {
        int n = i * 256 + tid;
        float s = S[n];
        bool valid = (n < R_) ? (n == r) : (mrow[n - R_] != 0);
        s = valid ? s : -1e30f;
        vals[i] = s;
        mx = fmaxf(mx, s);
    }
    __shared__ float smx[8], ssm[8];
    float wmx = warpMax(mx);
    if ((tid & 31) == 0) smx[tid >> 5] = wmx;
    __syncthreads();
    float bm = smx[0];
    #pragma unroll
    for (int j = 1; j < 8; j++) bm = fmaxf(bm, smx[j]);

    float sum = 0.f;
    #pragma unroll
    for (int i = 0; i < 16; i++) {
        vals[i] = expf(vals[i] - bm);
        sum += vals[i];
    }
    float wsm = warpSum(sum);
    if ((tid & 31) == 0) ssm[tid >> 5] = wsm;
    __syncthreads();
    float tot = 0.f;
    #pragma unroll
    for (int j = 0; j < 8; j++) tot += ssm[j];
    float inv = 1.0f / tot;
    #pragma unroll
    for (int i = 0; i < 16; i++) P[i * 256 + tid] = __float2half_rn(vals[i] * inv);
}

// ---------------------------------------------------------------------------
// k_ax: AX[m,c] += sum_{n in split} P16[m,n] * x16[n,c]   (split-K x4)
// BM=192, BN=128 (c), BK=32 (tokens). 384 threads: 12 warps (3m x 4n).
// grid (12, 4, 8). Epilogue: atomicAdd into zeroed g_AX.
// ---------------------------------------------------------------------------
#define AX_STAGE 24064                       // A 15360 + B 8704 (32 x 136 halfs)
#define AX_BOFF  15360
#define AX_SPLIT 4
__global__ __launch_bounds__(384) void k_ax() {
    extern __shared__ char smem[];
    uint32_t sb = (uint32_t)__cvta_generic_to_shared(smem);
    int b = blockIdx.z, nt = blockIdx.x, kc = blockIdx.y;
    int tid = threadIdx.x, lane = tid & 31, warp = tid >> 5;
    int g = lane >> 2, q = lane & 3;
    int m0 = (warp >> 2) * 64, n0 = (warp & 3) * 32;

    const int K0 = kc * (N_ / AX_SPLIT);
    const __half* Ab = g_P16 + (size_t)b * M_ * N_ + K0;
    const __half* Bx = g_x16 + (size_t)b * N_ * C_ + (size_t)K0 * C_ + nt * 128;

    float acc[4][4][4] = {};

    #define AX_LOAD(st, itv)                                                     \
        do {                                                                     \
            uint32_t a0 = sb + (st) * AX_STAGE;                                  \
            uint32_t b0 = a0 + AX_BOFF;                                          \
            int kb = (itv) * 32;                                                 \
            for (int i = tid; i < 1280; i += 384) {                              \
                if (i < 768) {                                                   \
                    int row = i >> 2, ch = i & 3;                                \
                    CPA(a0 + (row * 40 + ch * 8) * 2,                            \
                        Ab + (size_t)row * N_ + kb + ch * 8);                    \
                } else {                                                         \
                    int j = i - 768;                                             \
                    int row = j >> 4, ch = j & 15;                               \
                    CPA(b0 + (row * 136 + ch * 8) * 2,                           \
                        Bx + (size_t)(kb + row) * C_ + ch * 8);                  \
                }                                                                \
            }                                                                    \
            CPCOMMIT();                                                          \
        } while (0)

    const int NK = (N_ / AX_SPLIT) / 32;  // 32
    AX_LOAD(0, 0); AX_LOAD(1, 1); AX_LOAD(2, 2);

    for (int it = 0; it < NK; ++it) {
        int s = it % 3;
        int pend = NK - 1 - it;
        if (pend >= 2)      CPWAIT2();
        else if (pend == 1) CPWAIT1();
        else                CPWAIT0();
        __syncthreads();

        uint32_t aB = sb + s * AX_STAGE;
        uint32_t bB = aB + AX_BOFF;
        #pragma unroll
        for (int ks = 0; ks < 32; ks += 16) {
            uint32_t a[4][4];
            #pragma unroll
            for (int mi = 0; mi < 4; mi++) {
                uint32_t ad = aB + ((m0 + mi * 16 + (lane & 7) + ((lane >> 3) & 1) * 8) * 40
                                    + ks + (lane >> 4) * 8) * 2;
                LDSM4(a[mi][0], a[mi][1], a[mi][2], a[mi][3], ad);
            }
            uint32_t bf[2][4];
            #pragma unroll
            for (int bi = 0; bi < 2; bi++) {
                uint32_t bd = bB + ((ks + (lane & 7) + ((lane >> 3) & 1) * 8) * 136
                                    + n0 + bi * 16 + ((lane >> 4) & 1) * 8) * 2;
                LDSM4T(bf[bi][0], bf[bi][1], bf[bi][2], bf[bi][3], bd);
            }
            #pragma unroll
            for (int mi = 0; mi < 4; mi++)
                #pragma unroll
                for (int ni = 0; ni < 4; ni++)
                    mma16(acc[mi][ni], a[mi], &bf[ni >> 1][(ni & 1) * 2]);
        }
        __syncthreads();
        int nx = it + 3;
        if (nx < NK) AX_LOAD(s, nx);
    }
    #undef AX_LOAD

    float* Cb = g_AX + (size_t)b * M_ * C_ + nt * 128;
    #pragma unroll
    for (int mi = 0; mi < 4; mi++)
        #pragma unroll
        for (int ni = 0; ni < 4; ni++) {
            int row = m0 + mi * 16 + g;
            int col = n0 + ni * 8 + q * 2;
            float* p0 = Cb + (size_t)row * C_ + col;
            float* p1 = Cb + (size_t)(row + 8) * C_ + col;
            atomicAdd(p0,     acc[mi][ni][0]);
            atomicAdd(p0 + 1, acc[mi][ni][1]);
            atomicAdd(p1,     acc[mi][ni][2]);
            atomicAdd(p1 + 1, acc[mi][ni][3]);
        }
}

// ---------------------------------------------------------------------------
// k_d1: XCLS[b,r,cc] += sum_{c in slice} AX[b, (cc/64)*8+r, c] * Wv[cc, c]
// K-split x8: grid (6, 8, 8). atomicAdd into zeroed g_XCLS.
// ---------------------------------------------------------------------------
__global__ __launch_bounds__(256) void k_d1(const float* __restrict__ Wv) {
    int b = blockIdx.y, kc = blockIdx.z, t = threadIdx.x;
    int k0 = kc * QK_SLICE;
    int cc = blockIdx.x * 256 + t;
    int h = cc >> 6;
    const float4* wr = (const float4*)(Wv + (size_t)cc * C_ + k0);
    const float4* ax[R_];
    #pragma unroll
    for (int r = 0; r < R_; r++)
        ax[r] = (const float4*)(g_AX + ((size_t)b * M_ + h * 8 + r) * C_ + k0);
    float acc[R_] = {};
    #pragma unroll 4
    for (int k4 = 0; k4 < QK_SLICE / 4; k4++) {
        float4 w = wr[k4];
        #pragma unroll
        for (int r = 0; r < R_; r++) {
            float4 a = ax[r][k4];
            acc[r] += a.x * w.x + a.y * w.y + a.z * w.z + a.w * w.w;
        }
    }
    #pragma unroll
    for (int r = 0; r < R_; r++)
        atomicAdd(&g_XCLS[(b * R_ + r) * C_ + cc], acc[r]);
}

// ---------------------------------------------------------------------------
// k_d2: out[b,r,c'] += sum_{cc in slice} XCLS[b,r,cc] * Wp[c',cc]  (+bias on kc0)
// K-split x8: grid (6, 8, 8). atomicAdd into zeroed out.
// ---------------------------------------------------------------------------
__global__ __launch_bounds__(256) void k_d2(const float* __restrict__ Wp,
                                            const float* __restrict__ bp,
                                            float* __restrict__ out) {
    int b = blockIdx.y, kc = blockIdx.z, t = threadIdx.x;
    int k0 = kc * QK_SLICE;
    int cp = blockIdx.x * 256 + t;
    const float4* wr = (const float4*)(Wp + (size_t)cp * C_ + k0);
    const float4* xc[R_];
    #pragma unroll
    for (int r = 0; r < R_; r++)
        xc[r] = (const float4*)(g_XCLS + (size_t)(b * R_ + r) * C_ + k0);
    float acc[R_] = {};
    #pragma unroll 4
    for (int k4 = 0; k4 < QK_SLICE / 4; k4++) {
        float4 w = wr[k4];
        #pragma unroll
        for (int r = 0; r < R_; r++) {
            float4 a = xc[r][k4];
            acc[r] += a.x * w.x + a.y * w.y + a.z * w.z + a.w * w.w;
        }
    }
    float bias = (kc == 0) ? bp[cp] : 0.f;
    #pragma unroll
    for (int r = 0; r < R_; r++)
        atomicAdd(&out[((size_t)(b * R_ + r)) * C_ + cp], acc[r] + bias);
}

// ---------------------------------------------------------------------------
// launch
// ---------------------------------------------------------------------------
extern "C" void kernel_launch(void* const* d_in, const int* in_sizes, int n_in,
                              void* d_out, int out_size) {
    const float* x    = (const float*)d_in[0];
    const int*   mask = (const int*)d_in[1];
    const float* Wq   = (const float*)d_in[2];
    const float* Wk   = (const float*)d_in[3];
    const float* Wv   = (const float*)d_in[4];
    const float* Wp   = (const float*)d_in[5];
    const float* bp   = (const float*)d_in[6];
    float* out = (float*)d_out;

    const int SC_SMEM = 3 * SC_STAGE;  // 76800
    const int AX_SMEM = 3 * AX_STAGE;  // 72192
    cudaFuncSetAttribute(k_scores, cudaFuncAttributeMaxDynamicSharedMemorySize, SC_SMEM);
    cudaFuncSetAttribute(k_ax,     cudaFuncAttributeMaxDynamicSharedMemorySize, AX_SMEM);

    k_zero   <<<1024, 256>>>(out);
    k_conv   <<<4096, 256>>>(x);
    k_q      <<<dim3(C_ / 256, B_, 8), 256>>>(x, Wq);
    k_qk     <<<dim3(C_ / 128, H_, 4), 128>>>(Wk);
    k_scores <<<dim3(N_ / 128, 1, B_), 384, SC_SMEM>>>();
    k_softmax<<<B_ * M_, 256>>>(mask);
    k_ax     <<<dim3(C_ / 128, AX_SPLIT, B_), 384, AX_SMEM>>>();
    k_d1     <<<dim3(C_ / 256, B_, 8), 256>>>(Wv);
    k_d2     <<<dim3(C_ / 256, B_, 8), 256>>>(Wp, bp, out);
}

// round 9
// speedup vs baseline: 2.9554x; 1.0897x over previous
#include <cuda_runtime.h>
#include <cuda_fp16.h>
#include <cstdint>

// Problem constants
#define B_   8
#define N_   4096
#define C_   1536
#define H_   24
#define R_   8
#define M_   192
#define SCALE_ 0.125f

// Scratch (static device globals)
__device__ float    g_Q[B_ * R_ * C_];                 // atomically accumulated
__device__ __half   g_QK16[B_ * M_ * C_];              // q@Wk, fp16
__device__ float    g_S[(size_t)B_ * M_ * N_];         // scores f32
__device__ __half   g_P16[(size_t)B_ * M_ * N_];       // softmax probs fp16
__device__ float    g_AX[B_ * M_ * C_];                // P @ x (split-K accumulated)
__device__ float    g_XCLS[B_ * R_ * C_];              // atomically accumulated
__device__ __half   g_x16[(size_t)B_ * N_ * C_];       // x fp16

// ---------------------------------------------------------------------------
// helpers
// ---------------------------------------------------------------------------
#define CPA(dst, src) asm volatile("cp.async.cg.shared.global [%0], [%1], 16;" :: "r"(dst), "l"(src))
#define CPCOMMIT()    asm volatile("cp.async.commit_group;")
#define CPWAIT0()     asm volatile("cp.async.wait_group 0;")
#define CPWAIT1()     asm volatile("cp.async.wait_group 1;")
#define CPWAIT2()     asm volatile("cp.async.wait_group 2;")

#define LDSM4(r0, r1, r2, r3, addr) \
    asm volatile("ldmatrix.sync.aligned.m8n8.x4.shared.b16 {%0,%1,%2,%3}, [%4];" \
                 : "=r"(r0), "=r"(r1), "=r"(r2), "=r"(r3) : "r"(addr))
#define LDSM4T(r0, r1, r2, r3, addr) \
    asm volatile("ldmatrix.sync.aligned.m8n8.x4.trans.shared.b16 {%0,%1,%2,%3}, [%4];" \
                 : "=r"(r0), "=r"(r1), "=r"(r2), "=r"(r3) : "r"(addr))

__device__ __forceinline__ void mma16(float* c, const uint32_t* a, const uint32_t* b) {
    asm volatile(
        "mma.sync.aligned.m16n8k16.row.col.f32.f16.f16.f32 "
        "{%0,%1,%2,%3}, {%4,%5,%6,%7}, {%8,%9}, {%0,%1,%2,%3};"
        : "+f"(c[0]), "+f"(c[1]), "+f"(c[2]), "+f"(c[3])
        : "r"(a[0]), "r"(a[1]), "r"(a[2]), "r"(a[3]), "r"(b[0]), "r"(b[1]));
}

__device__ __forceinline__ float warpMax(float v) {
    #pragma unroll
    for (int o = 16; o; o >>= 1) v = fmaxf(v, __shfl_xor_sync(0xffffffffu, v, o));
    return v;
}
__device__ __forceinline__ float warpSum(float v) {
    #pragma unroll
    for (int o = 16; o; o >>= 1) v += __shfl_xor_sync(0xffffffffu, v, o);
    return v;
}

// ---------------------------------------------------------------------------
// k_conv: x (f32) -> g_x16 (fp16), linear
// ---------------------------------------------------------------------------
__global__ __launch_bounds__(256) void k_conv(const float* __restrict__ x) {
    const size_t total = (size_t)B_ * N_ * C_ / 8;
    size_t stride = (size_t)gridDim.x * 256;
    for (size_t i = blockIdx.x * 256 + threadIdx.x; i < total; i += stride) {
        float4 v0 = ((const float4*)x)[i * 2];
        float4 v1 = ((const float4*)x)[i * 2 + 1];
        __half h[8];
        h[0] = __float2half_rn(v0.x); h[1] = __float2half_rn(v0.y);
        h[2] = __float2half_rn(v0.z); h[3] = __float2half_rn(v0.w);
        h[4] = __float2half_rn(v1.x); h[5] = __float2half_rn(v1.y);
        h[6] = __float2half_rn(v1.z); h[7] = __float2half_rn(v1.w);
        ((uint4*)g_x16)[i] = *(uint4*)h;
    }
}

// ---------------------------------------------------------------------------
// k_zero: zero all atomically-accumulated buffers (g_AX, g_Q, g_XCLS, out)
// ---------------------------------------------------------------------------
__global__ __launch_bounds__(256) void k_zero(float* __restrict__ out) {
    const float4 z = make_float4(0.f, 0.f, 0.f, 0.f);
    size_t stride = (size_t)gridDim.x * 256;
    size_t t0 = blockIdx.x * 256 + threadIdx.x;
    for (size_t i = t0; i < (size_t)B_ * M_ * C_ / 4; i += stride) ((float4*)g_AX)[i] = z;
    for (size_t i = t0; i < (size_t)B_ * R_ * C_ / 4; i += stride) {
        ((float4*)g_Q)[i] = z;
        ((float4*)g_XCLS)[i] = z;
        ((float4*)out)[i] = z;
    }
}

// ---------------------------------------------------------------------------
// k_q: Q[b,r,c'] += SCALE * sum_{c in slice} x[b,r,c] * Wq[c',c]
// K-split x16: grid (6, 8, 16) = 768 blocks. atomicAdd epilogue.
// ---------------------------------------------------------------------------
#define QK_SLICE (C_ / 16)   // 96
__global__ __launch_bounds__(256) void k_q(const float* __restrict__ x,
                                           const float* __restrict__ Wq) {
    __shared__ float xs[R_ * QK_SLICE];
    int b = blockIdx.y, kc = blockIdx.z, t = threadIdx.x;
    int k0 = kc * QK_SLICE;
    if (t < R_ * QK_SLICE / 4) {
        int r = t / (QK_SLICE / 4), c4 = t % (QK_SLICE / 4);
        ((float4*)xs)[t] = *(const float4*)(x + ((size_t)(b * N_ + r)) * C_ + k0 + c4 * 4);
    }
    __syncthreads();
    int cp = blockIdx.x * 256 + t;
    const float4* wr = (const float4*)(Wq + (size_t)cp * C_ + k0);
    float acc[R_] = {};
    #pragma unroll 4
    for (int k4 = 0; k4 < QK_SLICE / 4; k4++) {
        float4 w = wr[k4];
        #pragma unroll
        for (int r = 0; r < R_; r++) {
            float4 a = ((const float4*)(xs + r * QK_SLICE))[k4];
            acc[r] += a.x * w.x + a.y * w.y + a.z * w.z + a.w * w.w;
        }
    }
    #pragma unroll
    for (int r = 0; r < R_; r++)
        atomicAdd(&g_Q[(b * R_ + r) * C_ + cp], acc[r] * SCALE_);
}

// ---------------------------------------------------------------------------
// k_qk: QK16[b, h*8+r, c] = sum_d Q[b,r,h*64+d] * Wk[h*64+d, c]
// grid (12 c-tiles, 24 h, 4 br-quarters) = 1152 blocks, 128 threads.
// ---------------------------------------------------------------------------
__global__ __launch_bounds__(128) void k_qk(const float* __restrict__ Wk) {
    __shared__ float Qs[16][64];
    int h = blockIdx.y, qt = blockIdx.z, t = threadIdx.x;
    for (int i = t; i < 16 * 64; i += 128) {
        int brl = i >> 6, d = i & 63;
        Qs[brl][d] = g_Q[(qt * 16 + brl) * C_ + h * 64 + d];
    }
    __syncthreads();
    int c = blockIdx.x * 128 + t;
    float acc[16] = {};
    #pragma unroll 4
    for (int d = 0; d < 64; d++) {
        float w = Wk[(size_t)(h * 64 + d) * C_ + c];
        #pragma unroll
        for (int brl = 0; brl < 16; brl++) acc[brl] += Qs[brl][d] * w;
    }
    #pragma unroll
    for (int brl = 0; brl < 16; brl++) {
        int br = qt * 16 + brl;
        int b = br >> 3, r = br & 7;
        g_QK16[((size_t)(b * M_ + h * 8 + r)) * C_ + c] = __float2half_rn(acc[brl]);
    }
}

// ---------------------------------------------------------------------------
// k_scores: S = QK16 . x16^T   fp16 mma, BK=64, 3-stage cp.async
// BM=192 (all M), BN=128. 384 threads: 12 warps (3m x 4n), warp 64x32.
// grid (32, 1, 8). Stage: A 192x72 halfs (27648B) + B 128x72 (18432B).
// ---------------------------------------------------------------------------
#define SC_STAGE 46080
#define SC_BOFF  27648
__global__ __launch_bounds__(384) void k_scores() {
    extern __shared__ char smem[];
    uint32_t sb = (uint32_t)__cvta_generic_to_shared(smem);
    int b = blockIdx.z, nt = blockIdx.x;
    int tid = threadIdx.x, lane = tid & 31, warp = tid >> 5;
    int g = lane >> 2, q = lane & 3;
    int m0 = (warp >> 2) * 64, n0 = (warp & 3) * 32;

    const __half* Ab = g_QK16 + (size_t)b * M_ * C_;
    const __half* Bb = g_x16 + ((size_t)(b * N_ + nt * 128)) * C_;

    float acc[4][4][4] = {};

    #define SC_LOAD(st, itv)                                                     \
        do {                                                                     \
            uint32_t a0 = sb + (st) * SC_STAGE;                                  \
            uint32_t b0 = a0 + SC_BOFF;                                          \
            int kb = (itv) * 64;                                                 \
            for (int i = tid; i < 2560; i += 384) {                              \
                if (i < 1536) {                                                  \
                    int row = i >> 3, ch = i & 7;                                \
                    CPA(a0 + (row * 72 + ch * 8) * 2,                            \
                        Ab + (size_t)row * C_ + kb + ch * 8);                    \
                } else {                                                         \
                    int j = i - 1536;                                            \
                    int row = j >> 3, ch = j & 7;                                \
                    CPA(b0 + (row * 72 + ch * 8) * 2,                            \
                        Bb + (size_t)row * C_ + kb + ch * 8);                    \
                }                                                                \
            }                                                                    \
            CPCOMMIT();                                                          \
        } while (0)

    const int NK = C_ / 64;  // 24
    SC_LOAD(0, 0); SC_LOAD(1, 1); SC_LOAD(2, 2);

    for (int it = 0; it < NK; ++it) {
        int s = it % 3;
        int pend = NK - 1 - it;
        if (pend >= 2)      CPWAIT2();
        else if (pend == 1) CPWAIT1();
        else                CPWAIT0();
        __syncthreads();

        uint32_t aB = sb + s * SC_STAGE;
        uint32_t bB = aB + SC_BOFF;
        #pragma unroll
        for (int ks = 0; ks < 64; ks += 16) {
            uint32_t a[4][4];
            #pragma unroll
            for (int mi = 0; mi < 4; mi++) {
                uint32_t ad = aB + ((m0 + mi * 16 + (lane & 7) + ((lane >> 3) & 1) * 8) * 72
                                    + ks + (lane >> 4) * 8) * 2;
                LDSM4(a[mi][0], a[mi][1], a[mi][2], a[mi][3], ad);
            }
            uint32_t bf[2][4];
            #pragma unroll
            for (int bi = 0; bi < 2; bi++) {
                uint32_t bd = bB + ((n0 + bi * 16 + (lane & 7) + ((lane >> 4) & 1) * 8) * 72
                                    + ks + ((lane >> 3) & 1) * 8) * 2;
                LDSM4(bf[bi][0], bf[bi][1], bf[bi][2], bf[bi][3], bd);
            }
            #pragma unroll
            for (int mi = 0; mi < 4; mi++)
                #pragma unroll
                for (int ni = 0; ni < 4; ni++)
                    mma16(acc[mi][ni], a[mi], &bf[ni >> 1][(ni & 1) * 2]);
        }
        __syncthreads();
        int nx = it + 3;
        if (nx < NK) SC_LOAD(s, nx);
    }
    #undef SC_LOAD

    float* Cb = g_S + (size_t)b * M_ * N_ + (size_t)nt * 128;
    #pragma unroll
    for (int mi = 0; mi < 4; mi++)
        #pragma unroll
        for (int ni = 0; ni < 4; ni++) {
            int row = m0 + mi * 16 + g;
            int col = n0 + ni * 8 + q * 2;
            *(float2*)(Cb + (size_t)row * N_ + col)       = make_float2(acc[mi][ni][0], acc[mi][ni][1]);
            *(float2*)(Cb + (size_t)(row + 8) * N_ + col) = make_float2(acc[mi][ni][2], acc[mi][ni][3]);
        }
}

// ---------------------------------------------------------------------------
// k_softmax: masked softmax; reads g_S f32, writes g_P16 fp16
// ---------------------------------------------------------------------------
__global__ __launch_bounds__(256) void k_softmax(const int* __restrict__ mask) {
    int row = blockIdx.x;
    int b = row / M_, m = row % M_, r = m & 7;
    const float* S = g_S + (size_t)row * N_;
    __half* P = g_P16 + (size_t)row * N_;
    const int* mrow = mask + ((size_t)(b * R_ + r)) * (N_ - R_);
    int tid = threadIdx.x;

    float vals[16];
    float mx = -1e30f;
    #pragma unroll
    for (int i = 0; i < 16; i++) {
        int n = i * 256 + tid;
        float s = S[n];
        bool valid = (n < R_) ? (n == r) : (mrow[n - R_] != 0);
        s = valid ? s : -1e30f;
        vals[i] = s;
        mx = fmaxf(mx, s);
    }
    __shared__ float smx[8], ssm[8];
    float wmx = warpMax(mx);
    if ((tid & 31) == 0) smx[tid >> 5] = wmx;
    __syncthreads();
    float bm = smx[0];
    #pragma unroll
    for (int j = 1; j < 8; j++) bm = fmaxf(bm, smx[j]);

    float sum = 0.f;
    #pragma unroll
    for (int i = 0; i < 16; i++) {
        vals[i] = expf(vals[i] - bm);
        sum += vals[i];
    }
    float wsm = warpSum(sum);
    if ((tid & 31) == 0) ssm[tid >> 5] = wsm;
    __syncthreads();
    float tot = 0.f;
    #pragma unroll
    for (int j = 0; j < 8; j++) tot += ssm[j];
    float inv = 1.0f / tot;
    #pragma unroll
    for (int i = 0; i < 16; i++) P[i * 256 + tid] = __float2half_rn(vals[i] * inv);
}

// ---------------------------------------------------------------------------
// k_ax: AX[m,c] += sum_{n in split} P16[m,n] * x16[n,c]   (split-K x4)
// BM=192, BN=128 (c), BK=64 (tokens), 3-stage. 384 threads: 12 warps.
// grid (12, 4, 8). Stage: A 192x72 halfs (27648B) + B 64x136 halfs (17408B).
// ---------------------------------------------------------------------------
#define AX_STAGE 45056
#define AX_BOFF  27648
#define AX_SPLIT 4
__global__ __launch_bounds__(384) void k_ax() {
    extern __shared__ char smem[];
    uint32_t sb = (uint32_t)__cvta_generic_to_shared(smem);
    int b = blockIdx.z, nt = blockIdx.x, kc = blockIdx.y;
    int tid = threadIdx.x, lane = tid & 31, warp = tid >> 5;
    int g = lane >> 2, q = lane & 3;
    int m0 = (warp >> 2) * 64, n0 = (warp & 3) * 32;

    const int K0 = kc * (N_ / AX_SPLIT);
    const __half* Ab = g_P16 + (size_t)b * M_ * N_ + K0;
    const __half* Bx = g_x16 + (size_t)b * N_ * C_ + (size_t)K0 * C_ + nt * 128;

    float acc[4][4][4] = {};

    #define AX_LOAD(st, itv)                                                     \
        do {                                                                     \
            uint32_t a0 = sb + (st) * AX_STAGE;                                  \
            uint32_t b0 = a0 + AX_BOFF;                                          \
            int kb = (itv) * 64;                                                 \
            for (int i = tid; i < 2560; i += 384) {                              \
                if (i < 1536) {                                                  \
                    int row = i >> 3, ch = i & 7;                                \
                    CPA(a0 + (row * 72 + ch * 8) * 2,                            \
                        Ab + (size_t)row * N_ + kb + ch * 8);                    \
                } else {                                                         \
                    int j = i - 1536;                                            \
                    int row = j >> 4, ch = j & 15;                               \
                    CPA(b0 + (row * 136 + ch * 8) * 2,                           \
                        Bx + (size_t)(kb + row) * C_ + ch * 8);                  \
                }                                                                \
            }                                                                    \
            CPCOMMIT();                                                          \
        } while (0)

    const int NK = (N_ / AX_SPLIT) / 64;  // 16
    AX_LOAD(0, 0); AX_LOAD(1, 1); AX_LOAD(2, 2);

    for (int it = 0; it < NK; ++it) {
        int s = it % 3;
        int pend = NK - 1 - it;
        if (pend >= 2)      CPWAIT2();
        else if (pend == 1) CPWAIT1();
        else                CPWAIT0();
        __syncthreads();

        uint32_t aB = sb + s * AX_STAGE;
        uint32_t bB = aB + AX_BOFF;
        #pragma unroll
        for (int ks = 0; ks < 64; ks += 16) {
            uint32_t a[4][4];
            #pragma unroll
            for (int mi = 0; mi < 4; mi++) {
                uint32_t ad = aB + ((m0 + mi * 16 + (lane & 7) + ((lane >> 3) & 1) * 8) * 72
                                    + ks + (lane >> 4) * 8) * 2;
                LDSM4(a[mi][0], a[mi][1], a[mi][2], a[mi][3], ad);
            }
            uint32_t bf[2][4];
            #pragma unroll
            for (int bi = 0; bi < 2; bi++) {
                uint32_t bd = bB + ((ks + (lane & 7) + ((lane >> 3) & 1) * 8) * 136
                                    + n0 + bi * 16 + ((lane >> 4) & 1) * 8) * 2;
                LDSM4T(bf[bi][0], bf[bi][1], bf[bi][2], bf[bi][3], bd);
            }
            #pragma unroll
            for (int mi = 0; mi < 4; mi++)
                #pragma unroll
                for (int ni = 0; ni < 4; ni++)
                    mma16(acc[mi][ni], a[mi], &bf[ni >> 1][(ni & 1) * 2]);
        }
        __syncthreads();
        int nx = it + 3;
        if (nx < NK) AX_LOAD(s, nx);
    }
    #undef AX_LOAD

    float* Cb = g_AX + (size_t)b * M_ * C_ + nt * 128;
    #pragma unroll
    for (int mi = 0; mi < 4; mi++)
        #pragma unroll
        for (int ni = 0; ni < 4; ni++) {
            int row = m0 + mi * 16 + g;
            int col = n0 + ni * 8 + q * 2;
            float* p0 = Cb + (size_t)row * C_ + col;
            float* p1 = Cb + (size_t)(row + 8) * C_ + col;
            atomicAdd(p0,     acc[mi][ni][0]);
            atomicAdd(p0 + 1, acc[mi][ni][1]);
            atomicAdd(p1,     acc[mi][ni][2]);
            atomicAdd(p1 + 1, acc[mi][ni][3]);
        }
}

// ---------------------------------------------------------------------------
// k_d1: XCLS[b,r,cc] += sum_{c in slice} AX[b, (cc/64)*8+r, c] * Wv[cc, c]
// K-split x16: grid (6, 8, 16). atomicAdd into zeroed g_XCLS.
// ---------------------------------------------------------------------------
__global__ __launch_bounds__(256) void k_d1(const float* __restrict__ Wv) {
    int b = blockIdx.y, kc = blockIdx.z, t = threadIdx.x;
    int k0 = kc * QK_SLICE;
    int cc = blockIdx.x * 256 + t;
    int h = cc >> 6;
    const float4* wr = (const float4*)(Wv + (size_t)cc * C_ + k0);
    const float4* ax[R_];
    #pragma unroll
    for (int r = 0; r < R_; r++)
        ax[r] = (const float4*)(g_AX + ((size_t)b * M_ + h * 8 + r) * C_ + k0);
    float acc[R_] = {};
    #pragma unroll 4
    for (int k4 = 0; k4 < QK_SLICE / 4; k4++) {
        float4 w = wr[k4];
        #pragma unroll
        for (int r = 0; r < R_; r++) {
            float4 a = ax[r][k4];
            acc[r] += a.x * w.x + a.y * w.y + a.z * w.z + a.w * w.w;
        }
    }
    #pragma unroll
    for (int r = 0; r < R_; r++)
        atomicAdd(&g_XCLS[(b * R_ + r) * C_ + cc], acc[r]);
}

// ---------------------------------------------------------------------------
// k_d2: out[b,r,c'] += sum_{cc in slice} XCLS[b,r,cc] * Wp[c',cc]  (+bias on kc0)
// K-split x16: grid (6, 8, 16). atomicAdd into zeroed out.
// ---------------------------------------------------------------------------
__global__ __launch_bounds__(256) void k_d2(const float* __restrict__ Wp,
                                            const float* __restrict__ bp,
                                            float* __restrict__ out) {
    int b = blockIdx.y, kc = blockIdx.z, t = threadIdx.x;
    int k0 = kc * QK_SLICE;
    int cp = blockIdx.x * 256 + t;
    const float4* wr = (const float4*)(Wp + (size_t)cp * C_ + k0);
    const float4* xc[R_];
    #pragma unroll
    for (int r = 0; r < R_; r++)
        xc[r] = (const float4*)(g_XCLS + (size_t)(b * R_ + r) * C_ + k0);
    float acc[R_] = {};
    #pragma unroll 4
    for (int k4 = 0; k4 < QK_SLICE / 4; k4++) {
        float4 w = wr[k4];
        #pragma unroll
        for (int r = 0; r < R_; r++) {
            float4 a = xc[r][k4];
            acc[r] += a.x * w.x + a.y * w.y + a.z * w.z + a.w * w.w;
        }
    }
    float bias = (kc == 0) ? bp[cp] : 0.f;
    #pragma unroll
    for (int r = 0; r < R_; r++)
        atomicAdd(&out[((size_t)(b * R_ + r)) * C_ + cp], acc[r] + bias);
}

// ---------------------------------------------------------------------------
// launch
// ---------------------------------------------------------------------------
extern "C" void kernel_launch(void* const* d_in, const int* in_sizes, int n_in,
                              void* d_out, int out_size) {
    const float* x    = (const float*)d_in[0];
    const int*   mask = (const int*)d_in[1];
    const float* Wq   = (const float*)d_in[2];
    const float* Wk   = (const float*)d_in[3];
    const float* Wv   = (const float*)d_in[4];
    const float* Wp   = (const float*)d_in[5];
    const float* bp   = (const float*)d_in[6];
    float* out = (float*)d_out;

    const int SC_SMEM = 3 * SC_STAGE;  // 138240
    const int AX_SMEM = 3 * AX_STAGE;  // 135168
    cudaFuncSetAttribute(k_scores, cudaFuncAttributeMaxDynamicSharedMemorySize, SC_SMEM);
    cudaFuncSetAttribute(k_ax,     cudaFuncAttributeMaxDynamicSharedMemorySize, AX_SMEM);

    k_zero   <<<1024, 256>>>(out);
    k_conv   <<<4096, 256>>>(x);
    k_q      <<<dim3(C_ / 256, B_, 16), 256>>>(x, Wq);
    k_qk     <<<dim3(C_ / 128, H_, 4), 128>>>(Wk);
    k_scores <<<dim3(N_ / 128, 1, B_), 384, SC_SMEM>>>();
    k_softmax<<<B_ * M_, 256>>>(mask);
    k_ax     <<<dim3(C_ / 128, AX_SPLIT, B_), 384, AX_SMEM>>>();
    k_d1     <<<dim3(C_ / 256, B_, 16), 256>>>(Wv);
    k_d2     <<<dim3(C_ / 256, B_, 16), 256>>>(Wp, bp, out);
}

// round 10
// speedup vs baseline: 3.0242x; 1.0233x over previous
#include <cuda_runtime.h>
#include <cuda_fp16.h>
#include <cstdint>

// Problem constants
#define B_   8
#define N_   4096
#define C_   1536
#define H_   24
#define R_   8
#define M_   192
#define SCALE_ 0.125f

// Scratch (static device globals)
__device__ float    g_Q[B_ * R_ * C_];                 // atomically accumulated
__device__ __half   g_QK16[B_ * M_ * C_];              // q@Wk, fp16
__device__ float    g_S[(size_t)B_ * M_ * N_];         // scores f32
__device__ __half   g_P16[(size_t)B_ * M_ * N_];       // softmax probs fp16
__device__ float    g_AX[B_ * M_ * C_];                // P @ x (split-K accumulated)
__device__ float    g_XCLS[B_ * R_ * C_];              // atomically accumulated
__device__ __half   g_x16[(size_t)B_ * N_ * C_];       // x fp16

// ---------------------------------------------------------------------------
// helpers
// ---------------------------------------------------------------------------
#define CPA(dst, src) asm volatile("cp.async.cg.shared.global [%0], [%1], 16;" :: "r"(dst), "l"(src))
#define CPCOMMIT()    asm volatile("cp.async.commit_group;")
#define CPWAIT0()     asm volatile("cp.async.wait_group 0;")
#define CPWAIT1()     asm volatile("cp.async.wait_group 1;")
#define CPWAIT2()     asm volatile("cp.async.wait_group 2;")

#define LDSM4(r0, r1, r2, r3, addr) \
    asm volatile("ldmatrix.sync.aligned.m8n8.x4.shared.b16 {%0,%1,%2,%3}, [%4];" \
                 : "=r"(r0), "=r"(r1), "=r"(r2), "=r"(r3) : "r"(addr))
#define LDSM4T(r0, r1, r2, r3, addr) \
    asm volatile("ldmatrix.sync.aligned.m8n8.x4.trans.shared.b16 {%0,%1,%2,%3}, [%4];" \
                 : "=r"(r0), "=r"(r1), "=r"(r2), "=r"(r3) : "r"(addr))

__device__ __forceinline__ void mma16(float* c, const uint32_t* a, const uint32_t* b) {
    asm volatile(
        "mma.sync.aligned.m16n8k16.row.col.f32.f16.f16.f32 "
        "{%0,%1,%2,%3}, {%4,%5,%6,%7}, {%8,%9}, {%0,%1,%2,%3};"
        : "+f"(c[0]), "+f"(c[1]), "+f"(c[2]), "+f"(c[3])
        : "r"(a[0]), "r"(a[1]), "r"(a[2]), "r"(a[3]), "r"(b[0]), "r"(b[1]));
}

__device__ __forceinline__ float warpMax(float v) {
    #pragma unroll
    for (int o = 16; o; o >>= 1) v = fmaxf(v, __shfl_xor_sync(0xffffffffu, v, o));
    return v;
}
__device__ __forceinline__ float warpSum(float v) {
    #pragma unroll
    for (int o = 16; o; o >>= 1) v += __shfl_xor_sync(0xffffffffu, v, o);
    return v;
}

// ---------------------------------------------------------------------------
// k_conv: x (f32) -> g_x16 (fp16), linear
// ---------------------------------------------------------------------------
__global__ __launch_bounds__(256) void k_conv(const float* __restrict__ x) {
    const size_t total = (size_t)B_ * N_ * C_ / 8;
    size_t stride = (size_t)gridDim.x * 256;
    for (size_t i = blockIdx.x * 256 + threadIdx.x; i < total; i += stride) {
        float4 v0 = ((const float4*)x)[i * 2];
        float4 v1 = ((const float4*)x)[i * 2 + 1];
        __half h[8];
        h[0] = __float2half_rn(v0.x); h[1] = __float2half_rn(v0.y);
        h[2] = __float2half_rn(v0.z); h[3] = __float2half_rn(v0.w);
        h[4] = __float2half_rn(v1.x); h[5] = __float2half_rn(v1.y);
        h[6] = __float2half_rn(v1.z); h[7] = __float2half_rn(v1.w);
        ((uint4*)g_x16)[i] = *(uint4*)h;
    }
}

// ---------------------------------------------------------------------------
// k_zero: zero all atomically-accumulated buffers (g_AX, g_Q, g_XCLS, out)
// ---------------------------------------------------------------------------
__global__ __launch_bounds__(256) void k_zero(float* __restrict__ out) {
    const float4 z = make_float4(0.f, 0.f, 0.f, 0.f);
    size_t stride = (size_t)gridDim.x * 256;
    size_t t0 = blockIdx.x * 256 + threadIdx.x;
    for (size_t i = t0; i < (size_t)B_ * M_ * C_ / 4; i += stride) ((float4*)g_AX)[i] = z;
    for (size_t i = t0; i < (size_t)B_ * R_ * C_ / 4; i += stride) {
        ((float4*)g_Q)[i] = z;
        ((float4*)g_XCLS)[i] = z;
        ((float4*)out)[i] = z;
    }
}

// ---------------------------------------------------------------------------
// k_q: Q[b,r,c'] += SCALE * sum_{c in slice} x[b,r,c] * Wq[c',c]
// K-split x16: grid (6, 8, 16) = 768 blocks. atomicAdd epilogue.
// ---------------------------------------------------------------------------
#define QK_SLICE (C_ / 16)   // 96
__global__ __launch_bounds__(256) void k_q(const float* __restrict__ x,
                                           const float* __restrict__ Wq) {
    __shared__ float xs[R_ * QK_SLICE];
    int b = blockIdx.y, kc = blockIdx.z, t = threadIdx.x;
    int k0 = kc * QK_SLICE;
    if (t < R_ * QK_SLICE / 4) {
        int r = t / (QK_SLICE / 4), c4 = t % (QK_SLICE / 4);
        ((float4*)xs)[t] = *(const float4*)(x + ((size_t)(b * N_ + r)) * C_ + k0 + c4 * 4);
    }
    __syncthreads();
    int cp = blockIdx.x * 256 + t;
    const float4* wr = (const float4*)(Wq + (size_t)cp * C_ + k0);
    float acc[R_] = {};
    #pragma unroll 4
    for (int k4 = 0; k4 < QK_SLICE / 4; k4++) {
        float4 w = wr[k4];
        #pragma unroll
        for (int r = 0; r < R_; r++) {
            float4 a = ((const float4*)(xs + r * QK_SLICE))[k4];
            acc[r] += a.x * w.x + a.y * w.y + a.z * w.z + a.w * w.w;
        }
    }
    #pragma unroll
    for (int r = 0; r < R_; r++)
        atomicAdd(&g_Q[(b * R_ + r) * C_ + cp], acc[r] * SCALE_);
}

// ---------------------------------------------------------------------------
// k_qk: QK16[b, h*8+r, c] = sum_d Q[b,r,h*64+d] * Wk[h*64+d, c]
// grid (12 c-tiles, 24 h, 4 br-quarters) = 1152 blocks, 128 threads.
// ---------------------------------------------------------------------------
__global__ __launch_bounds__(128) void k_qk(const float* __restrict__ Wk) {
    __shared__ float Qs[16][64];
    int h = blockIdx.y, qt = blockIdx.z, t = threadIdx.x;
    for (int i = t; i < 16 * 64; i += 128) {
        int brl = i >> 6, d = i & 63;
        Qs[brl][d] = g_Q[(qt * 16 + brl) * C_ + h * 64 + d];
    }
    __syncthreads();
    int c = blockIdx.x * 128 + t;
    float acc[16] = {};
    #pragma unroll 4
    for (int d = 0; d < 64; d++) {
        float w = Wk[(size_t)(h * 64 + d) * C_ + c];
        #pragma unroll
        for (int brl = 0; brl < 16; brl++) acc[brl] += Qs[brl][d] * w;
    }
    #pragma unroll
    for (int brl = 0; brl < 16; brl++) {
        int br = qt * 16 + brl;
        int b = br >> 3, r = br & 7;
        g_QK16[((size_t)(b * M_ + h * 8 + r)) * C_ + c] = __float2half_rn(acc[brl]);
    }
}

// ---------------------------------------------------------------------------
// k_scores: S = QK16 . x16^T   fp16 mma, BM=64, BN=128, BK=64, 3-stage
// 256 threads: 8 warps (2m x 4n), warp 32x32. 2 CTAs/SM target.
// grid (32 n-tiles, 3 m-tiles, 8). Stage: A 64x72 (9216B) + B 128x72 (18432B).
// ---------------------------------------------------------------------------
#define SC_STAGE 27648
#define SC_BOFF  9216
__global__ __launch_bounds__(256, 2) void k_scores() {
    extern __shared__ char smem[];
    uint32_t sb = (uint32_t)__cvta_generic_to_shared(smem);
    int b = blockIdx.z, mt = blockIdx.y, nt = blockIdx.x;
    int tid = threadIdx.x, lane = tid & 31, warp = tid >> 5;
    int g = lane >> 2, q = lane & 3;
    int m0 = (warp >> 2) * 32, n0 = (warp & 3) * 32;

    const __half* Ab = g_QK16 + ((size_t)(b * M_ + mt * 64)) * C_;
    const __half* Bb = g_x16 + ((size_t)(b * N_ + nt * 128)) * C_;

    float acc[2][4][4] = {};

    #define SC_LOAD(st, itv)                                                     \
        do {                                                                     \
            uint32_t a0 = sb + (st) * SC_STAGE;                                  \
            uint32_t b0 = a0 + SC_BOFF;                                          \
            int kb = (itv) * 64;                                                 \
            for (int i = tid; i < 1536; i += 256) {                              \
                if (i < 512) {                                                   \
                    int row = i >> 3, ch = i & 7;                                \
                    CPA(a0 + (row * 72 + ch * 8) * 2,                            \
                        Ab + (size_t)row * C_ + kb + ch * 8);                    \
                } else {                                                         \
                    int j = i - 512;                                             \
                    int row = j >> 3, ch = j & 7;                                \
                    CPA(b0 + (row * 72 + ch * 8) * 2,                            \
                        Bb + (size_t)row * C_ + kb + ch * 8);                    \
                }                                                                \
            }                                                                    \
            CPCOMMIT();                                                          \
        } while (0)

    const int NK = C_ / 64;  // 24
    SC_LOAD(0, 0); SC_LOAD(1, 1); SC_LOAD(2, 2);

    for (int it = 0; it < NK; ++it) {
        int s = it % 3;
        int pend = NK - 1 - it;
        if (pend >= 2)      CPWAIT2();
        else if (pend == 1) CPWAIT1();
        else                CPWAIT0();
        __syncthreads();

        uint32_t aB = sb + s * SC_STAGE;
        uint32_t bB = aB + SC_BOFF;
        #pragma unroll
        for (int ks = 0; ks < 64; ks += 16) {
            uint32_t a[2][4];
            #pragma unroll
            for (int mi = 0; mi < 2; mi++) {
                uint32_t ad = aB + ((m0 + mi * 16 + (lane & 7) + ((lane >> 3) & 1) * 8) * 72
                                    + ks + (lane >> 4) * 8) * 2;
                LDSM4(a[mi][0], a[mi][1], a[mi][2], a[mi][3], ad);
            }
            uint32_t bf[2][4];
            #pragma unroll
            for (int bi = 0; bi < 2; bi++) {
                uint32_t bd = bB + ((n0 + bi * 16 + (lane & 7) + ((lane >> 4) & 1) * 8) * 72
                                    + ks + ((lane >> 3) & 1) * 8) * 2;
                LDSM4(bf[bi][0], bf[bi][1], bf[bi][2], bf[bi][3], bd);
            }
            #pragma unroll
            for (int mi = 0; mi < 2; mi++)
                #pragma unroll
                for (int ni = 0; ni < 4; ni++)
                    mma16(acc[mi][ni], a[mi], &bf[ni >> 1][(ni & 1) * 2]);
        }
        __syncthreads();
        int nx = it + 3;
        if (nx < NK) SC_LOAD(s, nx);
    }
    #undef SC_LOAD

    float* Cb = g_S + ((size_t)(b * M_ + mt * 64)) * N_ + (size_t)nt * 128;
    #pragma unroll
    for (int mi = 0; mi < 2; mi++)
        #pragma unroll
        for (int ni = 0; ni < 4; ni++) {
            int row = m0 + mi * 16 + g;
            int col = n0 + ni * 8 + q * 2;
            *(float2*)(Cb + (size_t)row * N_ + col)       = make_float2(acc[mi][ni][0], acc[mi][ni][1]);
            *(float2*)(Cb + (size_t)(row + 8) * N_ + col) = make_float2(acc[mi][ni][2], acc[mi][ni][3]);
        }
}

// ---------------------------------------------------------------------------
// k_softmax: masked softmax; reads g_S f32, writes g_P16 fp16
// ---------------------------------------------------------------------------
__global__ __launch_bounds__(256) void k_softmax(const int* __restrict__ mask) {
    int row = blockIdx.x;
    int b = row / M_, m = row % M_, r = m & 7;
    const float* S = g_S + (size_t)row * N_;
    __half* P = g_P16 + (size_t)row * N_;
    const int* mrow = mask + ((size_t)(b * R_ + r)) * (N_ - R_);
    int tid = threadIdx.x;

    float vals[16];
    float mx = -1e30f;
    #pragma unroll
    for (int i = 0; i < 16; i++) {
        int n = i * 256 + tid;
        float s = S[n];
        bool valid = (n < R_) ? (n == r) : (mrow[n - R_] != 0);
        s = valid ? s : -1e30f;
        vals[i] = s;
        mx = fmaxf(mx, s);
    }
    __shared__ float smx[8], ssm[8];
    float wmx = warpMax(mx);
    if ((tid & 31) == 0) smx[tid >> 5] = wmx;
    __syncthreads();
    float bm = smx[0];
    #pragma unroll
    for (int j = 1; j < 8; j++) bm = fmaxf(bm, smx[j]);

    float sum = 0.f;
    #pragma unroll
    for (int i = 0; i < 16; i++) {
        vals[i] = expf(vals[i] - bm);
        sum += vals[i];
    }
    float wsm = warpSum(sum);
    if ((tid & 31) == 0) ssm[tid >> 5] = wsm;
    __syncthreads();
    float tot = 0.f;
    #pragma unroll
    for (int j = 0; j < 8; j++) tot += ssm[j];
    float inv = 1.0f / tot;
    #pragma unroll
    for (int i = 0; i < 16; i++) P[i * 256 + tid] = __float2half_rn(vals[i] * inv);
}

// ---------------------------------------------------------------------------
// k_ax: AX[m,c] += sum_{n in split} P16[m,n] * x16[n,c]   (split-K x4)
// BM=64, BN=128 (c), BK=64 (tokens), 3-stage. 256 threads (2m x 4n).
// grid (12 c-tiles, 3 m-tiles * 4 splits, 8). Stage: A 9216B + B 64x136 (17408B).
// ---------------------------------------------------------------------------
#define AX_STAGE 26624
#define AX_BOFF  9216
#define AX_SPLIT 4
__global__ __launch_bounds__(256, 2) void k_ax() {
    extern __shared__ char smem[];
    uint32_t sb = (uint32_t)__cvta_generic_to_shared(smem);
    int b = blockIdx.z, nt = blockIdx.x;
    int mt = blockIdx.y >> 2, kc = blockIdx.y & 3;
    int tid = threadIdx.x, lane = tid & 31, warp = tid >> 5;
    int g = lane >> 2, q = lane & 3;
    int m0 = (warp >> 2) * 32, n0 = (warp & 3) * 32;

    const int K0 = kc * (N_ / AX_SPLIT);
    const __half* Ab = g_P16 + ((size_t)(b * M_ + mt * 64)) * N_ + K0;
    const __half* Bx = g_x16 + (size_t)b * N_ * C_ + (size_t)K0 * C_ + nt * 128;

    float acc[2][4][4] = {};

    #define AX_LOAD(st, itv)                                                     \
        do {                                                                     \
            uint32_t a0 = sb + (st) * AX_STAGE;                                  \
            uint32_t b0 = a0 + AX_BOFF;                                          \
            int kb = (itv) * 64;                                                 \
            for (int i = tid; i < 1536; i += 256) {                              \
                if (i < 512) {                                                   \
                    int row = i >> 3, ch = i & 7;                                \
                    CPA(a0 + (row * 72 + ch * 8) * 2,                            \
                        Ab + (size_t)row * N_ + kb + ch * 8);                    \
                } else {                                                         \
                    int j = i - 512;                                             \
                    int row = j >> 4, ch = j & 15;                               \
                    CPA(b0 + (row * 136 + ch * 8) * 2,                           \
                        Bx + (size_t)(kb + row) * C_ + ch * 8);                  \
                }                                                                \
            }                                                                    \
            CPCOMMIT();                                                          \
        } while (0)

    const int NK = (N_ / AX_SPLIT) / 64;  // 16
    AX_LOAD(0, 0); AX_LOAD(1, 1); AX_LOAD(2, 2);

    for (int it = 0; it < NK; ++it) {
        int s = it % 3;
        int pend = NK - 1 - it;
        if (pend >= 2)      CPWAIT2();
        else if (pend == 1) CPWAIT1();
        else                CPWAIT0();
        __syncthreads();

        uint32_t aB = sb + s * AX_STAGE;
        uint32_t bB = aB + AX_BOFF;
        #pragma unroll
        for (int ks = 0; ks < 64; ks += 16) {
            uint32_t a[2][4];
            #pragma unroll
            for (int mi = 0; mi < 2; mi++) {
                uint32_t ad = aB + ((m0 + mi * 16 + (lane & 7) + ((lane >> 3) & 1) * 8) * 72
                                    + ks + (lane >> 4) * 8) * 2;
                LDSM4(a[mi][0], a[mi][1], a[mi][2], a[mi][3], ad);
            }
            uint32_t bf[2][4];
            #pragma unroll
            for (int bi = 0; bi < 2; bi++) {
                uint32_t bd = bB + ((ks + (lane & 7) + ((lane >> 3) & 1) * 8) * 136
                                    + n0 + bi * 16 + ((lane >> 4) & 1) * 8) * 2;
                LDSM4T(bf[bi][0], bf[bi][1], bf[bi][2], bf[bi][3], bd);
            }
            #pragma unroll
            for (int mi = 0; mi < 2; mi++)
                #pragma unroll
                for (int ni = 0; ni < 4; ni++)
                    mma16(acc[mi][ni], a[mi], &bf[ni >> 1][(ni & 1) * 2]);
        }
        __syncthreads();
        int nx = it + 3;
        if (nx < NK) AX_LOAD(s, nx);
    }
    #undef AX_LOAD

    float* Cb = g_AX + ((size_t)(b * M_ + mt * 64)) * C_ + nt * 128;
    #pragma unroll
    for (int mi = 0; mi < 2; mi++)
        #pragma unroll
        for (int ni = 0; ni < 4; ni++) {
            int row = m0 + mi * 16 + g;
            int col = n0 + ni * 8 + q * 2;
            float* p0 = Cb + (size_t)row * C_ + col;
            float* p1 = Cb + (size_t)(row + 8) * C_ + col;
            atomicAdd(p0,     acc[mi][ni][0]);
            atomicAdd(p0 + 1, acc[mi][ni][1]);
            atomicAdd(p1,     acc[mi][ni][2]);
            atomicAdd(p1 + 1, acc[mi][ni][3]);
        }
}

// ---------------------------------------------------------------------------
// k_d1: XCLS[b,r,cc] += sum_{c in slice} AX[b, (cc/64)*8+r, c] * Wv[cc, c]
// K-split x16: grid (6, 8, 16). atomicAdd into zeroed g_XCLS.
// ---------------------------------------------------------------------------
__global__ __launch_bounds__(256) void k_d1(const float* __restrict__ Wv) {
    int b = blockIdx.y, kc = blockIdx.z, t = threadIdx.x;
    int k0 = kc * QK_SLICE;
    int cc = blockIdx.x * 256 + t;
    int h = cc >> 6;
    const float4* wr = (const float4*)(Wv + (size_t)cc * C_ + k0);
    const float4* ax[R_];
    #pragma unroll
    for (int r = 0; r < R_; r++)
        ax[r] = (const float4*)(g_AX + ((size_t)b * M_ + h * 8 + r) * C_ + k0);
    float acc[R_] = {};
    #pragma unroll 4
    for (int k4 = 0; k4 < QK_SLICE / 4; k4++) {
        float4 w = wr[k4];
        #pragma unroll
        for (int r = 0; r < R_; r++) {
            float4 a = ax[r][k4];
            acc[r] += a.x * w.x + a.y * w.y + a.z * w.z + a.w * w.w;
        }
    }
    #pragma unroll
    for (int r = 0; r < R_; r++)
        atomicAdd(&g_XCLS[(b * R_ + r) * C_ + cc], acc[r]);
}

// ---------------------------------------------------------------------------
// k_d2: out[b,r,c'] += sum_{cc in slice} XCLS[b,r,cc] * Wp[c',cc]  (+bias on kc0)
// K-split x16: grid (6, 8, 16). atomicAdd into zeroed out.
// ---------------------------------------------------------------------------
__global__ __launch_bounds__(256) void k_d2(const float* __restrict__ Wp,
                                            const float* __restrict__ bp,
                                            float* __restrict__ out) {
    int b = blockIdx.y, kc = blockIdx.z, t = threadIdx.x;
    int k0 = kc * QK_SLICE;
    int cp = blockIdx.x * 256 + t;
    const float4* wr = (const float4*)(Wp + (size_t)cp * C_ + k0);
    const float4* xc[R_];
    #pragma unroll
    for (int r = 0; r < R_; r++)
        xc[r] = (const float4*)(g_XCLS + (size_t)(b * R_ + r) * C_ + k0);
    float acc[R_] = {};
    #pragma unroll 4
    for (int k4 = 0; k4 < QK_SLICE / 4; k4++) {
        float4 w = wr[k4];
        #pragma unroll
        for (int r = 0; r < R_; r++) {
            float4 a = xc[r][k4];
            acc[r] += a.x * w.x + a.y * w.y + a.z * w.z + a.w * w.w;
        }
    }
    float bias = (kc == 0) ? bp[cp] : 0.f;
    #pragma unroll
    for (int r = 0; r < R_; r++)
        atomicAdd(&out[((size_t)(b * R_ + r)) * C_ + cp], acc[r] + bias);
}

// ---------------------------------------------------------------------------
// launch
// ---------------------------------------------------------------------------
extern "C" void kernel_launch(void* const* d_in, const int* in_sizes, int n_in,
                              void* d_out, int out_size) {
    const float* x    = (const float*)d_in[0];
    const int*   mask = (const int*)d_in[1];
    const float* Wq   = (const float*)d_in[2];
    const float* Wk   = (const float*)d_in[3];
    const float* Wv   = (const float*)d_in[4];
    const float* Wp   = (const float*)d_in[5];
    const float* bp   = (const float*)d_in[6];
    float* out = (float*)d_out;

    const int SC_SMEM = 3 * SC_STAGE;  // 82944
    const int AX_SMEM = 3 * AX_STAGE;  // 79872
    cudaFuncSetAttribute(k_scores, cudaFuncAttributeMaxDynamicSharedMemorySize, SC_SMEM);
    cudaFuncSetAttribute(k_ax,     cudaFuncAttributeMaxDynamicSharedMemorySize, AX_SMEM);

    k_zero   <<<1024, 256>>>(out);
    k_conv   <<<4096, 256>>>(x);
    k_q      <<<dim3(C_ / 256, B_, 16), 256>>>(x, Wq);
    k_qk     <<<dim3(C_ / 128, H_, 4), 128>>>(Wk);
    k_scores <<<dim3(N_ / 128, M_ / 64, B_), 256, SC_SMEM>>>();
    k_softmax<<<B_ * M_, 256>>>(mask);
    k_ax     <<<dim3(C_ / 128, (M_ / 64) * AX_SPLIT, B_), 256, AX_SMEM>>>();
    k_d1     <<<dim3(C_ / 256, B_, 16), 256>>>(Wv);
    k_d2     <<<dim3(C_ / 256, B_, 16), 256>>>(Wp, bp, out);
}

// round 11
// speedup vs baseline: 3.1717x; 1.0488x over previous
#include <cuda_runtime.h>
#include <cuda_fp16.h>
#include <cstdint>

// Problem constants
#define B_   8
#define N_   4096
#define C_   1536
#define H_   24
#define R_   8
#define M_   192
#define SCALE_ 0.125f

// Scratch (static device globals)
__device__ float    g_Q[B_ * R_ * C_];                 // atomically accumulated
__device__ __half   g_QK16[B_ * M_ * C_];              // q@Wk, fp16
__device__ float    g_S[(size_t)B_ * M_ * N_];         // scores f32
__device__ __half   g_P16[(size_t)B_ * M_ * N_];       // softmax probs fp16
__device__ float    g_AX[B_ * M_ * C_];                // P @ x (split-K accumulated)
__device__ float    g_XCLS[B_ * R_ * C_];              // atomically accumulated
__device__ __half   g_x16[(size_t)B_ * N_ * C_];       // x fp16

// ---------------------------------------------------------------------------
// helpers
// ---------------------------------------------------------------------------
#define CPA(dst, src) asm volatile("cp.async.cg.shared.global [%0], [%1], 16;" :: "r"(dst), "l"(src))
#define CPCOMMIT()    asm volatile("cp.async.commit_group;")
#define CPWAIT0()     asm volatile("cp.async.wait_group 0;")
#define CPWAIT1()     asm volatile("cp.async.wait_group 1;")
#define CPWAIT2()     asm volatile("cp.async.wait_group 2;")

#define LDSM4(r0, r1, r2, r3, addr) \
    asm volatile("ldmatrix.sync.aligned.m8n8.x4.shared.b16 {%0,%1,%2,%3}, [%4];" \
                 : "=r"(r0), "=r"(r1), "=r"(r2), "=r"(r3) : "r"(addr))
#define LDSM4T(r0, r1, r2, r3, addr) \
    asm volatile("ldmatrix.sync.aligned.m8n8.x4.trans.shared.b16 {%0,%1,%2,%3}, [%4];" \
                 : "=r"(r0), "=r"(r1), "=r"(r2), "=r"(r3) : "r"(addr))

__device__ __forceinline__ void mma16(float* c, const uint32_t* a, const uint32_t* b) {
    asm volatile(
        "mma.sync.aligned.m16n8k16.row.col.f32.f16.f16.f32 "
        "{%0,%1,%2,%3}, {%4,%5,%6,%7}, {%8,%9}, {%0,%1,%2,%3};"
        : "+f"(c[0]), "+f"(c[1]), "+f"(c[2]), "+f"(c[3])
        : "r"(a[0]), "r"(a[1]), "r"(a[2]), "r"(a[3]), "r"(b[0]), "r"(b[1]));
}

__device__ __forceinline__ float warpMax(float v) {
    #pragma unroll
    for (int o = 16; o; o >>= 1) v = fmaxf(v, __shfl_xor_sync(0xffffffffu, v, o));
    return v;
}
__device__ __forceinline__ float warpSum(float v) {
    #pragma unroll
    for (int o = 16; o; o >>= 1) v += __shfl_xor_sync(0xffffffffu, v, o);
    return v;
}

// ---------------------------------------------------------------------------
// conv range worker: convert x[f32] -> g_x16 over uint4 indices [lo, hi)
// ---------------------------------------------------------------------------
__device__ __forceinline__ void conv_range(const float* __restrict__ x,
                                           size_t lo, size_t hi,
                                           int rb, int nb, int t) {
    for (size_t i = lo + (size_t)rb * 256 + t; i < hi; i += (size_t)nb * 256) {
        float4 v0 = ((const float4*)x)[i * 2];
        float4 v1 = ((const float4*)x)[i * 2 + 1];
        __half h[8];
        h[0] = __float2half_rn(v0.x); h[1] = __float2half_rn(v0.y);
        h[2] = __float2half_rn(v0.z); h[3] = __float2half_rn(v0.w);
        h[4] = __float2half_rn(v1.x); h[5] = __float2half_rn(v1.y);
        h[6] = __float2half_rn(v1.z); h[7] = __float2half_rn(v1.w);
        ((uint4*)g_x16)[i] = *(uint4*)h;
    }
}

#define CONV_TOTAL ((size_t)B_ * N_ * C_ / 8)   // 6291456 uint4 elements
#define CONV_HALF  (CONV_TOTAL / 2)

// ---------------------------------------------------------------------------
// k_zq: zero g_Q (must precede k_q atomics)
// ---------------------------------------------------------------------------
__global__ __launch_bounds__(256) void k_zq() {
    int i = blockIdx.x * 256 + threadIdx.x;
    ((float4*)g_Q)[i] = make_float4(0.f, 0.f, 0.f, 0.f);
}

// ---------------------------------------------------------------------------
// k_p2: union launch — conv_lo (1280 blocks) | k_q (768 blocks) | zero_rest (64)
// ---------------------------------------------------------------------------
#define P2_CONV 1280
#define P2_Q    768
#define P2_Z    64
#define QK_SLICE (C_ / 16)   // 96
__global__ __launch_bounds__(256) void k_p2(const float* __restrict__ x,
                                            const float* __restrict__ Wq,
                                            float* __restrict__ out) {
    int bid = blockIdx.x, t = threadIdx.x;
    if (bid < P2_CONV) {
        conv_range(x, 0, CONV_HALF, bid, P2_CONV, t);
        return;
    }
    bid -= P2_CONV;
    if (bid < P2_Q) {
        // k_q: Q[b,r,cp] += SCALE * sum_{slice} x[b,r,:]*Wq[cp,:]
        __shared__ float xs[R_ * QK_SLICE];
        int cpt = bid % 6, b = (bid / 6) % 8, kc = bid / 48;
        int k0 = kc * QK_SLICE;
        if (t < R_ * QK_SLICE / 4) {
            int r = t / (QK_SLICE / 4), c4 = t % (QK_SLICE / 4);
            ((float4*)xs)[t] = *(const float4*)(x + ((size_t)(b * N_ + r)) * C_ + k0 + c4 * 4);
        }
        __syncthreads();
        int cp = cpt * 256 + t;
        const float4* wr = (const float4*)(Wq + (size_t)cp * C_ + k0);
        float acc[R_] = {};
        #pragma unroll 4
        for (int k4 = 0; k4 < QK_SLICE / 4; k4++) {
            float4 w = wr[k4];
            #pragma unroll
            for (int r = 0; r < R_; r++) {
                float4 a = ((const float4*)(xs + r * QK_SLICE))[k4];
                acc[r] += a.x * w.x + a.y * w.y + a.z * w.z + a.w * w.w;
            }
        }
        #pragma unroll
        for (int r = 0; r < R_; r++)
            atomicAdd(&g_Q[(b * R_ + r) * C_ + cp], acc[r] * SCALE_);
        return;
    }
    bid -= P2_Q;
    // zero_rest: g_AX, g_XCLS, out
    const float4 z = make_float4(0.f, 0.f, 0.f, 0.f);
    size_t stride = (size_t)P2_Z * 256;
    size_t t0 = (size_t)bid * 256 + t;
    for (size_t i = t0; i < (size_t)B_ * M_ * C_ / 4; i += stride) ((float4*)g_AX)[i] = z;
    for (size_t i = t0; i < (size_t)B_ * R_ * C_ / 4; i += stride) {
        ((float4*)g_XCLS)[i] = z;
        ((float4*)out)[i] = z;
    }
}

// ---------------------------------------------------------------------------
// k_p3: union launch — conv_hi (1280 blocks) | k_qk (576 blocks, 256 thr)
// ---------------------------------------------------------------------------
#define P3_CONV 1280
__global__ __launch_bounds__(256) void k_p3(const float* __restrict__ x,
                                            const float* __restrict__ Wk) {
    int bid = blockIdx.x, t = threadIdx.x;
    if (bid < P3_CONV) {
        conv_range(x, CONV_HALF, CONV_TOTAL, bid, P3_CONV, t);
        return;
    }
    bid -= P3_CONV;
    // k_qk: QK16[b, h*8+r, c] = sum_d Q[b,r,h*64+d] * Wk[h*64+d, c]
    // 576 blocks: cx (6 tiles of 256) x h (24) x qt (4 groups of 16 br-rows)
    __shared__ float Qs[16][64];
    int cx = bid % 6, h = (bid / 6) % 24, qt = bid / 144;
    for (int i = t; i < 16 * 64; i += 256) {
        int brl = i >> 6, d = i & 63;
        Qs[brl][d] = g_Q[(qt * 16 + brl) * C_ + h * 64 + d];
    }
    __syncthreads();
    int c = cx * 256 + t;
    float acc[16] = {};
    #pragma unroll 4
    for (int d = 0; d < 64; d++) {
        float w = Wk[(size_t)(h * 64 + d) * C_ + c];
        #pragma unroll
        for (int brl = 0; brl < 16; brl++) acc[brl] += Qs[brl][d] * w;
    }
    #pragma unroll
    for (int brl = 0; brl < 16; brl++) {
        int br = qt * 16 + brl;
        int b = br >> 3, r = br & 7;
        g_QK16[((size_t)(b * M_ + h * 8 + r)) * C_ + c] = __float2half_rn(acc[brl]);
    }
}

// ---------------------------------------------------------------------------
// k_scores: S = QK16 . x16^T   fp16 mma, BM=64, BN=128, BK=64, 4-stage
// 256 threads: 8 warps (2m x 4n), warp 32x32. 2 CTAs/SM.
// grid (32 n-tiles, 3 m-tiles, 8). One __syncthreads per K-iter.
// ---------------------------------------------------------------------------
#define SC_STAGE 27648
#define SC_BOFF  9216
__global__ __launch_bounds__(256, 2) void k_scores() {
    extern __shared__ char smem[];
    uint32_t sb = (uint32_t)__cvta_generic_to_shared(smem);
    int b = blockIdx.z, mt = blockIdx.y, nt = blockIdx.x;
    int tid = threadIdx.x, lane = tid & 31, warp = tid >> 5;
    int g = lane >> 2, q = lane & 3;
    int m0 = (warp >> 2) * 32, n0 = (warp & 3) * 32;

    const __half* Ab = g_QK16 + ((size_t)(b * M_ + mt * 64)) * C_;
    const __half* Bb = g_x16 + ((size_t)(b * N_ + nt * 128)) * C_;

    float acc[2][4][4] = {};

    #define SC_LOAD(st, itv)                                                     \
        do {                                                                     \
            uint32_t a0 = sb + (st) * SC_STAGE;                                  \
            uint32_t b0 = a0 + SC_BOFF;                                          \
            int kb = (itv) * 64;                                                 \
            for (int i = tid; i < 1536; i += 256) {                              \
                if (i < 512) {                                                   \
                    int row = i >> 3, ch = i & 7;                                \
                    CPA(a0 + (row * 72 + ch * 8) * 2,                            \
                        Ab + (size_t)row * C_ + kb + ch * 8);                    \
                } else {                                                         \
                    int j = i - 512;                                             \
                    int row = j >> 3, ch = j & 7;                                \
                    CPA(b0 + (row * 72 + ch * 8) * 2,                            \
                        Bb + (size_t)row * C_ + kb + ch * 8);                    \
                }                                                                \
            }                                                                    \
            CPCOMMIT();                                                          \
        } while (0)

    const int NK = C_ / 64;  // 24
    SC_LOAD(0, 0); SC_LOAD(1, 1); SC_LOAD(2, 2);

    for (int it = 0; it < NK; ++it) {
        int s = it & 3;
        int pend = NK - 1 - it;
        if (pend >= 2)      CPWAIT2();
        else if (pend == 1) CPWAIT1();
        else                CPWAIT0();
        __syncthreads();

        uint32_t aB = sb + s * SC_STAGE;
        uint32_t bB = aB + SC_BOFF;
        #pragma unroll
        for (int ks = 0; ks < 64; ks += 16) {
            uint32_t a[2][4];
            #pragma unroll
            for (int mi = 0; mi < 2; mi++) {
                uint32_t ad = aB + ((m0 + mi * 16 + (lane & 7) + ((lane >> 3) & 1) * 8) * 72
                                    + ks + (lane >> 4) * 8) * 2;
                LDSM4(a[mi][0], a[mi][1], a[mi][2], a[mi][3], ad);
            }
            uint32_t bf[2][4];
            #pragma unroll
            for (int bi = 0; bi < 2; bi++) {
                uint32_t bd = bB + ((n0 + bi * 16 + (lane & 7) + ((lane >> 4) & 1) * 8) * 72
                                    + ks + ((lane >> 3) & 1) * 8) * 2;
                LDSM4(bf[bi][0], bf[bi][1], bf[bi][2], bf[bi][3], bd);
            }
            #pragma unroll
            for (int mi = 0; mi < 2; mi++)
                #pragma unroll
                for (int ni = 0; ni < 4; ni++)
                    mma16(acc[mi][ni], a[mi], &bf[ni >> 1][(ni & 1) * 2]);
        }
        int nx = it + 3;
        if (nx < NK) SC_LOAD(nx & 3, nx);
    }
    #undef SC_LOAD

    float* Cb = g_S + ((size_t)(b * M_ + mt * 64)) * N_ + (size_t)nt * 128;
    #pragma unroll
    for (int mi = 0; mi < 2; mi++)
        #pragma unroll
        for (int ni = 0; ni < 4; ni++) {
            int row = m0 + mi * 16 + g;
            int col = n0 + ni * 8 + q * 2;
            *(float2*)(Cb + (size_t)row * N_ + col)       = make_float2(acc[mi][ni][0], acc[mi][ni][1]);
            *(float2*)(Cb + (size_t)(row + 8) * N_ + col) = make_float2(acc[mi][ni][2], acc[mi][ni][3]);
        }
}

// ---------------------------------------------------------------------------
// k_softmax: masked softmax; reads g_S f32, writes g_P16 fp16
// ---------------------------------------------------------------------------
__global__ __launch_bounds__(256) void k_softmax(const int* __restrict__ mask) {
    int row = blockIdx.x;
    int b = row / M_, m = row % M_, r = m & 7;
    const float* S = g_S + (size_t)row * N_;
    __half* P = g_P16 + (size_t)row * N_;
    const int* mrow = mask + ((size_t)(b * R_ + r)) * (N_ - R_);
    int tid = threadIdx.x;

    float vals[16];
    float mx = -1e30f;
    #pragma unroll
    for (int i = 0; i < 16; i++) {
        int n = i * 256 + tid;
        float s = S[n];
        bool valid = (n < R_) ? (n == r) : (mrow[n - R_] != 0);
        s = valid ? s : -1e30f;
        vals[i] = s;
        mx = fmaxf(mx, s);
    }
    __shared__ float smx[8], ssm[8];
    float wmx = warpMax(mx);
    if ((tid & 31) == 0) smx[tid >> 5] = wmx;
    __syncthreads();
    float bm = smx[0];
    #pragma unroll
    for (int j = 1; j < 8; j++) bm = fmaxf(bm, smx[j]);

    float sum = 0.f;
    #pragma unroll
    for (int i = 0; i < 16; i++) {
        vals[i] = expf(vals[i] - bm);
        sum += vals[i];
    }
    float wsm = warpSum(sum);
    if ((tid & 31) == 0) ssm[tid >> 5] = wsm;
    __syncthreads();
    float tot = 0.f;
    #pragma unroll
    for (int j = 0; j < 8; j++) tot += ssm[j];
    float inv = 1.0f / tot;
    #pragma unroll
    for (int i = 0; i < 16; i++) P[i * 256 + tid] = __float2half_rn(vals[i] * inv);
}

// ---------------------------------------------------------------------------
// k_ax: AX[m,c] += sum_{n in split} P16[m,n] * x16[n,c]   (split-K x4)
// BM=64, BN=128 (c), BK=64 (tokens), 4-stage. 256 threads (2m x 4n).
// grid (12 c-tiles, 3 m-tiles * 4 splits, 8). One __syncthreads per K-iter.
// ---------------------------------------------------------------------------
#define AX_STAGE 26624
#define AX_BOFF  9216
#define AX_SPLIT 4
__global__ __launch_bounds__(256, 2) void k_ax() {
    extern __shared__ char smem[];
    uint32_t sb = (uint32_t)__cvta_generic_to_shared(smem);
    int b = blockIdx.z, nt = blockIdx.x;
    int mt = blockIdx.y >> 2, kc = blockIdx.y & 3;
    int tid = threadIdx.x, lane = tid & 31, warp = tid >> 5;
    int g = lane >> 2, q = lane & 3;
    int m0 = (warp >> 2) * 32, n0 = (warp & 3) * 32;

    const int K0 = kc * (N_ / AX_SPLIT);
    const __half* Ab = g_P16 + ((size_t)(b * M_ + mt * 64)) * N_ + K0;
    const __half* Bx = g_x16 + (size_t)b * N_ * C_ + (size_t)K0 * C_ + nt * 128;

    float acc[2][4][4] = {};

    #define AX_LOAD(st, itv)                                                     \
        do {                                                                     \
            uint32_t a0 = sb + (st) * AX_STAGE;                                  \
            uint32_t b0 = a0 + AX_BOFF;                                          \
            int kb = (itv) * 64;                                                 \
            for (int i = tid; i < 1536; i += 256) {                              \
                if (i < 512) {                                                   \
                    int row = i >> 3, ch = i & 7;                                \
                    CPA(a0 + (row * 72 + ch * 8) * 2,                            \
                        Ab + (size_t)row * N_ + kb + ch * 8);                    \
                } else {                                                         \
                    int j = i - 512;                                             \
                    int row = j >> 4, ch = j & 15;                               \
                    CPA(b0 + (row * 136 + ch * 8) * 2,                           \
                        Bx + (size_t)(kb + row) * C_ + ch * 8);                  \
                }                                                                \
            }                                                                    \
            CPCOMMIT();                                                          \
        } while (0)

    const int NK = (N_ / AX_SPLIT) / 64;  // 16
    AX_LOAD(0, 0); AX_LOAD(1, 1); AX_LOAD(2, 2);

    for (int it = 0; it < NK; ++it) {
        int s = it & 3;
        int pend = NK - 1 - it;
        if (pend >= 2)      CPWAIT2();
        else if (pend == 1) CPWAIT1();
        else                CPWAIT0();
        __syncthreads();

        uint32_t aB = sb + s * AX_STAGE;
        uint32_t bB = aB + AX_BOFF;
        #pragma unroll
        for (int ks = 0; ks < 64; ks += 16) {
            uint32_t a[2][4];
            #pragma unroll
            for (int mi = 0; mi < 2; mi++) {
                uint32_t ad = aB + ((m0 + mi * 16 + (lane & 7) + ((lane >> 3) & 1) * 8) * 72
                                    + ks + (lane >> 4) * 8) * 2;
                LDSM4(a[mi][0], a[mi][1], a[mi][2], a[mi][3], ad);
            }
            uint32_t bf[2][4];
            #pragma unroll
            for (int bi = 0; bi < 2; bi++) {
                uint32_t bd = bB + ((ks + (lane & 7) + ((lane >> 3) & 1) * 8) * 136
                                    + n0 + bi * 16 + ((lane >> 4) & 1) * 8) * 2;
                LDSM4T(bf[bi][0], bf[bi][1], bf[bi][2], bf[bi][3], bd);
            }
            #pragma unroll
            for (int mi = 0; mi < 2; mi++)
                #pragma unroll
                for (int ni = 0; ni < 4; ni++)
                    mma16(acc[mi][ni], a[mi], &bf[ni >> 1][(ni & 1) * 2]);
        }
        int nx = it + 3;
        if (nx < NK) AX_LOAD(nx & 3, nx);
    }
    #undef AX_LOAD

    float* Cb = g_AX + ((size_t)(b * M_ + mt * 64)) * C_ + nt * 128;
    #pragma unroll
    for (int mi = 0; mi < 2; mi++)
        #pragma unroll
        for (int ni = 0; ni < 4; ni++) {
            int row = m0 + mi * 16 + g;
            int col = n0 + ni * 8 + q * 2;
            float* p0 = Cb + (size_t)row * C_ + col;
            float* p1 = Cb + (size_t)(row + 8) * C_ + col;
            atomicAdd(p0,     acc[mi][ni][0]);
            atomicAdd(p0 + 1, acc[mi][ni][1]);
            atomicAdd(p1,     acc[mi][ni][2]);
            atomicAdd(p1 + 1, acc[mi][ni][3]);
        }
}

// ---------------------------------------------------------------------------
// k_d1: XCLS[b,r,cc] += sum_{c in slice} AX[b, (cc/64)*8+r, c] * Wv[cc, c]
// K-split x16: grid (6, 8, 16). atomicAdd into zeroed g_XCLS.
// ---------------------------------------------------------------------------
__global__ __launch_bounds__(256) void k_d1(const float* __restrict__ Wv) {
    int b = blockIdx.y, kc = blockIdx.z, t = threadIdx.x;
    int k0 = kc * QK_SLICE;
    int cc = blockIdx.x * 256 + t;
    int h = cc >> 6;
    const float4* wr = (const float4*)(Wv + (size_t)cc * C_ + k0);
    const float4* ax[R_];
    #pragma unroll
    for (int r = 0; r < R_; r++)
        ax[r] = (const float4*)(g_AX + ((size_t)b * M_ + h * 8 + r) * C_ + k0);
    float acc[R_] = {};
    #pragma unroll 4
    for (int k4 = 0; k4 < QK_SLICE / 4; k4++) {
        float4 w = wr[k4];
        #pragma unroll
        for (int r = 0; r < R_; r++) {
            float4 a = ax[r][k4];
            acc[r] += a.x * w.x + a.y * w.y + a.z * w.z + a.w * w.w;
        }
    }
    #pragma unroll
    for (int r = 0; r < R_; r++)
        atomicAdd(&g_XCLS[(b * R_ + r) * C_ + cc], acc[r]);
}

// ---------------------------------------------------------------------------
// k_d2: out[b,r,c'] += sum_{cc in slice} XCLS[b,r,cc] * Wp[c',cc]  (+bias on kc0)
// K-split x16: grid (6, 8, 16). atomicAdd into zeroed out.
// ---------------------------------------------------------------------------
__global__ __launch_bounds__(256) void k_d2(const float* __restrict__ Wp,
                                            const float* __restrict__ bp,
                                            float* __restrict__ out) {
    int b = blockIdx.y, kc = blockIdx.z, t = threadIdx.x;
    int k0 = kc * QK_SLICE;
    int cp = blockIdx.x * 256 + t;
    const float4* wr = (const float4*)(Wp + (size_t)cp * C_ + k0);
    const float4* xc[R_];
    #pragma unroll
    for (int r = 0; r < R_; r++)
        xc[r] = (const float4*)(g_XCLS + (size_t)(b * R_ + r) * C_ + k0);
    float acc[R_] = {};
    #pragma unroll 4
    for (int k4 = 0; k4 < QK_SLICE / 4; k4++) {
        float4 w = wr[k4];
        #pragma unroll
        for (int r = 0; r < R_; r++) {
            float4 a = xc[r][k4];
            acc[r] += a.x * w.x + a.y * w.y + a.z * w.z + a.w * w.w;
        }
    }
    float bias = (kc == 0) ? bp[cp] : 0.f;
    #pragma unroll
    for (int r = 0; r < R_; r++)
        atomicAdd(&out[((size_t)(b * R_ + r)) * C_ + cp], acc[r] + bias);
}

// ---------------------------------------------------------------------------
// launch
// ---------------------------------------------------------------------------
extern "C" void kernel_launch(void* const* d_in, const int* in_sizes, int n_in,
                              void* d_out, int out_size) {
    const float* x    = (const float*)d_in[0];
    const int*   mask = (const int*)d_in[1];
    const float* Wq   = (const float*)d_in[2];
    const float* Wk   = (const float*)d_in[3];
    const float* Wv   = (const float*)d_in[4];
    const float* Wp   = (const float*)d_in[5];
    const float* bp   = (const float*)d_in[6];
    float* out = (float*)d_out;

    const int SC_SMEM = 4 * SC_STAGE;  // 110592
    const int AX_SMEM = 4 * AX_STAGE;  // 106496
    cudaFuncSetAttribute(k_scores, cudaFuncAttributeMaxDynamicSharedMemorySize, SC_SMEM);
    cudaFuncSetAttribute(k_ax,     cudaFuncAttributeMaxDynamicSharedMemorySize, AX_SMEM);

    k_zq     <<<96, 256>>>();
    k_p2     <<<P2_CONV + P2_Q + P2_Z, 256>>>(x, Wq, out);
    k_p3     <<<P3_CONV + 576, 256>>>(x, Wk);
    k_scores <<<dim3(N_ / 128, M_ / 64, B_), 256, SC_SMEM>>>();
    k_softmax<<<B_ * M_, 256>>>(mask);
    k_ax     <<<dim3(C_ / 128, (M_ / 64) * AX_SPLIT, B_), 256, AX_SMEM>>>();
    k_d1     <<<dim3(C_ / 256, B_, 16), 256>>>(Wv);
    k_d2     <<<dim3(C_ / 256, B_, 16), 256>>>(Wp, bp, out);
}

// round 13
// speedup vs baseline: 3.3346x; 1.0514x over previous
#include <cuda_runtime.h>
#include <cuda_fp16.h>
#include <cstdint>

// Problem constants
#define B_   8
#define N_   4096
#define C_   1536
#define H_   24
#define R_   8
#define M_   192
#define SCALE_ 0.125f

// Scratch (static device globals)
__device__ float    g_Q[B_ * R_ * C_];                 // atomically accumulated
__device__ __half   g_QK16[B_ * M_ * C_];              // q@Wk, fp16
__device__ float    g_S[(size_t)B_ * M_ * N_];         // scores f32
__device__ __half   g_P16[(size_t)B_ * M_ * N_];       // softmax probs fp16
__device__ float    g_AX[B_ * M_ * C_];                // P @ x (split-K accumulated)
__device__ float    g_XCLS[B_ * R_ * C_];              // atomically accumulated
__device__ __half   g_x16[(size_t)B_ * N_ * C_];       // x fp16

// ---------------------------------------------------------------------------
// helpers
// ---------------------------------------------------------------------------
#define CPA(dst, src) asm volatile("cp.async.cg.shared.global [%0], [%1], 16;" :: "r"(dst), "l"(src))
#define CPCOMMIT()    asm volatile("cp.async.commit_group;")
#define CPWAIT0()     asm volatile("cp.async.wait_group 0;")
#define CPWAIT1()     asm volatile("cp.async.wait_group 1;")

#define LDSM4(r0, r1, r2, r3, addr) \
    asm volatile("ldmatrix.sync.aligned.m8n8.x4.shared.b16 {%0,%1,%2,%3}, [%4];" \
                 : "=r"(r0), "=r"(r1), "=r"(r2), "=r"(r3) : "r"(addr))
#define LDSM4T(r0, r1, r2, r3, addr) \
    asm volatile("ldmatrix.sync.aligned.m8n8.x4.trans.shared.b16 {%0,%1,%2,%3}, [%4];" \
                 : "=r"(r0), "=r"(r1), "=r"(r2), "=r"(r3) : "r"(addr))

__device__ __forceinline__ void mma16(float* c, const uint32_t* a, const uint32_t* b) {
    asm volatile(
        "mma.sync.aligned.m16n8k16.row.col.f32.f16.f16.f32 "
        "{%0,%1,%2,%3}, {%4,%5,%6,%7}, {%8,%9}, {%0,%1,%2,%3};"
        : "+f"(c[0]), "+f"(c[1]), "+f"(c[2]), "+f"(c[3])
        : "r"(a[0]), "r"(a[1]), "r"(a[2]), "r"(a[3]), "r"(b[0]), "r"(b[1]));
}

__device__ __forceinline__ float warpMax(float v) {
    #pragma unroll
    for (int o = 16; o; o >>= 1) v = fmaxf(v, __shfl_xor_sync(0xffffffffu, v, o));
    return v;
}
__device__ __forceinline__ float warpSum(float v) {
    #pragma unroll
    for (int o = 16; o; o >>= 1) v += __shfl_xor_sync(0xffffffffu, v, o);
    return v;
}

// ---------------------------------------------------------------------------
// conv range worker: convert x[f32] -> g_x16 over uint4 indices [lo, hi)
// ---------------------------------------------------------------------------
__device__ __forceinline__ void conv_range(const float* __restrict__ x,
                                           size_t lo, size_t hi,
                                           int rb, int nb, int t) {
    for (size_t i = lo + (size_t)rb * 256 + t; i < hi; i += (size_t)nb * 256) {
        float4 v0 = ((const float4*)x)[i * 2];
        float4 v1 = ((const float4*)x)[i * 2 + 1];
        __half h[8];
        h[0] = __float2half_rn(v0.x); h[1] = __float2half_rn(v0.y);
        h[2] = __float2half_rn(v0.z); h[3] = __float2half_rn(v0.w);
        h[4] = __float2half_rn(v1.x); h[5] = __float2half_rn(v1.y);
        h[6] = __float2half_rn(v1.z); h[7] = __float2half_rn(v1.w);
        ((uint4*)g_x16)[i] = *(uint4*)h;
    }
}

#define CONV_TOTAL ((size_t)B_ * N_ * C_ / 8)
#define CONV_HALF  (CONV_TOTAL / 2)

// ---------------------------------------------------------------------------
// k_zq: zero g_Q (must precede k_q atomics)
// ---------------------------------------------------------------------------
__global__ __launch_bounds__(256) void k_zq() {
    int i = blockIdx.x * 256 + threadIdx.x;
    ((float4*)g_Q)[i] = make_float4(0.f, 0.f, 0.f, 0.f);
}

// ---------------------------------------------------------------------------
// k_p2: union launch — conv_lo (1280 blocks) | k_q (768 blocks) | zero_rest (64)
// ---------------------------------------------------------------------------
#define P2_CONV 1280
#define P2_Q    768
#define P2_Z    64
#define QK_SLICE (C_ / 16)   // 96
__global__ __launch_bounds__(256) void k_p2(const float* __restrict__ x,
                                            const float* __restrict__ Wq,
                                            float* __restrict__ out) {
    int bid = blockIdx.x, t = threadIdx.x;
    if (bid < P2_CONV) {
        conv_range(x, 0, CONV_HALF, bid, P2_CONV, t);
        return;
    }
    bid -= P2_CONV;
    if (bid < P2_Q) {
        __shared__ float xs[R_ * QK_SLICE];
        int cpt = bid % 6, b = (bid / 6) % 8, kc = bid / 48;
        int k0 = kc * QK_SLICE;
        if (t < R_ * QK_SLICE / 4) {
            int r = t / (QK_SLICE / 4), c4 = t % (QK_SLICE / 4);
            ((float4*)xs)[t] = *(const float4*)(x + ((size_t)(b * N_ + r)) * C_ + k0 + c4 * 4);
        }
        __syncthreads();
        int cp = cpt * 256 + t;
        const float4* wr = (const float4*)(Wq + (size_t)cp * C_ + k0);
        float acc[R_] = {};
        #pragma unroll 4
        for (int k4 = 0; k4 < QK_SLICE / 4; k4++) {
            float4 w = wr[k4];
            #pragma unroll
            for (int r = 0; r < R_; r++) {
                float4 a = ((const float4*)(xs + r * QK_SLICE))[k4];
                acc[r] += a.x * w.x + a.y * w.y + a.z * w.z + a.w * w.w;
            }
        }
        #pragma unroll
        for (int r = 0; r < R_; r++)
            atomicAdd(&g_Q[(b * R_ + r) * C_ + cp], acc[r] * SCALE_);
        return;
    }
    bid -= P2_Q;
    const float4 z = make_float4(0.f, 0.f, 0.f, 0.f);
    size_t stride = (size_t)P2_Z * 256;
    size_t t0 = (size_t)bid * 256 + t;
    for (size_t i = t0; i < (size_t)B_ * M_ * C_ / 4; i += stride) ((float4*)g_AX)[i] = z;
    for (size_t i = t0; i < (size_t)B_ * R_ * C_ / 4; i += stride) {
        ((float4*)g_XCLS)[i] = z;
        ((float4*)out)[i] = z;
    }
}

// ---------------------------------------------------------------------------
// k_p3: union launch — conv_hi (1280 blocks) | k_qk (576 blocks, 256 thr)
// ---------------------------------------------------------------------------
#define P3_CONV 1280
__global__ __launch_bounds__(256) void k_p3(const float* __restrict__ x,
                                            const float* __restrict__ Wk) {
    int bid = blockIdx.x, t = threadIdx.x;
    if (bid < P3_CONV) {
        conv_range(x, CONV_HALF, CONV_TOTAL, bid, P3_CONV, t);
        return;
    }
    bid -= P3_CONV;
    __shared__ float Qs[16][64];
    int cx = bid % 6, h = (bid / 6) % 24, qt = bid / 144;
    for (int i = t; i < 16 * 64; i += 256) {
        int brl = i >> 6, d = i & 63;
        Qs[brl][d] = g_Q[(qt * 16 + brl) * C_ + h * 64 + d];
    }
    __syncthreads();
    int c = cx * 256 + t;
    float acc[16] = {};
    #pragma unroll 4
    for (int d = 0; d < 64; d++) {
        float w = Wk[(size_t)(h * 64 + d) * C_ + c];
        #pragma unroll
        for (int brl = 0; brl < 16; brl++) acc[brl] += Qs[brl][d] * w;
    }
    #pragma unroll
    for (int brl = 0; brl < 16; brl++) {
        int br = qt * 16 + brl;
        int b = br >> 3, r = br & 7;
        g_QK16[((size_t)(b * M_ + h * 8 + r)) * C_ + c] = __float2half_rn(acc[brl]);
    }
}

// ---------------------------------------------------------------------------
// k_scores: S = QK16 . x16^T   fp16 mma, BM=192, BN=64, BK=64, 3-stage depth-2
// 192 threads: 6 warps (3m x 2n), warp 64x32. 2 CTAs/SM (110.6KB smem each).
// grid (64 n-tiles, 1, 8). Single barrier; load(it+2) issued after barrier,
// targeting buffer (it-1)%3 which the barrier just retired — race-free.
// ---------------------------------------------------------------------------
#define SC_STAGE 36864   // (192+64) rows * 72 halfs * 2B
#define SC_BOFF  27648   // A = 192*72*2
__global__ __launch_bounds__(192, 2) void k_scores() {
    extern __shared__ char smem[];
    uint32_t sb = (uint32_t)__cvta_generic_to_shared(smem);
    int b = blockIdx.z, nt = blockIdx.x;
    int tid = threadIdx.x, lane = tid & 31, warp = tid >> 5;
    int g = lane >> 2, q = lane & 3;
    int m0 = (warp >> 1) * 64, n0 = (warp & 1) * 32;

    const __half* Ab = g_QK16 + (size_t)b * M_ * C_;
    const __half* Bb = g_x16 + ((size_t)(b * N_ + nt * 64)) * C_;

    float acc[4][4][4] = {};

    #define SC_LOAD(st, itv)                                                     \
        do {                                                                     \
            uint32_t a0 = sb + (st) * SC_STAGE;                                  \
            uint32_t b0 = a0 + SC_BOFF;                                          \
            int kb = (itv) * 64;                                                 \
            for (int i = tid; i < 2048; i += 192) {                              \
                if (i < 1536) {                                                  \
                    int row = i >> 3, ch = i & 7;                                \
                    CPA(a0 + (row * 72 + ch * 8) * 2,                            \
                        Ab + (size_t)row * C_ + kb + ch * 8);                    \
                } else {                                                         \
                    int j = i - 1536;                                            \
                    int row = j >> 3, ch = j & 7;                                \
                    CPA(b0 + (row * 72 + ch * 8) * 2,                            \
                        Bb + (size_t)row * C_ + kb + ch * 8);                    \
                }                                                                \
            }                                                                    \
            CPCOMMIT();                                                          \
        } while (0)

    const int NK = C_ / 64;  // 24
    SC_LOAD(0, 0); SC_LOAD(1, 1);

    for (int it = 0; it < NK; ++it) {
        if (it < NK - 1) CPWAIT1();   // buffer `it` complete, `it+1` may pend
        else             CPWAIT0();
        __syncthreads();
        // prefetch it+2 into buffer (it+2)%3 == (it-1)%3 (retired by barrier)
        int nx = it + 2;
        if (nx < NK) SC_LOAD(nx % 3, nx);

        uint32_t aB = sb + (it % 3) * SC_STAGE;
        uint32_t bB = aB + SC_BOFF;
        #pragma unroll
        for (int ks = 0; ks < 64; ks += 16) {
            uint32_t a[4][4];
            #pragma unroll
            for (int mi = 0; mi < 4; mi++) {
                uint32_t ad = aB + ((m0 + mi * 16 + (lane & 7) + ((lane >> 3) & 1) * 8) * 72
                                    + ks + (lane >> 4) * 8) * 2;
                LDSM4(a[mi][0], a[mi][1], a[mi][2], a[mi][3], ad);
            }
            uint32_t bf[2][4];
            #pragma unroll
            for (int bi = 0; bi < 2; bi++) {
                uint32_t bd = bB + ((n0 + bi * 16 + (lane & 7) + ((lane >> 4) & 1) * 8) * 72
                                    + ks + ((lane >> 3) & 1) * 8) * 2;
                LDSM4(bf[bi][0], bf[bi][1], bf[bi][2], bf[bi][3], bd);
            }
            #pragma unroll
            for (int mi = 0; mi < 4; mi++)
                #pragma unroll
                for (int ni = 0; ni < 4; ni++)
                    mma16(acc[mi][ni], a[mi], &bf[ni >> 1][(ni & 1) * 2]);
        }
    }
    #undef SC_LOAD

    float* Cb = g_S + (size_t)b * M_ * N_ + (size_t)nt * 64;
    #pragma unroll
    for (int mi = 0; mi < 4; mi++)
        #pragma unroll
        for (int ni = 0; ni < 4; ni++) {
            int row = m0 + mi * 16 + g;
            int col = n0 + ni * 8 + q * 2;
            *(float2*)(Cb + (size_t)row * N_ + col)       = make_float2(acc[mi][ni][0], acc[mi][ni][1]);
            *(float2*)(Cb + (size_t)(row + 8) * N_ + col) = make_float2(acc[mi][ni][2], acc[mi][ni][3]);
        }
}

// ---------------------------------------------------------------------------
// k_softmax: masked softmax; reads g_S f32, writes g_P16 fp16
// ---------------------------------------------------------------------------
__global__ __launch_bounds__(256) void k_softmax(const int* __restrict__ mask) {
    int row = blockIdx.x;
    int b = row / M_, m = row % M_, r = m & 7;
    const float* S = g_S + (size_t)row * N_;
    __half* P = g_P16 + (size_t)row * N_;
    const int* mrow = mask + ((size_t)(b * R_ + r)) * (N_ - R_);
    int tid = threadIdx.x;

    float vals[16];
    float mx = -1e30f;
    #pragma unroll
    for (int i = 0; i < 16; i++) {
        int n = i * 256 + tid;
        float s = S[n];
        bool valid = (n < R_) ? (n == r) : (mrow[n - R_] != 0);
        s = valid ? s : -1e30f;
        vals[i] = s;
        mx = fmaxf(mx, s);
    }
    __shared__ float smx[8], ssm[8];
    float wmx = warpMax(mx);
    if ((tid & 31) == 0) smx[tid >> 5] = wmx;
    __syncthreads();
    float bm = smx[0];
    #pragma unroll
    for (int j = 1; j < 8; j++) bm = fmaxf(bm, smx[j]);

    float sum = 0.f;
    #pragma unroll
    for (int i = 0; i < 16; i++) {
        vals[i] = expf(vals[i] - bm);
        sum += vals[i];
    }
    float wsm = warpSum(sum);
    if ((tid & 31) == 0) ssm[tid >> 5] = wsm;
    __syncthreads();
    float tot = 0.f;
    #pragma unroll
    for (int j = 0; j < 8; j++) tot += ssm[j];
    float inv = 1.0f / tot;
    #pragma unroll
    for (int i = 0; i < 16; i++) P[i * 256 + tid] = __float2half_rn(vals[i] * inv);
}

// ---------------------------------------------------------------------------
// k_ax: AX[m,c] += sum_{n in split} P16[m,n] * x16[n,c]   (split-K x4)
// BM=192, BN=64 (c), BK=64 (tokens), 3-stage depth-2, single barrier.
// 192 threads (3m x 2n), warp 64x32. 2 CTAs/SM. grid (24 c-tiles, 4, 8).
// ---------------------------------------------------------------------------
#define AX_STAGE 36864   // A 192*72*2 + B 64*72*2
#define AX_BOFF  27648
#define AX_SPLIT 4
__global__ __launch_bounds__(192, 2) void k_ax() {
    extern __shared__ char smem[];
    uint32_t sb = (uint32_t)__cvta_generic_to_shared(smem);
    int b = blockIdx.z, nt = blockIdx.x, kc = blockIdx.y;
    int tid = threadIdx.x, lane = tid & 31, warp = tid >> 5;
    int g = lane >> 2, q = lane & 3;
    int m0 = (warp >> 1) * 64, n0 = (warp & 1) * 32;

    const int K0 = kc * (N_ / AX_SPLIT);
    const __half* Ab = g_P16 + (size_t)b * M_ * N_ + K0;
    const __half* Bx = g_x16 + (size_t)b * N_ * C_ + (size_t)K0 * C_ + nt * 64;

    float acc[4][4][4] = {};

    #define AX_LOAD(st, itv)                                                     \
        do {                                                                     \
            uint32_t a0 = sb + (st) * AX_STAGE;                                  \
            uint32_t b0 = a0 + AX_BOFF;                                          \
            int kb = (itv) * 64;                                                 \
            for (int i = tid; i < 2048; i += 192) {                              \
                if (i < 1536) {                                                  \
                    int row = i >> 3, ch = i & 7;                                \
                    CPA(a0 + (row * 72 + ch * 8) * 2,                            \
                        Ab + (size_t)row * N_ + kb + ch * 8);                    \
                } else {                                                         \
                    int j = i - 1536;                                            \
                    int row = j >> 3, ch = j & 7;                                \
                    CPA(b0 + (row * 72 + ch * 8) * 2,                            \
                        Bx + (size_t)(kb + row) * C_ + ch * 8);                  \
                }                                                                \
            }                                                                    \
            CPCOMMIT();                                                          \
        } while (0)

    const int NK = (N_ / AX_SPLIT) / 64;  // 16
    AX_LOAD(0, 0); AX_LOAD(1, 1);

    for (int it = 0; it < NK; ++it) {
        if (it < NK - 1) CPWAIT1();
        else             CPWAIT0();
        __syncthreads();
        int nx = it + 2;
        if (nx < NK) AX_LOAD(nx % 3, nx);

        uint32_t aB = sb + (it % 3) * AX_STAGE;
        uint32_t bB = aB + AX_BOFF;
        #pragma unroll
        for (int ks = 0; ks < 64; ks += 16) {
            uint32_t a[4][4];
            #pragma unroll
            for (int mi = 0; mi < 4; mi++) {
                uint32_t ad = aB + ((m0 + mi * 16 + (lane & 7) + ((lane >> 3) & 1) * 8) * 72
                                    + ks + (lane >> 4) * 8) * 2;
                LDSM4(a[mi][0], a[mi][1], a[mi][2], a[mi][3], ad);
            }
            uint32_t bf[2][4];
            #pragma unroll
            for (int bi = 0; bi < 2; bi++) {
                // trans: storage rows = k (tokens), cols = n (channels)
                uint32_t bd = bB + ((ks + (lane & 7) + ((lane >> 3) & 1) * 8) * 72
                                    + n0 + bi * 16 + ((lane >> 4) & 1) * 8) * 2;
                LDSM4T(bf[bi][0], bf[bi][1], bf[bi][2], bf[bi][3], bd);
            }
            #pragma unroll
            for (int mi = 0; mi < 4; mi++)
                #pragma unroll
                for (int ni = 0; ni < 4; ni++)
                    mma16(acc[mi][ni], a[mi], &bf[ni >> 1][(ni & 1) * 2]);
        }
    }
    #undef AX_LOAD

    float* Cb = g_AX + (size_t)b * M_ * C_ + nt * 64;
    #pragma unroll
    for (int mi = 0; mi < 4; mi++)
        #pragma unroll
        for (int ni = 0; ni < 4; ni++) {
            int row = m0 + mi * 16 + g;
            int col = n0 + ni * 8 + q * 2;
            float* p0 = Cb + (size_t)row * C_ + col;
            float* p1 = Cb + (size_t)(row + 8) * C_ + col;
            atomicAdd(p0,     acc[mi][ni][0]);
            atomicAdd(p0 + 1, acc[mi][ni][1]);
            atomicAdd(p1,     acc[mi][ni][2]);
            atomicAdd(p1 + 1, acc[mi][ni][3]);
        }
}

// ---------------------------------------------------------------------------
// k_d1: XCLS[b,r,cc] += sum_{c in slice} AX[b, (cc/64)*8+r, c] * Wv[cc, c]
// K-split x16: grid (6, 8, 16). atomicAdd into zeroed g_XCLS.
// ---------------------------------------------------------------------------
__global__ __launch_bounds__(256) void k_d1(const float* __restrict__ Wv) {
    int b = blockIdx.y, kc = blockIdx.z, t = threadIdx.x;
    int k0 = kc * QK_SLICE;
    int cc = blockIdx.x * 256 + t;
    int h = cc >> 6;
    const float4* wr = (const float4*)(Wv + (size_t)cc * C_ + k0);
    const float4* ax[R_];
    #pragma unroll
    for (int r = 0; r < R_; r++)
        ax[r] = (const float4*)(g_AX + ((size_t)b * M_ + h * 8 + r) * C_ + k0);
    float acc[R_] = {};
    #pragma unroll 4
    for (int k4 = 0; k4 < QK_SLICE / 4; k4++) {
        float4 w = wr[k4];
        #pragma unroll
        for (int r = 0; r < R_; r++) {
            float4 a = ax[r][k4];
            acc[r] += a.x * w.x + a.y * w.y + a.z * w.z + a.w * w.w;
        }
    }
    #pragma unroll
    for (int r = 0; r < R_; r++)
        atomicAdd(&g_XCLS[(b * R_ + r) * C_ + cc], acc[r]);
}

// ---------------------------------------------------------------------------
// k_d2: out[b,r,c'] += sum_{cc in slice} XCLS[b,r,cc] * Wp[c',cc]  (+bias on kc0)
// K-split x16: grid (6, 8, 16). atomicAdd into zeroed out.
// ---------------------------------------------------------------------------
__global__ __launch_bounds__(256) void k_d2(const float* __restrict__ Wp,
                                            const float* __restrict__ bp,
                                            float* __restrict__ out) {
    int b = blockIdx.y, kc = blockIdx.z, t = threadIdx.x;
    int k0 = kc * QK_SLICE;
    int cp = blockIdx.x * 256 + t;
    const float4* wr = (const float4*)(Wp + (size_t)cp * C_ + k0);
    const float4* xc[R_];
    #pragma unroll
    for (int r = 0; r < R_; r++)
        xc[r] = (const float4*)(g_XCLS + (size_t)(b * R_ + r) * C_ + k0);
    float acc[R_] = {};
    #pragma unroll 4
    for (int k4 = 0; k4 < QK_SLICE / 4; k4++) {
        float4 w = wr[k4];
        #pragma unroll
        for (int r = 0; r < R_; r++) {
            float4 a = xc[r][k4];
            acc[r] += a.x * w.x + a.y * w.y + a.z * w.z + a.w * w.w;
        }
    }
    float bias = (kc == 0) ? bp[cp] : 0.f;
    #pragma unroll
    for (int r = 0; r < R_; r++)
        atomicAdd(&out[((size_t)(b * R_ + r)) * C_ + cp], acc[r] + bias);
}

// ---------------------------------------------------------------------------
// launch
// ---------------------------------------------------------------------------
extern "C" void kernel_launch(void* const* d_in, const int* in_sizes, int n_in,
                              void* d_out, int out_size) {
    const float* x    = (const float*)d_in[0];
    const int*   mask = (const int*)d_in[1];
    const float* Wq   = (const float*)d_in[2];
    const float* Wk   = (const float*)d_in[3];
    const float* Wv   = (const float*)d_in[4];
    const float* Wp   = (const float*)d_in[5];
    const float* bp   = (const float*)d_in[6];
    float* out = (float*)d_out;

    const int SC_SMEM = 3 * SC_STAGE;  // 110592
    const int AX_SMEM = 3 * AX_STAGE;  // 110592
    cudaFuncSetAttribute(k_scores, cudaFuncAttributeMaxDynamicSharedMemorySize, SC_SMEM);
    cudaFuncSetAttribute(k_ax,     cudaFuncAttributeMaxDynamicSharedMemorySize, AX_SMEM);

    k_zq     <<<96, 256>>>();
    k_p2     <<<P2_CONV + P2_Q + P2_Z, 256>>>(x, Wq, out);
    k_p3     <<<P3_CONV + 576, 256>>>(x, Wk);
    k_scores <<<dim3(N_ / 64, 1, B_), 192, SC_SMEM>>>();
    k_softmax<<<B_ * M_, 256>>>(mask);
    k_ax     <<<dim3(C_ / 64, AX_SPLIT, B_), 192, AX_SMEM>>>();
    k_d1     <<<dim3(C_ / 256, B_, 16), 256>>>(Wv);
    k_d2     <<<dim3(C_ / 256, B_, 16), 256>>>(Wp, bp, out);
}

// round 14
// speedup vs baseline: 3.3426x; 1.0024x over previous
#include <cuda_runtime.h>
#include <cuda_fp16.h>
#include <cstdint>

// Problem constants
#define B_   8
#define N_   4096
#define C_   1536
#define H_   24
#define R_   8
#define M_   192
#define SCALE_ 0.125f

// Scratch (static device globals)
__device__ float    g_Q[B_ * R_ * C_];                 // atomically accumulated
__device__ __half   g_QK16[B_ * M_ * C_];              // q@Wk, fp16
__device__ float    g_S[(size_t)B_ * M_ * N_];         // scores f32
__device__ __half   g_P16[(size_t)B_ * M_ * N_];       // softmax probs fp16
__device__ float    g_AX[B_ * M_ * C_];                // P @ x (split-K accumulated)
__device__ float    g_XCLS[B_ * R_ * C_];              // atomically accumulated
__device__ __half   g_x16[(size_t)B_ * N_ * C_];       // x fp16

// ---------------------------------------------------------------------------
// helpers
// ---------------------------------------------------------------------------
#define CPA(dst, src) asm volatile("cp.async.cg.shared.global [%0], [%1], 16;" :: "r"(dst), "l"(src))
#define CPCOMMIT()    asm volatile("cp.async.commit_group;")
#define CPWAIT0()     asm volatile("cp.async.wait_group 0;")
#define CPWAIT1()     asm volatile("cp.async.wait_group 1;")

#define LDSM4(r0, r1, r2, r3, addr) \
    asm volatile("ldmatrix.sync.aligned.m8n8.x4.shared.b16 {%0,%1,%2,%3}, [%4];" \
                 : "=r"(r0), "=r"(r1), "=r"(r2), "=r"(r3) : "r"(addr))
#define LDSM4T(r0, r1, r2, r3, addr) \
    asm volatile("ldmatrix.sync.aligned.m8n8.x4.trans.shared.b16 {%0,%1,%2,%3}, [%4];" \
                 : "=r"(r0), "=r"(r1), "=r"(r2), "=r"(r3) : "r"(addr))

__device__ __forceinline__ void mma16(float* c, const uint32_t* a, const uint32_t* b) {
    asm volatile(
        "mma.sync.aligned.m16n8k16.row.col.f32.f16.f16.f32 "
        "{%0,%1,%2,%3}, {%4,%5,%6,%7}, {%8,%9}, {%0,%1,%2,%3};"
        : "+f"(c[0]), "+f"(c[1]), "+f"(c[2]), "+f"(c[3])
        : "r"(a[0]), "r"(a[1]), "r"(a[2]), "r"(a[3]), "r"(b[0]), "r"(b[1]));
}

__device__ __forceinline__ float warpMax(float v) {
    #pragma unroll
    for (int o = 16; o; o >>= 1) v = fmaxf(v, __shfl_xor_sync(0xffffffffu, v, o));
    return v;
}
__device__ __forceinline__ float warpSum(float v) {
    #pragma unroll
    for (int o = 16; o; o >>= 1) v += __shfl_xor_sync(0xffffffffu, v, o);
    return v;
}

// ---------------------------------------------------------------------------
// conv range worker: convert x[f32] -> g_x16 over uint4 indices [lo, hi)
// ---------------------------------------------------------------------------
__device__ __forceinline__ void conv_range(const float* __restrict__ x,
                                           size_t lo, size_t hi,
                                           int rb, int nb, int t) {
    for (size_t i = lo + (size_t)rb * 256 + t; i < hi; i += (size_t)nb * 256) {
        float4 v0 = ((const float4*)x)[i * 2];
        float4 v1 = ((const float4*)x)[i * 2 + 1];
        __half h[8];
        h[0] = __float2half_rn(v0.x); h[1] = __float2half_rn(v0.y);
        h[2] = __float2half_rn(v0.z); h[3] = __float2half_rn(v0.w);
        h[4] = __float2half_rn(v1.x); h[5] = __float2half_rn(v1.y);
        h[6] = __float2half_rn(v1.z); h[7] = __float2half_rn(v1.w);
        ((uint4*)g_x16)[i] = *(uint4*)h;
    }
}

#define CONV_TOTAL ((size_t)B_ * N_ * C_ / 8)
#define CONV_HALF  (CONV_TOTAL / 2)

// ---------------------------------------------------------------------------
// k_zq: zero g_Q (must precede k_q atomics)
// ---------------------------------------------------------------------------
__global__ __launch_bounds__(256) void k_zq() {
    int i = blockIdx.x * 256 + threadIdx.x;
    ((float4*)g_Q)[i] = make_float4(0.f, 0.f, 0.f, 0.f);
}

// ---------------------------------------------------------------------------
// k_p2: union launch — conv_lo (1280 blocks) | k_q (768 blocks) | zero_rest (64)
// ---------------------------------------------------------------------------
#define P2_CONV 1280
#define P2_Q    768
#define P2_Z    64
#define QK_SLICE (C_ / 16)   // 96
__global__ __launch_bounds__(256) void k_p2(const float* __restrict__ x,
                                            const float* __restrict__ Wq,
                                            float* __restrict__ out) {
    int bid = blockIdx.x, t = threadIdx.x;
    if (bid < P2_CONV) {
        conv_range(x, 0, CONV_HALF, bid, P2_CONV, t);
        return;
    }
    bid -= P2_CONV;
    if (bid < P2_Q) {
        __shared__ float xs[R_ * QK_SLICE];
        int cpt = bid % 6, b = (bid / 6) % 8, kc = bid / 48;
        int k0 = kc * QK_SLICE;
        if (t < R_ * QK_SLICE / 4) {
            int r = t / (QK_SLICE / 4), c4 = t % (QK_SLICE / 4);
            ((float4*)xs)[t] = *(const float4*)(x + ((size_t)(b * N_ + r)) * C_ + k0 + c4 * 4);
        }
        __syncthreads();
        int cp = cpt * 256 + t;
        const float4* wr = (const float4*)(Wq + (size_t)cp * C_ + k0);
        float acc[R_] = {};
        #pragma unroll 4
        for (int k4 = 0; k4 < QK_SLICE / 4; k4++) {
            float4 w = wr[k4];
            #pragma unroll
            for (int r = 0; r < R_; r++) {
                float4 a = ((const float4*)(xs + r * QK_SLICE))[k4];
                acc[r] += a.x * w.x + a.y * w.y + a.z * w.z + a.w * w.w;
            }
        }
        #pragma unroll
        for (int r = 0; r < R_; r++)
            atomicAdd(&g_Q[(b * R_ + r) * C_ + cp], acc[r] * SCALE_);
        return;
    }
    bid -= P2_Q;
    const float4 z = make_float4(0.f, 0.f, 0.f, 0.f);
    size_t stride = (size_t)P2_Z * 256;
    size_t t0 = (size_t)bid * 256 + t;
    for (size_t i = t0; i < (size_t)B_ * M_ * C_ / 4; i += stride) ((float4*)g_AX)[i] = z;
    for (size_t i = t0; i < (size_t)B_ * R_ * C_ / 4; i += stride) {
        ((float4*)g_XCLS)[i] = z;
        ((float4*)out)[i] = z;
    }
}

// ---------------------------------------------------------------------------
// k_p3: union launch — conv_hi (1280 blocks) | k_qk (576 blocks, 256 thr)
// ---------------------------------------------------------------------------
#define P3_CONV 1280
__global__ __launch_bounds__(256) void k_p3(const float* __restrict__ x,
                                            const float* __restrict__ Wk) {
    int bid = blockIdx.x, t = threadIdx.x;
    if (bid < P3_CONV) {
        conv_range(x, CONV_HALF, CONV_TOTAL, bid, P3_CONV, t);
        return;
    }
    bid -= P3_CONV;
    __shared__ float Qs[16][64];
    int cx = bid % 6, h = (bid / 6) % 24, qt = bid / 144;
    for (int i = t; i < 16 * 64; i += 256) {
        int brl = i >> 6, d = i & 63;
        Qs[brl][d] = g_Q[(qt * 16 + brl) * C_ + h * 64 + d];
    }
    __syncthreads();
    int c = cx * 256 + t;
    float acc[16] = {};
    #pragma unroll 4
    for (int d = 0; d < 64; d++) {
        float w = Wk[(size_t)(h * 64 + d) * C_ + c];
        #pragma unroll
        for (int brl = 0; brl < 16; brl++) acc[brl] += Qs[brl][d] * w;
    }
    #pragma unroll
    for (int brl = 0; brl < 16; brl++) {
        int br = qt * 16 + brl;
        int b = br >> 3, r = br & 7;
        g_QK16[((size_t)(b * M_ + h * 8 + r)) * C_ + c] = __float2half_rn(acc[brl]);
    }
}

// ---------------------------------------------------------------------------
// k_scores: S = QK16 . x16^T   fp16 mma, BM=192, BN=64, BK=64, 3-stage depth-2
// 192 threads: 6 warps (3m x 2n), warp 64x32. 2 CTAs/SM. Fragment double-buffer
// inside the ks loop to hide LDSM latency behind mma.
// ---------------------------------------------------------------------------
#define SC_STAGE 36864   // (192+64) rows * 72 halfs * 2B
#define SC_BOFF  27648   // A = 192*72*2
__global__ __launch_bounds__(192, 2) void k_scores() {
    extern __shared__ char smem[];
    uint32_t sb = (uint32_t)__cvta_generic_to_shared(smem);
    int b = blockIdx.z, nt = blockIdx.x;
    int tid = threadIdx.x, lane = tid & 31, warp = tid >> 5;
    int g = lane >> 2, q = lane & 3;
    int m0 = (warp >> 1) * 64, n0 = (warp & 1) * 32;

    const __half* Ab = g_QK16 + (size_t)b * M_ * C_;
    const __half* Bb = g_x16 + ((size_t)(b * N_ + nt * 64)) * C_;

    // per-lane LDSM base offsets (in halfs, before *2 byte scale)
    const uint32_t aoff = (uint32_t)((m0 + (lane & 7) + ((lane >> 3) & 1) * 8) * 72
                                     + (lane >> 4) * 8) * 2;
    const uint32_t boff = (uint32_t)((n0 + (lane & 7) + ((lane >> 4) & 1) * 8) * 72
                                     + ((lane >> 3) & 1) * 8) * 2;

    float acc[4][4][4] = {};
    uint32_t afr[2][4][4], bfr[2][2][4];

    #define SC_LOAD(st, itv)                                                     \
        do {                                                                     \
            uint32_t a0 = sb + (st) * SC_STAGE;                                  \
            uint32_t b0 = a0 + SC_BOFF;                                          \
            int kb = (itv) * 64;                                                 \
            for (int i = tid; i < 2048; i += 192) {                              \
                if (i < 1536) {                                                  \
                    int row = i >> 3, ch = i & 7;                                \
                    CPA(a0 + (row * 72 + ch * 8) * 2,                            \
                        Ab + (size_t)row * C_ + kb + ch * 8);                    \
                } else {                                                         \
                    int j = i - 1536;                                            \
                    int row = j >> 3, ch = j & 7;                                \
                    CPA(b0 + (row * 72 + ch * 8) * 2,                            \
                        Bb + (size_t)row * C_ + kb + ch * 8);                    \
                }                                                                \
            }                                                                    \
            CPCOMMIT();                                                          \
        } while (0)

    #define SC_FRAG(slot, aB, bB, ks)                                            \
        do {                                                                     \
            _Pragma("unroll")                                                    \
            for (int mi = 0; mi < 4; mi++)                                       \
                LDSM4(afr[slot][mi][0], afr[slot][mi][1],                        \
                      afr[slot][mi][2], afr[slot][mi][3],                        \
                      (aB) + aoff + (mi * 16 * 72 + (ks)) * 2);                  \
            _Pragma("unroll")                                                    \
            for (int bi = 0; bi < 2; bi++)                                       \
                LDSM4(bfr[slot][bi][0], bfr[slot][bi][1],                        \
                      bfr[slot][bi][2], bfr[slot][bi][3],                        \
                      (bB) + boff + (bi * 16 * 72 + (ks)) * 2);                  \
        } while (0)

    const int NK = C_ / 64;  // 24
    SC_LOAD(0, 0); SC_LOAD(1, 1);

    for (int it = 0; it < NK; ++it) {
        if (it < NK - 1) CPWAIT1();
        else             CPWAIT0();
        __syncthreads();
        int nx = it + 2;
        if (nx < NK) SC_LOAD(nx % 3, nx);

        uint32_t aB = sb + (it % 3) * SC_STAGE;
        uint32_t bB = aB + SC_BOFF;

        SC_FRAG(0, aB, bB, 0);
        #pragma unroll
        for (int ks = 0; ks < 64; ks += 16) {
            int cur = (ks >> 4) & 1;
            if (ks + 16 < 64) SC_FRAG(cur ^ 1, aB, bB, ks + 16);
            #pragma unroll
            for (int mi = 0; mi < 4; mi++)
                #pragma unroll
                for (int ni = 0; ni < 4; ni++)
                    mma16(acc[mi][ni], afr[cur][mi], &bfr[cur][ni >> 1][(ni & 1) * 2]);
        }
    }
    #undef SC_FRAG
    #undef SC_LOAD

    float* Cb = g_S + (size_t)b * M_ * N_ + (size_t)nt * 64;
    #pragma unroll
    for (int mi = 0; mi < 4; mi++)
        #pragma unroll
        for (int ni = 0; ni < 4; ni++) {
            int row = m0 + mi * 16 + g;
            int col = n0 + ni * 8 + q * 2;
            *(float2*)(Cb + (size_t)row * N_ + col)       = make_float2(acc[mi][ni][0], acc[mi][ni][1]);
            *(float2*)(Cb + (size_t)(row + 8) * N_ + col) = make_float2(acc[mi][ni][2], acc[mi][ni][3]);
        }
}

// ---------------------------------------------------------------------------
// k_softmax: masked softmax; reads g_S f32, writes g_P16 fp16
// ---------------------------------------------------------------------------
__global__ __launch_bounds__(256) void k_softmax(const int* __restrict__ mask) {
    int row = blockIdx.x;
    int b = row / M_, m = row % M_, r = m & 7;
    const float* S = g_S + (size_t)row * N_;
    __half* P = g_P16 + (size_t)row * N_;
    const int* mrow = mask + ((size_t)(b * R_ + r)) * (N_ - R_);
    int tid = threadIdx.x;

    float vals[16];
    float mx = -1e30f;
    #pragma unroll
    for (int i = 0; i < 16; i++) {
        int n = i * 256 + tid;
        float s = S[n];
        bool valid = (n < R_) ? (n == r) : (mrow[n - R_] != 0);
        s = valid ? s : -1e30f;
        vals[i] = s;
        mx = fmaxf(mx, s);
    }
    __shared__ float smx[8], ssm[8];
    float wmx = warpMax(mx);
    if ((tid & 31) == 0) smx[tid >> 5] = wmx;
    __syncthreads();
    float bm = smx[0];
    #pragma unroll
    for (int j = 1; j < 8; j++) bm = fmaxf(bm, smx[j]);

    float sum = 0.f;
    #pragma unroll
    for (int i = 0; i < 16; i++) {
        vals[i] = expf(vals[i] - bm);
        sum += vals[i];
    }
    float wsm = warpSum(sum);
    if ((tid & 31) == 0) ssm[tid >> 5] = wsm;
    __syncthreads();
    float tot = 0.f;
    #pragma unroll
    for (int j = 0; j < 8; j++) tot += ssm[j];
    float inv = 1.0f / tot;
    #pragma unroll
    for (int i = 0; i < 16; i++) P[i * 256 + tid] = __float2half_rn(vals[i] * inv);
}

// ---------------------------------------------------------------------------
// k_ax: AX[m,c] += sum_{n in split} P16[m,n] * x16[n,c]   (split-K x4)
// BM=192, BN=64 (c), BK=64 (tokens), 3-stage depth-2, fragment double-buffer.
// 192 threads (3m x 2n), warp 64x32. 2 CTAs/SM. grid (24 c-tiles, 4, 8).
// ---------------------------------------------------------------------------
#define AX_STAGE 36864   // A 192*72*2 + B 64*72*2
#define AX_BOFF  27648
#define AX_SPLIT 4
__global__ __launch_bounds__(192, 2) void k_ax() {
    extern __shared__ char smem[];
    uint32_t sb = (uint32_t)__cvta_generic_to_shared(smem);
    int b = blockIdx.z, nt = blockIdx.x, kc = blockIdx.y;
    int tid = threadIdx.x, lane = tid & 31, warp = tid >> 5;
    int g = lane >> 2, q = lane & 3;
    int m0 = (warp >> 1) * 64, n0 = (warp & 1) * 32;

    const int K0 = kc * (N_ / AX_SPLIT);
    const __half* Ab = g_P16 + (size_t)b * M_ * N_ + K0;
    const __half* Bx = g_x16 + (size_t)b * N_ * C_ + (size_t)K0 * C_ + nt * 64;

    const uint32_t aoff = (uint32_t)((m0 + (lane & 7) + ((lane >> 3) & 1) * 8) * 72
                                     + (lane >> 4) * 8) * 2;
    // trans B: rows = k (tokens), cols = n
    const uint32_t boff = (uint32_t)(((lane & 7) + ((lane >> 3) & 1) * 8) * 72
                                     + n0 + ((lane >> 4) & 1) * 8) * 2;

    float acc[4][4][4] = {};
    uint32_t afr[2][4][4], bfr[2][2][4];

    #define AX_LOAD(st, itv)                                                     \
        do {                                                                     \
            uint32_t a0 = sb + (st) * AX_STAGE;                                  \
            uint32_t b0 = a0 + AX_BOFF;                                          \
            int kb = (itv) * 64;                                                 \
            for (int i = tid; i < 2048; i += 192) {                              \
                if (i < 1536) {                                                  \
                    int row = i >> 3, ch = i & 7;                                \
                    CPA(a0 + (row * 72 + ch * 8) * 2,                            \
                        Ab + (size_t)row * N_ + kb + ch * 8);                    \
                } else {                                                         \
                    int j = i - 1536;                                            \
                    int row = j >> 3, ch = j & 7;                                \
                    CPA(b0 + (row * 72 + ch * 8) * 2,                            \
                        Bx + (size_t)(kb + row) * C_ + ch * 8);                  \
                }                                                                \
            }                                                                    \
            CPCOMMIT();                                                          \
        } while (0)

    #define AX_FRAG(slot, aB, bB, ks)                                            \
        do {                                                                     \
            _Pragma("unroll")                                                    \
            for (int mi = 0; mi < 4; mi++)                                       \
                LDSM4(afr[slot][mi][0], afr[slot][mi][1],                        \
                      afr[slot][mi][2], afr[slot][mi][3],                        \
                      (aB) + aoff + (mi * 16 * 72 + (ks)) * 2);                  \
            _Pragma("unroll")                                                    \
            for (int bi = 0; bi < 2; bi++)                                       \
                LDSM4T(bfr[slot][bi][0], bfr[slot][bi][1],                       \
                       bfr[slot][bi][2], bfr[slot][bi][3],                       \
                       (bB) + boff + ((ks) * 72 + bi * 16) * 2);                 \
        } while (0)

    const int NK = (N_ / AX_SPLIT) / 64;  // 16
    AX_LOAD(0, 0); AX_LOAD(1, 1);

    for (int it = 0; it < NK; ++it) {
        if (it < NK - 1) CPWAIT1();
        else             CPWAIT0();
        __syncthreads();
        int nx = it + 2;
        if (nx < NK) AX_LOAD(nx % 3, nx);

        uint32_t aB = sb + (it % 3) * AX_STAGE;
        uint32_t bB = aB + AX_BOFF;

        AX_FRAG(0, aB, bB, 0);
        #pragma unroll
        for (int ks = 0; ks < 64; ks += 16) {
            int cur = (ks >> 4) & 1;
            if (ks + 16 < 64) AX_FRAG(cur ^ 1, aB, bB, ks + 16);
            #pragma unroll
            for (int mi = 0; mi < 4; mi++)
                #pragma unroll
                for (int ni = 0; ni < 4; ni++)
                    mma16(acc[mi][ni], afr[cur][mi], &bfr[cur][ni >> 1][(ni & 1) * 2]);
        }
    }
    #undef AX_FRAG
    #undef AX_LOAD

    float* Cb = g_AX + (size_t)b * M_ * C_ + nt * 64;
    #pragma unroll
    for (int mi = 0; mi < 4; mi++)
        #pragma unroll
        for (int ni = 0; ni < 4; ni++) {
            int row = m0 + mi * 16 + g;
            int col = n0 + ni * 8 + q * 2;
            float* p0 = Cb + (size_t)row * C_ + col;
            float* p1 = Cb + (size_t)(row + 8) * C_ + col;
            atomicAdd(p0,     acc[mi][ni][0]);
            atomicAdd(p0 + 1, acc[mi][ni][1]);
            atomicAdd(p1,     acc[mi][ni][2]);
            atomicAdd(p1 + 1, acc[mi][ni][3]);
        }
}

// ---------------------------------------------------------------------------
// k_d1: XCLS[b,r,cc] += sum_{c in slice} AX[b, (cc/64)*8+r, c] * Wv[cc, c]
// K-split x16: grid (6, 8, 16). atomicAdd into zeroed g_XCLS.
// ---------------------------------------------------------------------------
__global__ __launch_bounds__(256) void k_d1(const float* __restrict__ Wv) {
    int b = blockIdx.y, kc = blockIdx.z, t = threadIdx.x;
    int k0 = kc * QK_SLICE;
    int cc = blockIdx.x * 256 + t;
    int h = cc >> 6;
    const float4* wr = (const float4*)(Wv + (size_t)cc * C_ + k0);
    const float4* ax[R_];
    #pragma unroll
    for (int r = 0; r < R_; r++)
        ax[r] = (const float4*)(g_AX + ((size_t)b * M_ + h * 8 + r) * C_ + k0);
    float acc[R_] = {};
    #pragma unroll 4
    for (int k4 = 0; k4 < QK_SLICE / 4; k4++) {
        float4 w = wr[k4];
        #pragma unroll
        for (int r = 0; r < R_; r++) {
            float4 a = ax[r][k4];
            acc[r] += a.x * w.x + a.y * w.y + a.z * w.z + a.w * w.w;
        }
    }
    #pragma unroll
    for (int r = 0; r < R_; r++)
        atomicAdd(&g_XCLS[(b * R_ + r) * C_ + cc], acc[r]);
}

// ---------------------------------------------------------------------------
// k_d2: out[b,r,c'] += sum_{cc in slice} XCLS[b,r,cc] * Wp[c',cc]  (+bias on kc0)
// K-split x16: grid (6, 8, 16). atomicAdd into zeroed out.
// ---------------------------------------------------------------------------
__global__ __launch_bounds__(256) void k_d2(const float* __restrict__ Wp,
                                            const float* __restrict__ bp,
                                            float* __restrict__ out) {
    int b = blockIdx.y, kc = blockIdx.z, t = threadIdx.x;
    int k0 = kc * QK_SLICE;
    int cp = blockIdx.x * 256 + t;
    const float4* wr = (const float4*)(Wp + (size_t)cp * C_ + k0);
    const float4* xc[R_];
    #pragma unroll
    for (int r = 0; r < R_; r++)
        xc[r] = (const float4*)(g_XCLS + (size_t)(b * R_ + r) * C_ + k0);
    float acc[R_] = {};
    #pragma unroll 4
    for (int k4 = 0; k4 < QK_SLICE / 4; k4++) {
        float4 w = wr[k4];
        #pragma unroll
        for (int r = 0; r < R_; r++) {
            float4 a = xc[r][k4];
            acc[r] += a.x * w.x + a.y * w.y + a.z * w.z + a.w * w.w;
        }
    }
    float bias = (kc == 0) ? bp[cp] : 0.f;
    #pragma unroll
    for (int r = 0; r < R_; r++)
        atomicAdd(&out[((size_t)(b * R_ + r)) * C_ + cp], acc[r] + bias);
}

// ---------------------------------------------------------------------------
// launch
// ---------------------------------------------------------------------------
extern "C" void kernel_launch(void* const* d_in, const int* in_sizes, int n_in,
                              void* d_out, int out_size) {
    const float* x    = (const float*)d_in[0];
    const int*   mask = (const int*)d_in[1];
    const float* Wq   = (const float*)d_in[2];
    const float* Wk   = (const float*)d_in[3];
    const float* Wv   = (const float*)d_in[4];
    const float* Wp   = (const float*)d_in[5];
    const float* bp   = (const float*)d_in[6];
    float* out = (float*)d_out;

    const int SC_SMEM = 3 * SC_STAGE;  // 110592
    const int AX_SMEM = 3 * AX_STAGE;  // 110592
    cudaFuncSetAttribute(k_scores, cudaFuncAttributeMaxDynamicSharedMemorySize, SC_SMEM);
    cudaFuncSetAttribute(k_ax,     cudaFuncAttributeMaxDynamicSharedMemorySize, AX_SMEM);

    k_zq     <<<96, 256>>>();
    k_p2     <<<P2_CONV + P2_Q + P2_Z, 256>>>(x, Wq, out);
    k_p3     <<<P3_CONV + 576, 256>>>(x, Wk);
    k_scores <<<dim3(N_ / 64, 1, B_), 192, SC_SMEM>>>();
    k_softmax<<<B_ * M_, 256>>>(mask);
    k_ax     <<<dim3(C_ / 64, AX_SPLIT, B_), 192, AX_SMEM>>>();
    k_d1     <<<dim3(C_ / 256, B_, 16), 256>>>(Wv);
    k_d2     <<<dim3(C_ / 256, B_, 16), 256>>>(Wp, bp, out);
}